// round 5
// baseline (speedup 1.0000x reference)
#include <cuda_runtime.h>
#include <math.h>
#include <stdint.h>

// Problem dims
#define BN   64
#define TN   512
#define BT   32768       // B*T
#define DN   1536        // 2*D_BERT
#define C1   192         // conv channels each
#define C4T  768         // 4*C
#define HN   256
#define G4   1024        // 4*H
#define LBL  20

// ---------------- scratch (static device memory; no allocations) -------------
__device__ float g_xn [ (size_t)BT * DN  ];   // LN1 output
__device__ float g_cv [ (size_t)BT * C4T ];   // conv+relu output
__device__ float g_co [ (size_t)BT * C4T ];   // LN2 output
__device__ float g_gxf[ (size_t)BT * G4  ];   // x@Wx_f + bf
__device__ float g_gxb[ (size_t)BT * G4  ];   // x@Wx_b + bb
__device__ float g_h  [ (size_t)BT * 2*HN];   // [hf|hb] concat per (b,t)
__device__ float g_lg [ (size_t)BT * LBL ];   // logits

// ---------------- helpers -----------------------------------------------------
__device__ __forceinline__ uint32_t f2tf32(float f) {
    uint32_t u;
    asm("cvt.rna.tf32.f32 %0, %1;" : "=r"(u) : "f"(f));
    return u;
}

__device__ __forceinline__ void mma_tf32(float* c, uint32_t a0, uint32_t a1,
                                         uint32_t a2, uint32_t a3,
                                         uint32_t b0, uint32_t b1) {
    asm volatile(
        "mma.sync.aligned.m16n8k8.row.col.f32.tf32.tf32.f32 "
        "{%0,%1,%2,%3}, {%4,%5,%6,%7}, {%8,%9}, {%0,%1,%2,%3};\n"
        : "+f"(c[0]), "+f"(c[1]), "+f"(c[2]), "+f"(c[3])
        : "r"(a0), "r"(a1), "r"(a2), "r"(a3), "r"(b0), "r"(b1));
}

#define AST 36
#define BST 68

// ---------------- LayerNorm 1: concat(hid_a,hid_b) + LN over 1536 ------------
__global__ __launch_bounds__(256) void ln1_kernel(
    const float* __restrict__ ha, const float* __restrict__ hb,
    const float* __restrict__ g,  const float* __restrict__ be,
    float* __restrict__ out)
{
    int row = blockIdx.x;
    const float* A = ha + (size_t)row * 768;
    const float* B = hb + (size_t)row * 768;
    float s = 0.f, s2 = 0.f;
    for (int d = threadIdx.x; d < DN; d += 256) {
        float v = (d < 768) ? A[d] : B[d - 768];
        s += v; s2 += v * v;
    }
    __shared__ float rs[256], rq[256];
    rs[threadIdx.x] = s; rq[threadIdx.x] = s2;
    __syncthreads();
    for (int off = 128; off > 0; off >>= 1) {
        if (threadIdx.x < off) {
            rs[threadIdx.x] += rs[threadIdx.x + off];
            rq[threadIdx.x] += rq[threadIdx.x + off];
        }
        __syncthreads();
    }
    float mean = rs[0] * (1.f / DN);
    float var  = rq[0] * (1.f / DN) - mean * mean;
    float rstd = rsqrtf(var + 1e-5f);
    float* O = out + (size_t)row * DN;
    for (int d = threadIdx.x; d < DN; d += 256) {
        float v = (d < 768) ? A[d] : B[d - 768];
        O[d] = (v - mean) * rstd * g[d] + be[d];
    }
}

// ---------------- LayerNorm 2 over 768 ---------------------------------------
__global__ __launch_bounds__(256) void ln2_kernel(
    const float* __restrict__ in, const float* __restrict__ g,
    const float* __restrict__ be, float* __restrict__ out)
{
    int row = blockIdx.x;
    const float* X = in + (size_t)row * C4T;
    float s = 0.f, s2 = 0.f;
    for (int d = threadIdx.x; d < C4T; d += 256) {
        float v = X[d]; s += v; s2 += v * v;
    }
    __shared__ float rs[256], rq[256];
    rs[threadIdx.x] = s; rq[threadIdx.x] = s2;
    __syncthreads();
    for (int off = 128; off > 0; off >>= 1) {
        if (threadIdx.x < off) {
            rs[threadIdx.x] += rs[threadIdx.x + off];
            rq[threadIdx.x] += rq[threadIdx.x + off];
        }
        __syncthreads();
    }
    float mean = rs[0] * (1.f / C4T);
    float var  = rq[0] * (1.f / C4T) - mean * mean;
    float rstd = rsqrtf(var + 1e-5f);
    float* O = out + (size_t)row * C4T;
    for (int d = threadIdx.x; d < C4T; d += 256) {
        O[d] = (X[d] - mean) * rstd * g[d] + be[d];
    }
}

// ---------------- TF32 tensor-core GEMM: C = A[MxK]@W[KxN] + bias ------------
__global__ __launch_bounds__(256) void gemm_tf32_kernel(
    const float* __restrict__ A, const float* __restrict__ W,
    const float* __restrict__ bias, float* __restrict__ C,
    int M, int N, int K, int relu)
{
    __shared__ uint32_t As[128 * AST];
    __shared__ uint32_t Bs[32 * BST];

    int tid = threadIdx.x;
    int m0 = blockIdx.x * 128, n0 = blockIdx.y * 64;
    int wid = tid >> 5, lane = tid & 31;
    int wm0 = (wid & 3) * 32, wn0 = (wid >> 2) * 32;
    int g = lane >> 2, tg = lane & 3;

    float acc[2][4][4];
#pragma unroll
    for (int mt = 0; mt < 2; mt++)
#pragma unroll
        for (int nt = 0; nt < 4; nt++)
#pragma unroll
            for (int i = 0; i < 4; i++) acc[mt][nt][i] = 0.f;

    float4 pa[4], pb[2];
    int nk = K / 32;

    auto loadA = [&](int kt) {
#pragma unroll
        for (int j = 0; j < 4; j++) {
            int idx4 = tid + j * 256;
            int row = idx4 >> 3, kc = (idx4 & 7) << 2;
            pa[j] = *reinterpret_cast<const float4*>(A + (size_t)(m0 + row) * K + kt * 32 + kc);
        }
    };
    auto loadB = [&](int kt) {
#pragma unroll
        for (int j = 0; j < 2; j++) {
            int idx4 = tid + j * 256;
            int row = idx4 >> 4, nc = (idx4 & 15) << 2;
            int ncol = n0 + nc;
            const float* Wr = W + (size_t)(kt * 32 + row) * N;
            float4 v;
            if (ncol + 3 < N) {
                v = *reinterpret_cast<const float4*>(Wr + ncol);
            } else {
                v.x = (ncol + 0 < N) ? Wr[ncol + 0] : 0.f;
                v.y = (ncol + 1 < N) ? Wr[ncol + 1] : 0.f;
                v.z = (ncol + 2 < N) ? Wr[ncol + 2] : 0.f;
                v.w = (ncol + 3 < N) ? Wr[ncol + 3] : 0.f;
            }
            pb[j] = v;
        }
    };
    auto stage = [&]() {
#pragma unroll
        for (int j = 0; j < 4; j++) {
            int idx4 = tid + j * 256;
            int row = idx4 >> 3, kc = (idx4 & 7) << 2;
            As[row * AST + kc + 0] = f2tf32(pa[j].x);
            As[row * AST + kc + 1] = f2tf32(pa[j].y);
            As[row * AST + kc + 2] = f2tf32(pa[j].z);
            As[row * AST + kc + 3] = f2tf32(pa[j].w);
        }
#pragma unroll
        for (int j = 0; j < 2; j++) {
            int idx4 = tid + j * 256;
            int row = idx4 >> 4, nc = (idx4 & 15) << 2;
            Bs[row * BST + nc + 0] = f2tf32(pb[j].x);
            Bs[row * BST + nc + 1] = f2tf32(pb[j].y);
            Bs[row * BST + nc + 2] = f2tf32(pb[j].z);
            Bs[row * BST + nc + 3] = f2tf32(pb[j].w);
        }
    };

    loadA(0); loadB(0);
    for (int kt = 0; kt < nk; kt++) {
        __syncthreads();
        stage();
        __syncthreads();
        if (kt + 1 < nk) { loadA(kt + 1); loadB(kt + 1); }
#pragma unroll
        for (int ks = 0; ks < 4; ks++) {
            int kk = ks * 8;
            uint32_t a[2][4], b[4][2];
#pragma unroll
            for (int mt = 0; mt < 2; mt++) {
                int r0 = wm0 + mt * 16 + g;
                a[mt][0] = As[(r0    ) * AST + kk + tg];
                a[mt][1] = As[(r0 + 8) * AST + kk + tg];
                a[mt][2] = As[(r0    ) * AST + kk + tg + 4];
                a[mt][3] = As[(r0 + 8) * AST + kk + tg + 4];
            }
#pragma unroll
            for (int nt = 0; nt < 4; nt++) {
                int col = wn0 + nt * 8 + g;
                b[nt][0] = Bs[(kk + tg    ) * BST + col];
                b[nt][1] = Bs[(kk + tg + 4) * BST + col];
            }
#pragma unroll
            for (int mt = 0; mt < 2; mt++)
#pragma unroll
                for (int nt = 0; nt < 4; nt++)
                    mma_tf32(acc[mt][nt], a[mt][0], a[mt][1], a[mt][2], a[mt][3],
                             b[nt][0], b[nt][1]);
        }
    }

#pragma unroll
    for (int mt = 0; mt < 2; mt++) {
#pragma unroll
        for (int nt = 0; nt < 4; nt++) {
            int col = n0 + wn0 + nt * 8 + 2 * tg;
#pragma unroll
            for (int i = 0; i < 4; i++) {
                int row = m0 + wm0 + mt * 16 + g + (i >> 1) * 8;
                int c = col + (i & 1);
                if (c < N) {
                    float v = acc[mt][nt][i] + bias[c];
                    if (relu) v = fmaxf(v, 0.f);
                    C[(size_t)row * N + c] = v;
                }
            }
        }
    }
}

// ---------------- Conv (taps -1..+2) as TF32 GEMM, fused bias+ReLU -----------
__global__ __launch_bounds__(256) void conv_tf32_kernel(
    const float* __restrict__ xn,
    const float* __restrict__ w1, const float* __restrict__ w2,
    const float* __restrict__ w3, const float* __restrict__ w4,
    const float* __restrict__ b1, const float* __restrict__ b2,
    const float* __restrict__ b3, const float* __restrict__ b4,
    float* __restrict__ cv)
{
    __shared__ uint32_t As[128 * AST];
    __shared__ uint32_t Bs[32 * BST];

    int tid = threadIdx.x;
    int m0 = blockIdx.x * 128;
    int ct = blockIdx.y;            // 0..11
    int conv = ct / 3;
    int nloc0 = (ct % 3) * 64;
    int bidx = m0 >> 9;
    int t0   = m0 & 511;
    const float* wbase = (conv == 0) ? w1 : (conv == 1) ? w2 : (conv == 2) ? w3 : w4;
    const float* bias  = (conv == 0) ? b1 : (conv == 1) ? b2 : (conv == 2) ? b3 : b4;
    int ntaps = conv + 1;
    int dmin  = (conv < 2) ? 1 : 0;

    int wid = tid >> 5, lane = tid & 31;
    int wm0 = (wid & 3) * 32, wn0 = (wid >> 2) * 32;
    int g = lane >> 2, tg = lane & 3;

    float acc[2][4][4];
#pragma unroll
    for (int mt = 0; mt < 2; mt++)
#pragma unroll
        for (int nt = 0; nt < 4; nt++)
#pragma unroll
            for (int i = 0; i < 4; i++) acc[mt][nt][i] = 0.f;

    const int nk = DN / 32;          // 48
    int total = ntaps * nk;

    float4 pa[4], pb[2];
    auto loadA = [&](int it) {
        int ti = it / nk, kt = it % nk;
        int shift = dmin + ti - 1;
#pragma unroll
        for (int j = 0; j < 4; j++) {
            int idx4 = tid + j * 256;
            int row = idx4 >> 3, kc = (idx4 & 7) << 2;
            int tsrc = t0 + row + shift;
            if (tsrc >= 0 && tsrc < TN)
                pa[j] = *reinterpret_cast<const float4*>(
                    xn + (size_t)((bidx << 9) + tsrc) * DN + kt * 32 + kc);
            else
                pa[j] = make_float4(0.f, 0.f, 0.f, 0.f);
        }
    };
    auto loadB = [&](int it) {
        int ti = it / nk, kt = it % nk;
        const float* Wt = wbase + (size_t)ti * DN * C1 + nloc0;
#pragma unroll
        for (int j = 0; j < 2; j++) {
            int idx4 = tid + j * 256;
            int row = idx4 >> 4, nc = (idx4 & 15) << 2;
            pb[j] = *reinterpret_cast<const float4*>(Wt + (size_t)(kt * 32 + row) * C1 + nc);
        }
    };
    auto stage = [&]() {
#pragma unroll
        for (int j = 0; j < 4; j++) {
            int idx4 = tid + j * 256;
            int row = idx4 >> 3, kc = (idx4 & 7) << 2;
            As[row * AST + kc + 0] = f2tf32(pa[j].x);
            As[row * AST + kc + 1] = f2tf32(pa[j].y);
            As[row * AST + kc + 2] = f2tf32(pa[j].z);
            As[row * AST + kc + 3] = f2tf32(pa[j].w);
        }
#pragma unroll
        for (int j = 0; j < 2; j++) {
            int idx4 = tid + j * 256;
            int row = idx4 >> 4, nc = (idx4 & 15) << 2;
            Bs[row * BST + nc + 0] = f2tf32(pb[j].x);
            Bs[row * BST + nc + 1] = f2tf32(pb[j].y);
            Bs[row * BST + nc + 2] = f2tf32(pb[j].z);
            Bs[row * BST + nc + 3] = f2tf32(pb[j].w);
        }
    };

    loadA(0); loadB(0);
    for (int it = 0; it < total; it++) {
        __syncthreads();
        stage();
        __syncthreads();
        if (it + 1 < total) { loadA(it + 1); loadB(it + 1); }
#pragma unroll
        for (int ks = 0; ks < 4; ks++) {
            int kk = ks * 8;
            uint32_t a[2][4], b[4][2];
#pragma unroll
            for (int mt = 0; mt < 2; mt++) {
                int r0 = wm0 + mt * 16 + g;
                a[mt][0] = As[(r0    ) * AST + kk + tg];
                a[mt][1] = As[(r0 + 8) * AST + kk + tg];
                a[mt][2] = As[(r0    ) * AST + kk + tg + 4];
                a[mt][3] = As[(r0 + 8) * AST + kk + tg + 4];
            }
#pragma unroll
            for (int nt = 0; nt < 4; nt++) {
                int col = wn0 + nt * 8 + g;
                b[nt][0] = Bs[(kk + tg    ) * BST + col];
                b[nt][1] = Bs[(kk + tg + 4) * BST + col];
            }
#pragma unroll
            for (int mt = 0; mt < 2; mt++)
#pragma unroll
                for (int nt = 0; nt < 4; nt++)
                    mma_tf32(acc[mt][nt], a[mt][0], a[mt][1], a[mt][2], a[mt][3],
                             b[nt][0], b[nt][1]);
        }
    }

#pragma unroll
    for (int mt = 0; mt < 2; mt++) {
#pragma unroll
        for (int nt = 0; nt < 4; nt++) {
            int cl = wn0 + nt * 8 + 2 * tg;
#pragma unroll
            for (int i = 0; i < 4; i++) {
                int row = m0 + wm0 + mt * 16 + g + (i >> 1) * 8;
                int c   = cl + (i & 1);
                float v = acc[mt][nt][i] + bias[nloc0 + c];
                cv[(size_t)row * C4T + conv * C1 + nloc0 + c] = fmaxf(v, 0.f);
            }
        }
    }
}

// ---------------- LSTM recurrence (rewritten) --------------------------------
// 64 blocks = (dir, batch-pair), 512 threads.
// GEMM phase: thread = (ks = tid>>8 in {0,1}, c4 = tid&255). Each thread
// computes 4 consecutive gate cols for BOTH batches over its k-half using
// float4 (LDG.128) Wh loads -> Wh read exactly once per block per step.
// Partials in smem, summed in the pointwise phase.
__global__ __launch_bounds__(512) void lstm_kernel(
    const float* __restrict__ gxf, const float* __restrict__ gxb,
    const float* __restrict__ wh_f, const float* __restrict__ wh_b,
    const int* __restrict__ amask, float* __restrict__ hout)
{
    int blk = blockIdx.x;
    int dir = blk >> 5;
    int bp  = blk & 31;
    int b0  = bp * 2;
    const float* __restrict__ Wh = dir ? wh_b : wh_f;   // [256][1024]
    const float* __restrict__ gx = dir ? gxb : gxf;     // [BT][1024]

    __shared__ float h_s[2][HN], c_s[2][HN], op_s[2][HN];
    __shared__ float zp[2][2][G4];          // [ks][batch][col] partials

    int tid = threadIdx.x;
    int ks  = tid >> 8;          // 0/1 : k half
    int c4  = tid & 255;         // column group (4 cols)
    if (tid < HN) {
        h_s[0][tid] = 0.f; c_s[0][tid] = 0.f; op_s[0][tid] = 0.f;
        h_s[1][tid] = 0.f; c_s[1][tid] = 0.f; op_s[1][tid] = 0.f;
    }
    __syncthreads();

    const float* wbase = Wh + (size_t)(ks * 128) * G4 + (c4 << 2);
    const float* hrow0 = &h_s[0][ks * 128];
    const float* hrow1 = &h_s[1][ks * 128];

    for (int s = 0; s < TN; s++) {
        int t = dir ? (TN - 1 - s) : s;

        // ---- GEMM phase: z_partial[b][4c] over k half ----
        float4 a0 = make_float4(0.f, 0.f, 0.f, 0.f);
        float4 a1 = make_float4(0.f, 0.f, 0.f, 0.f);
        const float* wp = wbase;
#pragma unroll 8
        for (int k = 0; k < 128; k++) {
            float4 w = *reinterpret_cast<const float4*>(wp);
            wp += G4;
            float h0 = hrow0[k];
            float h1 = hrow1[k];
            a0.x += h0 * w.x; a0.y += h0 * w.y; a0.z += h0 * w.z; a0.w += h0 * w.w;
            a1.x += h1 * w.x; a1.y += h1 * w.y; a1.z += h1 * w.z; a1.w += h1 * w.w;
        }
        *reinterpret_cast<float4*>(&zp[ks][0][c4 << 2]) = a0;
        *reinterpret_cast<float4*>(&zp[ks][1][c4 << 2]) = a1;
        __syncthreads();

        // ---- pointwise: thread = (q = tid>>8, j = tid&255) ----
        {
            int q = tid >> 8, j = tid & 255;
            int bb_ = b0 + q;
            size_t base = ((size_t)(bb_ * TN + t)) * G4;
            float zi = zp[0][q][j      ] + zp[1][q][j      ] + gx[base + j      ];
            float zf = zp[0][q][j + 256] + zp[1][q][j + 256] + gx[base + j + 256];
            float zg = zp[0][q][j + 512] + zp[1][q][j + 512] + gx[base + j + 512];
            float zo = zp[0][q][j + 768] + zp[1][q][j + 768] + gx[base + j + 768];
            float ii = 1.f / (1.f + expf(-zi));
            float ff = 1.f / (1.f + expf(-zf));
            float gg = tanhf(zg);
            float oo = 1.f / (1.f + expf(-zo));
            float cn = ff * c_s[q][j] + ii * gg;
            float hn = oo * tanhf(cn);
            bool m = amask[bb_ * TN + t] != 0;
            float hq = m ? hn : h_s[q][j];
            float cq = m ? cn : c_s[q][j];
            float ov = m ? hn : op_s[q][j];
            h_s[q][j] = hq; c_s[q][j] = cq; op_s[q][j] = ov;
            hout[((size_t)(bb_ * TN + t)) * (2 * HN) + dir * HN + j] = ov;
        }
        __syncthreads();
    }
}

// ---------------- CRF log-likelihood: one warp per batch element -------------
__global__ __launch_bounds__(32) void crf_kernel(
    const int* __restrict__ inputs, const int* __restrict__ targets,
    const float* __restrict__ trans, const float* __restrict__ logits,
    float* __restrict__ out)
{
    int b = blockIdx.x;
    int lane = threadIdx.x;
    __shared__ float tr[LBL * LBL];
    __shared__ float alpha[LBL];
    for (int i = lane; i < LBL * LBL; i += 32) tr[i] = trans[i];

    int cnt = 0;
    for (int t = lane; t < TN; t += 32) cnt += (inputs[b * TN + t] != 0);
#pragma unroll
    for (int o = 16; o; o >>= 1) cnt += __shfl_xor_sync(0xffffffffu, cnt, o);
    int seqlen = cnt;

    const float* lg = logits + (size_t)b * TN * LBL;
    const int*   tg = targets + b * TN;

    float us = 0.f, bs = 0.f;
    for (int t = lane; t < TN; t += 32) {
        if (t < seqlen) us += lg[t * LBL + tg[t]];
        if (t >= 1 && t < seqlen) bs += tr[tg[t - 1] * LBL + tg[t]];
    }
#pragma unroll
    for (int o = 16; o; o >>= 1) {
        us += __shfl_xor_sync(0xffffffffu, us, o);
        bs += __shfl_xor_sync(0xffffffffu, bs, o);
    }

    __syncwarp();
    if (lane < LBL) alpha[lane] = lg[lane];
    __syncwarp();

    for (int t = 1; t < TN; t++) {
        float newv = 0.f;
        if (lane < LBL) {
            float m = -1e30f;
#pragma unroll
            for (int i = 0; i < LBL; i++) m = fmaxf(m, alpha[i] + tr[i * LBL + lane]);
            float ss = 0.f;
#pragma unroll
            for (int i = 0; i < LBL; i++) ss += expf(alpha[i] + tr[i * LBL + lane] - m);
            newv = m + logf(ss) + lg[t * LBL + lane];
        }
        __syncwarp();
        if (lane < LBL && t < seqlen) alpha[lane] = newv;
        __syncwarp();
    }

    float a = (lane < LBL) ? alpha[lane] : -1e30f;
    float mx = a;
#pragma unroll
    for (int o = 16; o; o >>= 1) mx = fmaxf(mx, __shfl_xor_sync(0xffffffffu, mx, o));
    float e = (lane < LBL) ? expf(a - mx) : 0.f;
#pragma unroll
    for (int o = 16; o; o >>= 1) e += __shfl_xor_sync(0xffffffffu, e, o);
    float lognorm = mx + logf(e);
    if (lane == 0) out[b] = us + bs - lognorm;
}

// ---------------- launch ------------------------------------------------------
extern "C" void kernel_launch(void* const* d_in, const int* in_sizes, int n_in,
                              void* d_out, int out_size)
{
    const int*   inputs = (const int*)  d_in[0];
    const int*   amask  = (const int*)  d_in[1];
    const int*   targets= (const int*)  d_in[2];
    const float* hid_a  = (const float*)d_in[3];
    const float* hid_b  = (const float*)d_in[4];
    const float* ln1_g  = (const float*)d_in[5];
    const float* ln1_b  = (const float*)d_in[6];
    const float* w1 = (const float*)d_in[7];
    const float* b1 = (const float*)d_in[8];
    const float* w2 = (const float*)d_in[9];
    const float* b2 = (const float*)d_in[10];
    const float* w3 = (const float*)d_in[11];
    const float* b3 = (const float*)d_in[12];
    const float* w4 = (const float*)d_in[13];
    const float* b4 = (const float*)d_in[14];
    const float* ln2_g = (const float*)d_in[15];
    const float* ln2_b = (const float*)d_in[16];
    const float* wx_f  = (const float*)d_in[17];
    const float* wh_f  = (const float*)d_in[18];
    const float* bf    = (const float*)d_in[19];
    const float* wx_b  = (const float*)d_in[20];
    const float* wh_b  = (const float*)d_in[21];
    const float* bb    = (const float*)d_in[22];
    const float* wd    = (const float*)d_in[23];
    const float* bd    = (const float*)d_in[24];
    const float* trans = (const float*)d_in[25];

    float *xn, *cv, *co, *gxf, *gxb, *hh, *lg;
    cudaGetSymbolAddress((void**)&xn,  g_xn);
    cudaGetSymbolAddress((void**)&cv,  g_cv);
    cudaGetSymbolAddress((void**)&co,  g_co);
    cudaGetSymbolAddress((void**)&gxf, g_gxf);
    cudaGetSymbolAddress((void**)&gxb, g_gxb);
    cudaGetSymbolAddress((void**)&hh,  g_h);
    cudaGetSymbolAddress((void**)&lg,  g_lg);

    ln1_kernel<<<BT, 256>>>(hid_a, hid_b, ln1_g, ln1_b, xn);
    conv_tf32_kernel<<<dim3(BT / 128, 12), 256>>>(xn, w1, w2, w3, w4, b1, b2, b3, b4, cv);
    ln2_kernel<<<BT, 256>>>(cv, ln2_g, ln2_b, co);
    gemm_tf32_kernel<<<dim3(BT / 128, 16), 256>>>(co, wx_f, bf, gxf, BT, G4, C4T, 0);
    gemm_tf32_kernel<<<dim3(BT / 128, 16), 256>>>(co, wx_b, bb, gxb, BT, G4, C4T, 0);
    lstm_kernel<<<64, 512>>>(gxf, gxb, wh_f, wh_b, amask, hh);
    gemm_tf32_kernel<<<dim3(BT / 128, 1), 256>>>(hh, wd, bd, lg, BT, LBL, 2 * HN, 0);
    crf_kernel<<<BN, 32>>>(inputs, targets, trans, lg, (float*)d_out);
}

// round 6
// speedup vs baseline: 2.0465x; 2.0465x over previous
#include <cuda_runtime.h>
#include <math.h>
#include <stdint.h>

#define BN   64
#define TN   512
#define BT   32768
#define DN   1536
#define C1   192
#define C4T  768
#define HN   256
#define G4   1024
#define LBL  20

__device__ float g_xn [ (size_t)BT * DN  ];
__device__ float g_cv [ (size_t)BT * C4T ];
__device__ float g_co [ (size_t)BT * C4T ];
__device__ float g_gxf[ (size_t)BT * G4  ];
__device__ float g_gxb[ (size_t)BT * G4  ];
__device__ float g_h  [ (size_t)BT * 2*HN];
__device__ float g_lg [ (size_t)BT * LBL ];

__device__ __forceinline__ uint32_t f2tf32(float f) {
    uint32_t u;
    asm("cvt.rna.tf32.f32 %0, %1;" : "=r"(u) : "f"(f));
    return u;
}
__device__ __forceinline__ void mma_tf32(float* c, uint32_t a0, uint32_t a1,
                                         uint32_t a2, uint32_t a3,
                                         uint32_t b0, uint32_t b1) {
    asm volatile(
        "mma.sync.aligned.m16n8k8.row.col.f32.tf32.tf32.f32 "
        "{%0,%1,%2,%3}, {%4,%5,%6,%7}, {%8,%9}, {%0,%1,%2,%3};\n"
        : "+f"(c[0]), "+f"(c[1]), "+f"(c[2]), "+f"(c[3])
        : "r"(a0), "r"(a1), "r"(a2), "r"(a3), "r"(b0), "r"(b1));
}
#define AST 36
#define BST 68

// ---------------- LayerNorm kernels ------------------------------------------
__global__ __launch_bounds__(256) void ln1_kernel(
    const float* __restrict__ ha, const float* __restrict__ hb,
    const float* __restrict__ g,  const float* __restrict__ be,
    float* __restrict__ out)
{
    int row = blockIdx.x;
    const float* A = ha + (size_t)row * 768;
    const float* B = hb + (size_t)row * 768;
    float s = 0.f, s2 = 0.f;
    for (int d = threadIdx.x; d < DN; d += 256) {
        float v = (d < 768) ? A[d] : B[d - 768];
        s += v; s2 += v * v;
    }
    __shared__ float rs[256], rq[256];
    rs[threadIdx.x] = s; rq[threadIdx.x] = s2;
    __syncthreads();
    for (int off = 128; off > 0; off >>= 1) {
        if (threadIdx.x < off) {
            rs[threadIdx.x] += rs[threadIdx.x + off];
            rq[threadIdx.x] += rq[threadIdx.x + off];
        }
        __syncthreads();
    }
    float mean = rs[0] * (1.f / DN);
    float var  = rq[0] * (1.f / DN) - mean * mean;
    float rstd = rsqrtf(var + 1e-5f);
    float* O = out + (size_t)row * DN;
    for (int d = threadIdx.x; d < DN; d += 256) {
        float v = (d < 768) ? A[d] : B[d - 768];
        O[d] = (v - mean) * rstd * g[d] + be[d];
    }
}

__global__ __launch_bounds__(256) void ln2_kernel(
    const float* __restrict__ in, const float* __restrict__ g,
    const float* __restrict__ be, float* __restrict__ out)
{
    int row = blockIdx.x;
    const float* X = in + (size_t)row * C4T;
    float s = 0.f, s2 = 0.f;
    for (int d = threadIdx.x; d < C4T; d += 256) {
        float v = X[d]; s += v; s2 += v * v;
    }
    __shared__ float rs[256], rq[256];
    rs[threadIdx.x] = s; rq[threadIdx.x] = s2;
    __syncthreads();
    for (int off = 128; off > 0; off >>= 1) {
        if (threadIdx.x < off) {
            rs[threadIdx.x] += rs[threadIdx.x + off];
            rq[threadIdx.x] += rq[threadIdx.x + off];
        }
        __syncthreads();
    }
    float mean = rs[0] * (1.f / C4T);
    float var  = rq[0] * (1.f / C4T) - mean * mean;
    float rstd = rsqrtf(var + 1e-5f);
    float* O = out + (size_t)row * C4T;
    for (int d = threadIdx.x; d < C4T; d += 256) {
        O[d] = (X[d] - mean) * rstd * g[d] + be[d];
    }
}

// ---------------- TF32 GEMM (unchanged from R3) -------------------------------
__global__ __launch_bounds__(256) void gemm_tf32_kernel(
    const float* __restrict__ A, const float* __restrict__ W,
    const float* __restrict__ bias, float* __restrict__ C,
    int M, int N, int K, int relu)
{
    __shared__ uint32_t As[128 * AST];
    __shared__ uint32_t Bs[32 * BST];
    int tid = threadIdx.x;
    int m0 = blockIdx.x * 128, n0 = blockIdx.y * 64;
    int wid = tid >> 5, lane = tid & 31;
    int wm0 = (wid & 3) * 32, wn0 = (wid >> 2) * 32;
    int g = lane >> 2, tg = lane & 3;
    float acc[2][4][4];
#pragma unroll
    for (int mt = 0; mt < 2; mt++)
#pragma unroll
        for (int nt = 0; nt < 4; nt++)
#pragma unroll
            for (int i = 0; i < 4; i++) acc[mt][nt][i] = 0.f;
    float4 pa[4], pb[2];
    int nk = K / 32;
    auto loadA = [&](int kt) {
#pragma unroll
        for (int j = 0; j < 4; j++) {
            int idx4 = tid + j * 256;
            int row = idx4 >> 3, kc = (idx4 & 7) << 2;
            pa[j] = *reinterpret_cast<const float4*>(A + (size_t)(m0 + row) * K + kt * 32 + kc);
        }
    };
    auto loadB = [&](int kt) {
#pragma unroll
        for (int j = 0; j < 2; j++) {
            int idx4 = tid + j * 256;
            int row = idx4 >> 4, nc = (idx4 & 15) << 2;
            int ncol = n0 + nc;
            const float* Wr = W + (size_t)(kt * 32 + row) * N;
            float4 v;
            if (ncol + 3 < N) v = *reinterpret_cast<const float4*>(Wr + ncol);
            else {
                v.x = (ncol + 0 < N) ? Wr[ncol + 0] : 0.f;
                v.y = (ncol + 1 < N) ? Wr[ncol + 1] : 0.f;
                v.z = (ncol + 2 < N) ? Wr[ncol + 2] : 0.f;
                v.w = (ncol + 3 < N) ? Wr[ncol + 3] : 0.f;
            }
            pb[j] = v;
        }
    };
    auto stage = [&]() {
#pragma unroll
        for (int j = 0; j < 4; j++) {
            int idx4 = tid + j * 256;
            int row = idx4 >> 3, kc = (idx4 & 7) << 2;
            As[row * AST + kc + 0] = f2tf32(pa[j].x);
            As[row * AST + kc + 1] = f2tf32(pa[j].y);
            As[row * AST + kc + 2] = f2tf32(pa[j].z);
            As[row * AST + kc + 3] = f2tf32(pa[j].w);
        }
#pragma unroll
        for (int j = 0; j < 2; j++) {
            int idx4 = tid + j * 256;
            int row = idx4 >> 4, nc = (idx4 & 15) << 2;
            Bs[row * BST + nc + 0] = f2tf32(pb[j].x);
            Bs[row * BST + nc + 1] = f2tf32(pb[j].y);
            Bs[row * BST + nc + 2] = f2tf32(pb[j].z);
            Bs[row * BST + nc + 3] = f2tf32(pb[j].w);
        }
    };
    loadA(0); loadB(0);
    for (int kt = 0; kt < nk; kt++) {
        __syncthreads();
        stage();
        __syncthreads();
        if (kt + 1 < nk) { loadA(kt + 1); loadB(kt + 1); }
#pragma unroll
        for (int ks = 0; ks < 4; ks++) {
            int kk = ks * 8;
            uint32_t a[2][4], b[4][2];
#pragma unroll
            for (int mt = 0; mt < 2; mt++) {
                int r0 = wm0 + mt * 16 + g;
                a[mt][0] = As[(r0    ) * AST + kk + tg];
                a[mt][1] = As[(r0 + 8) * AST + kk + tg];
                a[mt][2] = As[(r0    ) * AST + kk + tg + 4];
                a[mt][3] = As[(r0 + 8) * AST + kk + tg + 4];
            }
#pragma unroll
            for (int nt = 0; nt < 4; nt++) {
                int col = wn0 + nt * 8 + g;
                b[nt][0] = Bs[(kk + tg    ) * BST + col];
                b[nt][1] = Bs[(kk + tg + 4) * BST + col];
            }
#pragma unroll
            for (int mt = 0; mt < 2; mt++)
#pragma unroll
                for (int nt = 0; nt < 4; nt++)
                    mma_tf32(acc[mt][nt], a[mt][0], a[mt][1], a[mt][2], a[mt][3],
                             b[nt][0], b[nt][1]);
        }
    }
#pragma unroll
    for (int mt = 0; mt < 2; mt++)
#pragma unroll
        for (int nt = 0; nt < 4; nt++) {
            int col = n0 + wn0 + nt * 8 + 2 * tg;
#pragma unroll
            for (int i = 0; i < 4; i++) {
                int row = m0 + wm0 + mt * 16 + g + (i >> 1) * 8;
                int c = col + (i & 1);
                if (c < N) {
                    float v = acc[mt][nt][i] + bias[c];
                    if (relu) v = fmaxf(v, 0.f);
                    C[(size_t)row * N + c] = v;
                }
            }
        }
}

// ---------------- Conv as TF32 GEMM (unchanged from R3) ------------------------
__global__ __launch_bounds__(256) void conv_tf32_kernel(
    const float* __restrict__ xn,
    const float* __restrict__ w1, const float* __restrict__ w2,
    const float* __restrict__ w3, const float* __restrict__ w4,
    const float* __restrict__ b1, const float* __restrict__ b2,
    const float* __restrict__ b3, const float* __restrict__ b4,
    float* __restrict__ cv)
{
    __shared__ uint32_t As[128 * AST];
    __shared__ uint32_t Bs[32 * BST];
    int tid = threadIdx.x;
    int m0 = blockIdx.x * 128;
    int ct = blockIdx.y;
    int conv = ct / 3;
    int nloc0 = (ct % 3) * 64;
    int bidx = m0 >> 9;
    int t0   = m0 & 511;
    const float* wbase = (conv == 0) ? w1 : (conv == 1) ? w2 : (conv == 2) ? w3 : w4;
    const float* bias  = (conv == 0) ? b1 : (conv == 1) ? b2 : (conv == 2) ? b3 : b4;
    int ntaps = conv + 1;
    int dmin  = (conv < 2) ? 1 : 0;
    int wid = tid >> 5, lane = tid & 31;
    int wm0 = (wid & 3) * 32, wn0 = (wid >> 2) * 32;
    int g = lane >> 2, tg = lane & 3;
    float acc[2][4][4];
#pragma unroll
    for (int mt = 0; mt < 2; mt++)
#pragma unroll
        for (int nt = 0; nt < 4; nt++)
#pragma unroll
            for (int i = 0; i < 4; i++) acc[mt][nt][i] = 0.f;
    const int nk = DN / 32;
    int total = ntaps * nk;
    float4 pa[4], pb[2];
    auto loadA = [&](int it) {
        int ti = it / nk, kt = it % nk;
        int shift = dmin + ti - 1;
#pragma unroll
        for (int j = 0; j < 4; j++) {
            int idx4 = tid + j * 256;
            int row = idx4 >> 3, kc = (idx4 & 7) << 2;
            int tsrc = t0 + row + shift;
            if (tsrc >= 0 && tsrc < TN)
                pa[j] = *reinterpret_cast<const float4*>(
                    xn + (size_t)((bidx << 9) + tsrc) * DN + kt * 32 + kc);
            else
                pa[j] = make_float4(0.f, 0.f, 0.f, 0.f);
        }
    };
    auto loadB = [&](int it) {
        int ti = it / nk, kt = it % nk;
        const float* Wt = wbase + (size_t)ti * DN * C1 + nloc0;
#pragma unroll
        for (int j = 0; j < 2; j++) {
            int idx4 = tid + j * 256;
            int row = idx4 >> 4, nc = (idx4 & 15) << 2;
            pb[j] = *reinterpret_cast<const float4*>(Wt + (size_t)(kt * 32 + row) * C1 + nc);
        }
    };
    auto stage = [&]() {
#pragma unroll
        for (int j = 0; j < 4; j++) {
            int idx4 = tid + j * 256;
            int row = idx4 >> 3, kc = (idx4 & 7) << 2;
            As[row * AST + kc + 0] = f2tf32(pa[j].x);
            As[row * AST + kc + 1] = f2tf32(pa[j].y);
            As[row * AST + kc + 2] = f2tf32(pa[j].z);
            As[row * AST + kc + 3] = f2tf32(pa[j].w);
        }
#pragma unroll
        for (int j = 0; j < 2; j++) {
            int idx4 = tid + j * 256;
            int row = idx4 >> 4, nc = (idx4 & 15) << 2;
            Bs[row * BST + nc + 0] = f2tf32(pb[j].x);
            Bs[row * BST + nc + 1] = f2tf32(pb[j].y);
            Bs[row * BST + nc + 2] = f2tf32(pb[j].z);
            Bs[row * BST + nc + 3] = f2tf32(pb[j].w);
        }
    };
    loadA(0); loadB(0);
    for (int it = 0; it < total; it++) {
        __syncthreads();
        stage();
        __syncthreads();
        if (it + 1 < total) { loadA(it + 1); loadB(it + 1); }
#pragma unroll
        for (int ks = 0; ks < 4; ks++) {
            int kk = ks * 8;
            uint32_t a[2][4], b[4][2];
#pragma unroll
            for (int mt = 0; mt < 2; mt++) {
                int r0 = wm0 + mt * 16 + g;
                a[mt][0] = As[(r0    ) * AST + kk + tg];
                a[mt][1] = As[(r0 + 8) * AST + kk + tg];
                a[mt][2] = As[(r0    ) * AST + kk + tg + 4];
                a[mt][3] = As[(r0 + 8) * AST + kk + tg + 4];
            }
#pragma unroll
            for (int nt = 0; nt < 4; nt++) {
                int col = wn0 + nt * 8 + g;
                b[nt][0] = Bs[(kk + tg    ) * BST + col];
                b[nt][1] = Bs[(kk + tg + 4) * BST + col];
            }
#pragma unroll
            for (int mt = 0; mt < 2; mt++)
#pragma unroll
                for (int nt = 0; nt < 4; nt++)
                    mma_tf32(acc[mt][nt], a[mt][0], a[mt][1], a[mt][2], a[mt][3],
                             b[nt][0], b[nt][1]);
        }
    }
#pragma unroll
    for (int mt = 0; mt < 2; mt++)
#pragma unroll
        for (int nt = 0; nt < 4; nt++) {
            int cl = wn0 + nt * 8 + 2 * tg;
#pragma unroll
            for (int i = 0; i < 4; i++) {
                int row = m0 + wm0 + mt * 16 + g + (i >> 1) * 8;
                int c   = cl + (i & 1);
                float v = acc[mt][nt][i] + bias[nloc0 + c];
                cv[(size_t)row * C4T + conv * C1 + nloc0 + c] = fmaxf(v, 0.f);
            }
        }
}

// ---------------- LSTM: 4-CTA cluster, SMEM-resident bf16 Wh ------------------
// 128 CTAs = 32 clusters(4): cluster = (dir, 4-batch group). CTA rank owns
// hidden [64r,64r+64) with all 4 gates (256 local cols). Wh slice bf16 in smem.
// Per step: z-partials from smem weights, local pointwise, h_new DSMEM-broadcast
// into double-buffered h, one cluster barrier per step.
#define LS_WHB 131072
#define LS_HB  8192
#define LS_TOTAL (LS_WHB + LS_HB + 8192)

__global__ void __cluster_dims__(4, 1, 1) __launch_bounds__(256)
lstm_cluster_kernel(
    const float* __restrict__ gxf, const float* __restrict__ gxb,
    const float* __restrict__ wh_f, const float* __restrict__ wh_b,
    const int* __restrict__ amask, float* __restrict__ hout)
{
    extern __shared__ char sm_[];
    uint32_t* whs = (uint32_t*)sm_;                    // [256 k][128 colpairs]
    float* hsb = (float*)(sm_ + LS_WHB);               // [2 buf][4 b][256]
    float* zp  = (float*)(sm_ + LS_WHB + LS_HB);       // [2 kh][4 b][256]

    int tid = threadIdx.x;
    uint32_t rank;
    asm("mov.u32 %0, %%cluster_ctarank;" : "=r"(rank));
    int grp = blockIdx.x >> 2;
    int dir = grp >> 4;
    int b0  = (grp & 15) * 4;
    const float* __restrict__ Wh = dir ? wh_b : wh_f;  // [256][1024]
    const float* __restrict__ gx = dir ? gxb : gxf;    // [BT][1024]

    // load Wh slice -> bf16 pairs
    for (int i = tid; i < 256 * 128; i += 256) {
        int k = i >> 7, cp = i & 127;
        int l = cp << 1;
        int gcol = ((l >> 6) << 8) + (int)rank * 64 + (l & 63);
        float f0 = Wh[k * G4 + gcol], f1 = Wh[k * G4 + gcol + 1];
        uint32_t u;
        asm("cvt.rn.bf16x2.f32 %0, %1, %2;" : "=r"(u) : "f"(f1), "f"(f0));
        whs[k * 128 + cp] = u;
    }
    for (int i = tid; i < 2048; i += 256) hsb[i] = 0.f;

    int kh = tid >> 7, cp = tid & 127;      // z-phase identity
    int pb = tid >> 6, pj = tid & 63;       // pointwise identity
    int bb = b0 + pb;
    float c_r = 0.f, op_r = 0.f;

    // DSMEM broadcast addresses: value owned here lands at [buf][pb][rank*64+pj]
    uint32_t ha[2][4];
    {
        uint32_t loc;
        const void* p = (const void*)&hsb[pb * 256 + (int)rank * 64 + pj];
        asm("{ .reg .u64 t; cvta.to.shared.u64 t, %1; cvt.u32.u64 %0, t; }"
            : "=r"(loc) : "l"(p));
#pragma unroll
        for (int bf = 0; bf < 2; bf++) {
            uint32_t off = loc + bf * 4096;
#pragma unroll
            for (int r = 0; r < 4; r++)
                asm("mapa.shared::cluster.u32 %0, %1, %2;"
                    : "=r"(ha[bf][r]) : "r"(off), "r"(r));
        }
    }

    asm volatile("barrier.cluster.arrive.aligned;" ::: "memory");
    asm volatile("barrier.cluster.wait.aligned;"   ::: "memory");

    int buf = 0;
    for (int s = 0; s < TN; s++) {
        int t = dir ? (TN - 1 - s) : s;
        size_t gb = ((size_t)(bb * TN + t)) * G4 + (size_t)rank * 64 + pj;
        float gx0 = gx[gb], gx1 = gx[gb + 256], gx2 = gx[gb + 512], gx3 = gx[gb + 768];
        int mv = amask[bb * TN + t];

        // ---- z-phase: cols {2cp,2cp+1}, k in [128kh,128kh+128), 4 batches ----
        const float* hcur = hsb + buf * 1024;
        const uint32_t* wrow = whs + (kh << 7) * 128 + cp;
        const float* hb_ = hcur + (kh << 7);
        float aL0=0,aH0=0,aL1=0,aH1=0,aL2=0,aH2=0,aL3=0,aH3=0;
#pragma unroll 4
        for (int k4 = 0; k4 < 128; k4 += 4) {
            float4 H0 = *reinterpret_cast<const float4*>(hb_ + k4);
            float4 H1 = *reinterpret_cast<const float4*>(hb_ + 256 + k4);
            float4 H2 = *reinterpret_cast<const float4*>(hb_ + 512 + k4);
            float4 H3 = *reinterpret_cast<const float4*>(hb_ + 768 + k4);
#pragma unroll
            for (int q = 0; q < 4; q++) {
                uint32_t u = wrow[(k4 + q) * 128];
                float wl = __uint_as_float(u << 16);
                float wh = __uint_as_float(u & 0xffff0000u);
                float h0 = (&H0.x)[q], h1 = (&H1.x)[q], h2 = (&H2.x)[q], h3 = (&H3.x)[q];
                aL0 += wl * h0; aH0 += wh * h0;
                aL1 += wl * h1; aH1 += wh * h1;
                aL2 += wl * h2; aH2 += wh * h2;
                aL3 += wl * h3; aH3 += wh * h3;
            }
        }
        float2* zp2 = (float2*)zp;
        zp2[((kh << 2) + 0) * 128 + cp] = make_float2(aL0, aH0);
        zp2[((kh << 2) + 1) * 128 + cp] = make_float2(aL1, aH1);
        zp2[((kh << 2) + 2) * 128 + cp] = make_float2(aL2, aH2);
        zp2[((kh << 2) + 3) * 128 + cp] = make_float2(aL3, aH3);
        __syncthreads();

        // ---- pointwise for (pb, pj) ----
        {
            float zi = zp[pb * 256 + pj      ] + zp[(4 + pb) * 256 + pj      ] + gx0;
            float zf = zp[pb * 256 + pj +  64] + zp[(4 + pb) * 256 + pj +  64] + gx1;
            float zg = zp[pb * 256 + pj + 128] + zp[(4 + pb) * 256 + pj + 128] + gx2;
            float zo = zp[pb * 256 + pj + 192] + zp[(4 + pb) * 256 + pj + 192] + gx3;
            float ii = 1.f / (1.f + expf(-zi));
            float ff = 1.f / (1.f + expf(-zf));
            float gg = tanhf(zg);
            float oo = 1.f / (1.f + expf(-zo));
            float cn = ff * c_r + ii * gg;
            float hn = oo * tanhf(cn);
            bool m = mv != 0;
            float hold = hcur[pb * 256 + (int)rank * 64 + pj];
            float hq = m ? hn : hold;
            c_r  = m ? cn : c_r;
            op_r = m ? hn : op_r;
            hout[((size_t)(bb * TN + t)) * (2 * HN) + dir * HN + (int)rank * 64 + pj] = op_r;
            int nb = buf ^ 1;
#pragma unroll
            for (int r = 0; r < 4; r++)
                asm volatile("st.shared::cluster.f32 [%0], %1;"
                             :: "r"(ha[nb][r]), "f"(hq) : "memory");
        }
        asm volatile("barrier.cluster.arrive.aligned;" ::: "memory");
        asm volatile("barrier.cluster.wait.aligned;"   ::: "memory");
        buf ^= 1;
    }
}

// ---------------- CRF ----------------------------------------------------------
__global__ __launch_bounds__(32) void crf_kernel(
    const int* __restrict__ inputs, const int* __restrict__ targets,
    const float* __restrict__ trans, const float* __restrict__ logits,
    float* __restrict__ out)
{
    int b = blockIdx.x;
    int lane = threadIdx.x;
    __shared__ float tr[LBL * LBL];
    __shared__ float alpha[LBL];
    for (int i = lane; i < LBL * LBL; i += 32) tr[i] = trans[i];
    int cnt = 0;
    for (int t = lane; t < TN; t += 32) cnt += (inputs[b * TN + t] != 0);
#pragma unroll
    for (int o = 16; o; o >>= 1) cnt += __shfl_xor_sync(0xffffffffu, cnt, o);
    int seqlen = cnt;
    const float* lg = logits + (size_t)b * TN * LBL;
    const int*   tg = targets + b * TN;
    float us = 0.f, bs = 0.f;
    for (int t = lane; t < TN; t += 32) {
        if (t < seqlen) us += lg[t * LBL + tg[t]];
        if (t >= 1 && t < seqlen) bs += tr[tg[t - 1] * LBL + tg[t]];
    }
#pragma unroll
    for (int o = 16; o; o >>= 1) {
        us += __shfl_xor_sync(0xffffffffu, us, o);
        bs += __shfl_xor_sync(0xffffffffu, bs, o);
    }
    __syncwarp();
    if (lane < LBL) alpha[lane] = lg[lane];
    __syncwarp();
    for (int t = 1; t < TN; t++) {
        float newv = 0.f;
        if (lane < LBL) {
            float m = -1e30f;
#pragma unroll
            for (int i = 0; i < LBL; i++) m = fmaxf(m, alpha[i] + tr[i * LBL + lane]);
            float ss = 0.f;
#pragma unroll
            for (int i = 0; i < LBL; i++) ss += expf(alpha[i] + tr[i * LBL + lane] - m);
            newv = m + logf(ss) + lg[t * LBL + lane];
        }
        __syncwarp();
        if (lane < LBL && t < seqlen) alpha[lane] = newv;
        __syncwarp();
    }
    float a = (lane < LBL) ? alpha[lane] : -1e30f;
    float mx = a;
#pragma unroll
    for (int o = 16; o; o >>= 1) mx = fmaxf(mx, __shfl_xor_sync(0xffffffffu, mx, o));
    float e = (lane < LBL) ? expf(a - mx) : 0.f;
#pragma unroll
    for (int o = 16; o; o >>= 1) e += __shfl_xor_sync(0xffffffffu, e, o);
    float lognorm = mx + logf(e);
    if (lane == 0) out[b] = us + bs - lognorm;
}

// ---------------- launch --------------------------------------------------------
extern "C" void kernel_launch(void* const* d_in, const int* in_sizes, int n_in,
                              void* d_out, int out_size)
{
    const int*   inputs = (const int*)  d_in[0];
    const int*   amask  = (const int*)  d_in[1];
    const int*   targets= (const int*)  d_in[2];
    const float* hid_a  = (const float*)d_in[3];
    const float* hid_b  = (const float*)d_in[4];
    const float* ln1_g  = (const float*)d_in[5];
    const float* ln1_b  = (const float*)d_in[6];
    const float* w1 = (const float*)d_in[7];
    const float* b1 = (const float*)d_in[8];
    const float* w2 = (const float*)d_in[9];
    const float* b2 = (const float*)d_in[10];
    const float* w3 = (const float*)d_in[11];
    const float* b3 = (const float*)d_in[12];
    const float* w4 = (const float*)d_in[13];
    const float* b4 = (const float*)d_in[14];
    const float* ln2_g = (const float*)d_in[15];
    const float* ln2_b = (const float*)d_in[16];
    const float* wx_f  = (const float*)d_in[17];
    const float* wh_f  = (const float*)d_in[18];
    const float* bf    = (const float*)d_in[19];
    const float* wx_b  = (const float*)d_in[20];
    const float* wh_b  = (const float*)d_in[21];
    const float* bb    = (const float*)d_in[22];
    const float* wd    = (const float*)d_in[23];
    const float* bd    = (const float*)d_in[24];
    const float* trans = (const float*)d_in[25];

    float *xn, *cv, *co, *gxf, *gxb, *hh, *lg;
    cudaGetSymbolAddress((void**)&xn,  g_xn);
    cudaGetSymbolAddress((void**)&cv,  g_cv);
    cudaGetSymbolAddress((void**)&co,  g_co);
    cudaGetSymbolAddress((void**)&gxf, g_gxf);
    cudaGetSymbolAddress((void**)&gxb, g_gxb);
    cudaGetSymbolAddress((void**)&hh,  g_h);
    cudaGetSymbolAddress((void**)&lg,  g_lg);

    cudaFuncSetAttribute(lstm_cluster_kernel,
                         cudaFuncAttributeMaxDynamicSharedMemorySize, LS_TOTAL);

    ln1_kernel<<<BT, 256>>>(hid_a, hid_b, ln1_g, ln1_b, xn);
    conv_tf32_kernel<<<dim3(BT / 128, 12), 256>>>(xn, w1, w2, w3, w4, b1, b2, b3, b4, cv);
    ln2_kernel<<<BT, 256>>>(cv, ln2_g, ln2_b, co);
    gemm_tf32_kernel<<<dim3(BT / 128, 16), 256>>>(co, wx_f, bf, gxf, BT, G4, C4T, 0);
    gemm_tf32_kernel<<<dim3(BT / 128, 16), 256>>>(co, wx_b, bb, gxb, BT, G4, C4T, 0);
    lstm_cluster_kernel<<<128, 256, LS_TOTAL>>>(gxf, gxb, wh_f, wh_b, amask, hh);
    gemm_tf32_kernel<<<dim3(BT / 128, 1), 256>>>(hh, wd, bd, lg, BT, LBL, 2 * HN, 0);
    crf_kernel<<<BN, 32>>>(inputs, targets, trans, lg, (float*)d_out);
}

// round 7
// speedup vs baseline: 2.8014x; 1.3689x over previous
#include <cuda_runtime.h>
#include <math.h>
#include <stdint.h>

#define BN   64
#define TN   512
#define BT   32768
#define DN   1536
#define C1   192
#define C4T  768
#define HN   256
#define G4   1024
#define LBL  20

// ---------------- scratch (static device memory) ------------------------------
__device__ uint32_t g_xnb[ (size_t)BT * DN / 2 ];   // LN1 out, bf16 k-pairs
__device__ float    g_cv [ (size_t)BT * C4T    ];   // conv+relu out (fp32)
__device__ uint32_t g_cob[ (size_t)BT * C4T / 2];   // LN2 out, bf16 k-pairs
__device__ float    g_gxf[ (size_t)BT * G4     ];
__device__ float    g_gxb[ (size_t)BT * G4     ];
__device__ float    g_h  [ (size_t)BT * 2 * HN ];
__device__ float    g_lg [ (size_t)BT * LBL    ];
__device__ uint32_t g_wxpf[ (C4T / 2) * G4 ];       // packed wx_f
__device__ uint32_t g_wxpb[ (C4T / 2) * G4 ];       // packed wx_b
__device__ uint32_t g_cwp [ 10 * (DN / 2) * C1 ];   // packed conv weights (10 taps)

// ---------------- helpers -----------------------------------------------------
__device__ __forceinline__ uint32_t packbf(float lo, float hi) {
    uint32_t u;
    asm("cvt.rn.bf16x2.f32 %0, %1, %2;" : "=r"(u) : "f"(hi), "f"(lo));
    return u;
}
__device__ __forceinline__ uint32_t f2tf32(float f) {
    uint32_t u;
    asm("cvt.rna.tf32.f32 %0, %1;" : "=r"(u) : "f"(f));
    return u;
}
__device__ __forceinline__ void mma_bf16(float* c, uint32_t a0, uint32_t a1,
                                         uint32_t a2, uint32_t a3,
                                         uint32_t b0, uint32_t b1) {
    asm volatile(
        "mma.sync.aligned.m16n8k16.row.col.f32.bf16.bf16.f32 "
        "{%0,%1,%2,%3}, {%4,%5,%6,%7}, {%8,%9}, {%0,%1,%2,%3};\n"
        : "+f"(c[0]), "+f"(c[1]), "+f"(c[2]), "+f"(c[3])
        : "r"(a0), "r"(a1), "r"(a2), "r"(a3), "r"(b0), "r"(b1));
}
__device__ __forceinline__ void mma_tf32(float* c, uint32_t a0, uint32_t a1,
                                         uint32_t a2, uint32_t a3,
                                         uint32_t b0, uint32_t b1) {
    asm volatile(
        "mma.sync.aligned.m16n8k8.row.col.f32.tf32.tf32.f32 "
        "{%0,%1,%2,%3}, {%4,%5,%6,%7}, {%8,%9}, {%0,%1,%2,%3};\n"
        : "+f"(c[0]), "+f"(c[1]), "+f"(c[2]), "+f"(c[3])
        : "r"(a0), "r"(a1), "r"(a2), "r"(a3), "r"(b0), "r"(b1));
}

#define AST2 20     // As uint32 stride (16 kpairs + 4 pad) -> conflict-free
#define BST2 72     // Bs uint32 stride (64 cols + 8 pad)   -> conflict-free
#define AST 36
#define BST 68

// ---------------- weight prepack: fp32 [2*KP][N] -> bf16-pair [KP][N] ---------
__global__ __launch_bounds__(256) void pack_pairs_kernel(
    const float* __restrict__ W, uint32_t* __restrict__ Wp, int KP, int N)
{
    int idx = blockIdx.x * 256 + threadIdx.x;
    if (idx >= KP * N) return;
    int kp = idx / N, n = idx - kp * N;
    Wp[idx] = packbf(W[(size_t)(2 * kp) * N + n], W[(size_t)(2 * kp + 1) * N + n]);
}

// ---------------- LayerNorm 1 -> packed bf16 ----------------------------------
__global__ __launch_bounds__(256) void ln1_kernel(
    const float* __restrict__ ha, const float* __restrict__ hb,
    const float* __restrict__ g,  const float* __restrict__ be,
    uint32_t* __restrict__ out2)
{
    int row = blockIdx.x;
    const float* A = ha + (size_t)row * 768;
    const float* B = hb + (size_t)row * 768;
    float s = 0.f, s2 = 0.f;
    for (int d = threadIdx.x; d < DN; d += 256) {
        float v = (d < 768) ? A[d] : B[d - 768];
        s += v; s2 += v * v;
    }
    __shared__ float rs[256], rq[256];
    rs[threadIdx.x] = s; rq[threadIdx.x] = s2;
    __syncthreads();
    for (int off = 128; off > 0; off >>= 1) {
        if (threadIdx.x < off) {
            rs[threadIdx.x] += rs[threadIdx.x + off];
            rq[threadIdx.x] += rq[threadIdx.x + off];
        }
        __syncthreads();
    }
    float mean = rs[0] * (1.f / DN);
    float var  = rq[0] * (1.f / DN) - mean * mean;
    float rstd = rsqrtf(var + 1e-5f);
    uint32_t* O = out2 + (size_t)row * (DN / 2);
    for (int d2 = threadIdx.x; d2 < DN / 2; d2 += 256) {
        int d = d2 << 1;
        float v0 = (d < 768) ? A[d] : B[d - 768];
        float v1 = (d + 1 < 768) ? A[d + 1] : B[d + 1 - 768];
        float o0 = (v0 - mean) * rstd * g[d] + be[d];
        float o1 = (v1 - mean) * rstd * g[d + 1] + be[d + 1];
        O[d2] = packbf(o0, o1);
    }
}

// ---------------- LayerNorm 2 -> packed bf16 ----------------------------------
__global__ __launch_bounds__(256) void ln2_kernel(
    const float* __restrict__ in, const float* __restrict__ g,
    const float* __restrict__ be, uint32_t* __restrict__ out2)
{
    int row = blockIdx.x;
    const float* X = in + (size_t)row * C4T;
    float s = 0.f, s2 = 0.f;
    for (int d = threadIdx.x; d < C4T; d += 256) {
        float v = X[d]; s += v; s2 += v * v;
    }
    __shared__ float rs[256], rq[256];
    rs[threadIdx.x] = s; rq[threadIdx.x] = s2;
    __syncthreads();
    for (int off = 128; off > 0; off >>= 1) {
        if (threadIdx.x < off) {
            rs[threadIdx.x] += rs[threadIdx.x + off];
            rq[threadIdx.x] += rq[threadIdx.x + off];
        }
        __syncthreads();
    }
    float mean = rs[0] * (1.f / C4T);
    float var  = rq[0] * (1.f / C4T) - mean * mean;
    float rstd = rsqrtf(var + 1e-5f);
    uint32_t* O = out2 + (size_t)row * (C4T / 2);
    for (int d2 = threadIdx.x; d2 < C4T / 2; d2 += 256) {
        int d = d2 << 1;
        float o0 = (X[d]     - mean) * rstd * g[d]     + be[d];
        float o1 = (X[d + 1] - mean) * rstd * g[d + 1] + be[d + 1];
        O[d2] = packbf(o0, o1);
    }
}

// ---------------- bf16 tensor-core GEMM ----------------------------------------
// C[MxN] = A2[M x K/2 pairs] @ Wp[K/2 x N] + bias. Block 128x64, ktile 32,
// 8 warps (4M x 2N), warp tile 32x32, m16n8k16. M%128==0, K%32==0, N%64==0.
__global__ __launch_bounds__(256) void gemm_bf16_kernel(
    const uint32_t* __restrict__ A2, const uint32_t* __restrict__ Wp,
    const float* __restrict__ bias, float* __restrict__ C,
    int M, int N, int K)
{
    __shared__ uint32_t As[128 * AST2];
    __shared__ uint32_t Bs[16 * BST2];
    int tid = threadIdx.x;
    int m0 = blockIdx.x * 128, n0 = blockIdx.y * 64;
    int wid = tid >> 5, lane = tid & 31;
    int wm0 = (wid & 3) * 32, wn0 = (wid >> 2) * 32;
    int g = lane >> 2, tg = lane & 3;
    int K2 = K >> 1;

    float acc[2][4][4];
#pragma unroll
    for (int mt = 0; mt < 2; mt++)
#pragma unroll
        for (int nt = 0; nt < 4; nt++)
#pragma unroll
            for (int i = 0; i < 4; i++) acc[mt][nt][i] = 0.f;

    uint4 pa[2], pb;
    int nk = K / 32;
    // A: 512 uint4 loads; idx4 = tid + j*256: row = idx4>>2, qc = (idx4&3)*4
    auto loadA = [&](int kt) {
#pragma unroll
        for (int j = 0; j < 2; j++) {
            int idx4 = tid + j * 256;
            int row = idx4 >> 2, qc = (idx4 & 3) << 2;
            pa[j] = *reinterpret_cast<const uint4*>(A2 + (size_t)(m0 + row) * K2 + kt * 16 + qc);
        }
    };
    // B: 256 uint4: kp = tid>>4, nc = (tid&15)*4
    auto loadB = [&](int kt) {
        int kp = tid >> 4, nc = (tid & 15) << 2;
        pb = *reinterpret_cast<const uint4*>(Wp + (size_t)(kt * 16 + kp) * N + n0 + nc);
    };
    auto stage = [&]() {
#pragma unroll
        for (int j = 0; j < 2; j++) {
            int idx4 = tid + j * 256;
            int row = idx4 >> 2, qc = (idx4 & 3) << 2;
            *reinterpret_cast<uint4*>(&As[row * AST2 + qc]) = pa[j];
        }
        int kp = tid >> 4, nc = (tid & 15) << 2;
        *reinterpret_cast<uint4*>(&Bs[kp * BST2 + nc]) = pb;
    };

    loadA(0); loadB(0);
    for (int kt = 0; kt < nk; kt++) {
        __syncthreads();
        stage();
        __syncthreads();
        if (kt + 1 < nk) { loadA(kt + 1); loadB(kt + 1); }
#pragma unroll
        for (int ks = 0; ks < 2; ks++) {
            int kk2 = ks * 8;
            uint32_t a[2][4], b[4][2];
#pragma unroll
            for (int mt = 0; mt < 2; mt++) {
                int r0 = wm0 + mt * 16 + g;
                a[mt][0] = As[(r0    ) * AST2 + kk2 + tg];
                a[mt][1] = As[(r0 + 8) * AST2 + kk2 + tg];
                a[mt][2] = As[(r0    ) * AST2 + kk2 + tg + 4];
                a[mt][3] = As[(r0 + 8) * AST2 + kk2 + tg + 4];
            }
#pragma unroll
            for (int nt = 0; nt < 4; nt++) {
                int col = wn0 + nt * 8 + g;
                b[nt][0] = Bs[(kk2 + tg    ) * BST2 + col];
                b[nt][1] = Bs[(kk2 + tg + 4) * BST2 + col];
            }
#pragma unroll
            for (int mt = 0; mt < 2; mt++)
#pragma unroll
                for (int nt = 0; nt < 4; nt++)
                    mma_bf16(acc[mt][nt], a[mt][0], a[mt][1], a[mt][2], a[mt][3],
                             b[nt][0], b[nt][1]);
        }
    }
#pragma unroll
    for (int mt = 0; mt < 2; mt++)
#pragma unroll
        for (int nt = 0; nt < 4; nt++) {
            int col = n0 + wn0 + nt * 8 + 2 * tg;
#pragma unroll
            for (int i = 0; i < 4; i++) {
                int row = m0 + wm0 + mt * 16 + g + (i >> 1) * 8;
                int c = col + (i & 1);
                C[(size_t)row * N + c] = acc[mt][nt][i] + bias[c];
            }
        }
}

// ---------------- Conv as bf16 GEMM, fused bias+ReLU ---------------------------
__global__ __launch_bounds__(256) void conv_bf16_kernel(
    const uint32_t* __restrict__ xnb, const uint32_t* __restrict__ cwp,
    const float* __restrict__ b1, const float* __restrict__ b2,
    const float* __restrict__ b3, const float* __restrict__ b4,
    float* __restrict__ cv)
{
    __shared__ uint32_t As[128 * AST2];
    __shared__ uint32_t Bs[16 * BST2];
    int tid = threadIdx.x;
    int m0 = blockIdx.x * 128;
    int ct = blockIdx.y;              // 0..11
    int conv = ct / 3;
    int nloc0 = (ct % 3) * 64;
    int bidx = m0 >> 9;
    int t0   = m0 & 511;
    // tap base offsets into cwp (packed [10 taps][768][192])
    int tap0 = (conv == 0) ? 0 : (conv == 1) ? 1 : (conv == 2) ? 3 : 6;
    const float* bias = (conv == 0) ? b1 : (conv == 1) ? b2 : (conv == 2) ? b3 : b4;
    int ntaps = conv + 1;
    int dmin  = (conv < 2) ? 1 : 0;

    int wid = tid >> 5, lane = tid & 31;
    int wm0 = (wid & 3) * 32, wn0 = (wid >> 2) * 32;
    int g = lane >> 2, tg = lane & 3;

    float acc[2][4][4];
#pragma unroll
    for (int mt = 0; mt < 2; mt++)
#pragma unroll
        for (int nt = 0; nt < 4; nt++)
#pragma unroll
            for (int i = 0; i < 4; i++) acc[mt][nt][i] = 0.f;

    const int nk = DN / 32;            // 48
    int total = ntaps * nk;
    const int K2 = DN / 2;             // 768 pairs

    uint4 pa[2], pb;
    auto loadA = [&](int it) {
        int ti = it / nk, kt = it - ti * nk;
        int shift = dmin + ti - 1;
#pragma unroll
        for (int j = 0; j < 2; j++) {
            int idx4 = tid + j * 256;
            int row = idx4 >> 2, qc = (idx4 & 3) << 2;
            int tsrc = t0 + row + shift;
            if (tsrc >= 0 && tsrc < TN)
                pa[j] = *reinterpret_cast<const uint4*>(
                    xnb + (size_t)((bidx << 9) + tsrc) * K2 + kt * 16 + qc);
            else
                pa[j] = make_uint4(0u, 0u, 0u, 0u);
        }
    };
    auto loadB = [&](int it) {
        int ti = it / nk, kt = it - ti * nk;
        int kp = tid >> 4, nc = (tid & 15) << 2;
        pb = *reinterpret_cast<const uint4*>(
            cwp + ((size_t)(tap0 + ti) * 768 + kt * 16 + kp) * C1 + nloc0 + nc);
    };
    auto stage = [&]() {
#pragma unroll
        for (int j = 0; j < 2; j++) {
            int idx4 = tid + j * 256;
            int row = idx4 >> 2, qc = (idx4 & 3) << 2;
            *reinterpret_cast<uint4*>(&As[row * AST2 + qc]) = pa[j];
        }
        int kp = tid >> 4, nc = (tid & 15) << 2;
        *reinterpret_cast<uint4*>(&Bs[kp * BST2 + nc]) = pb;
    };

    loadA(0); loadB(0);
    for (int it = 0; it < total; it++) {
        __syncthreads();
        stage();
        __syncthreads();
        if (it + 1 < total) { loadA(it + 1); loadB(it + 1); }
#pragma unroll
        for (int ks = 0; ks < 2; ks++) {
            int kk2 = ks * 8;
            uint32_t a[2][4], b[4][2];
#pragma unroll
            for (int mt = 0; mt < 2; mt++) {
                int r0 = wm0 + mt * 16 + g;
                a[mt][0] = As[(r0    ) * AST2 + kk2 + tg];
                a[mt][1] = As[(r0 + 8) * AST2 + kk2 + tg];
                a[mt][2] = As[(r0    ) * AST2 + kk2 + tg + 4];
                a[mt][3] = As[(r0 + 8) * AST2 + kk2 + tg + 4];
            }
#pragma unroll
            for (int nt = 0; nt < 4; nt++) {
                int col = wn0 + nt * 8 + g;
                b[nt][0] = Bs[(kk2 + tg    ) * BST2 + col];
                b[nt][1] = Bs[(kk2 + tg + 4) * BST2 + col];
            }
#pragma unroll
            for (int mt = 0; mt < 2; mt++)
#pragma unroll
                for (int nt = 0; nt < 4; nt++)
                    mma_bf16(acc[mt][nt], a[mt][0], a[mt][1], a[mt][2], a[mt][3],
                             b[nt][0], b[nt][1]);
        }
    }
#pragma unroll
    for (int mt = 0; mt < 2; mt++)
#pragma unroll
        for (int nt = 0; nt < 4; nt++) {
            int cl = wn0 + nt * 8 + 2 * tg;
#pragma unroll
            for (int i = 0; i < 4; i++) {
                int row = m0 + wm0 + mt * 16 + g + (i >> 1) * 8;
                int c   = cl + (i & 1);
                float v = acc[mt][nt][i] + bias[nloc0 + c];
                cv[(size_t)row * C4T + conv * C1 + nloc0 + c] = fmaxf(v, 0.f);
            }
        }
}

// ---------------- TF32 GEMM (kept for the small logits matmul) ----------------
__global__ __launch_bounds__(256) void gemm_tf32_kernel(
    const float* __restrict__ A, const float* __restrict__ W,
    const float* __restrict__ bias, float* __restrict__ C,
    int M, int N, int K)
{
    __shared__ uint32_t As[128 * AST];
    __shared__ uint32_t Bs[32 * BST];
    int tid = threadIdx.x;
    int m0 = blockIdx.x * 128, n0 = blockIdx.y * 64;
    int wid = tid >> 5, lane = tid & 31;
    int wm0 = (wid & 3) * 32, wn0 = (wid >> 2) * 32;
    int g = lane >> 2, tg = lane & 3;
    float acc[2][4][4];
#pragma unroll
    for (int mt = 0; mt < 2; mt++)
#pragma unroll
        for (int nt = 0; nt < 4; nt++)
#pragma unroll
            for (int i = 0; i < 4; i++) acc[mt][nt][i] = 0.f;
    float4 pa[4], pb[2];
    int nk = K / 32;
    auto loadA = [&](int kt) {
#pragma unroll
        for (int j = 0; j < 4; j++) {
            int idx4 = tid + j * 256;
            int row = idx4 >> 3, kc = (idx4 & 7) << 2;
            pa[j] = *reinterpret_cast<const float4*>(A + (size_t)(m0 + row) * K + kt * 32 + kc);
        }
    };
    auto loadB = [&](int kt) {
#pragma unroll
        for (int j = 0; j < 2; j++) {
            int idx4 = tid + j * 256;
            int row = idx4 >> 4, nc = (idx4 & 15) << 2;
            int ncol = n0 + nc;
            const float* Wr = W + (size_t)(kt * 32 + row) * N;
            float4 v;
            if (ncol + 3 < N) v = *reinterpret_cast<const float4*>(Wr + ncol);
            else {
                v.x = (ncol + 0 < N) ? Wr[ncol + 0] : 0.f;
                v.y = (ncol + 1 < N) ? Wr[ncol + 1] : 0.f;
                v.z = (ncol + 2 < N) ? Wr[ncol + 2] : 0.f;
                v.w = (ncol + 3 < N) ? Wr[ncol + 3] : 0.f;
            }
            pb[j] = v;
        }
    };
    auto stage = [&]() {
#pragma unroll
        for (int j = 0; j < 4; j++) {
            int idx4 = tid + j * 256;
            int row = idx4 >> 3, kc = (idx4 & 7) << 2;
            As[row * AST + kc + 0] = f2tf32(pa[j].x);
            As[row * AST + kc + 1] = f2tf32(pa[j].y);
            As[row * AST + kc + 2] = f2tf32(pa[j].z);
            As[row * AST + kc + 3] = f2tf32(pa[j].w);
        }
#pragma unroll
        for (int j = 0; j < 2; j++) {
            int idx4 = tid + j * 256;
            int row = idx4 >> 4, nc = (idx4 & 15) << 2;
            Bs[row * BST + nc + 0] = f2tf32(pb[j].x);
            Bs[row * BST + nc + 1] = f2tf32(pb[j].y);
            Bs[row * BST + nc + 2] = f2tf32(pb[j].z);
            Bs[row * BST + nc + 3] = f2tf32(pb[j].w);
        }
    };
    loadA(0); loadB(0);
    for (int kt = 0; kt < nk; kt++) {
        __syncthreads();
        stage();
        __syncthreads();
        if (kt + 1 < nk) { loadA(kt + 1); loadB(kt + 1); }
#pragma unroll
        for (int ks = 0; ks < 4; ks++) {
            int kk = ks * 8;
            uint32_t a[2][4], b[4][2];
#pragma unroll
            for (int mt = 0; mt < 2; mt++) {
                int r0 = wm0 + mt * 16 + g;
                a[mt][0] = As[(r0    ) * AST + kk + tg];
                a[mt][1] = As[(r0 + 8) * AST + kk + tg];
                a[mt][2] = As[(r0    ) * AST + kk + tg + 4];
                a[mt][3] = As[(r0 + 8) * AST + kk + tg + 4];
            }
#pragma unroll
            for (int nt = 0; nt < 4; nt++) {
                int col = wn0 + nt * 8 + g;
                b[nt][0] = Bs[(kk + tg    ) * BST + col];
                b[nt][1] = Bs[(kk + tg + 4) * BST + col];
            }
#pragma unroll
            for (int mt = 0; mt < 2; mt++)
#pragma unroll
                for (int nt = 0; nt < 4; nt++)
                    mma_tf32(acc[mt][nt], a[mt][0], a[mt][1], a[mt][2], a[mt][3],
                             b[nt][0], b[nt][1]);
        }
    }
#pragma unroll
    for (int mt = 0; mt < 2; mt++)
#pragma unroll
        for (int nt = 0; nt < 4; nt++) {
            int col = n0 + wn0 + nt * 8 + 2 * tg;
#pragma unroll
            for (int i = 0; i < 4; i++) {
                int row = m0 + wm0 + mt * 16 + g + (i >> 1) * 8;
                int c = col + (i & 1);
                if (c < N) C[(size_t)row * N + c] = acc[mt][nt][i] + bias[c];
            }
        }
}

// ---------------- LSTM: 4-CTA cluster, SMEM-resident bf16 Wh (from R5) --------
#define LS_WHB 131072
#define LS_HB  8192
#define LS_TOTAL (LS_WHB + LS_HB + 8192)

__global__ void __cluster_dims__(4, 1, 1) __launch_bounds__(256)
lstm_cluster_kernel(
    const float* __restrict__ gxf, const float* __restrict__ gxb,
    const float* __restrict__ wh_f, const float* __restrict__ wh_b,
    const int* __restrict__ amask, float* __restrict__ hout)
{
    extern __shared__ char sm_[];
    uint32_t* whs = (uint32_t*)sm_;
    float* hsb = (float*)(sm_ + LS_WHB);
    float* zp  = (float*)(sm_ + LS_WHB + LS_HB);

    int tid = threadIdx.x;
    uint32_t rank;
    asm("mov.u32 %0, %%cluster_ctarank;" : "=r"(rank));
    int grp = blockIdx.x >> 2;
    int dir = grp >> 4;
    int b0  = (grp & 15) * 4;
    const float* __restrict__ Wh = dir ? wh_b : wh_f;
    const float* __restrict__ gx = dir ? gxb : gxf;

    for (int i = tid; i < 256 * 128; i += 256) {
        int k = i >> 7, cp = i & 127;
        int l = cp << 1;
        int gcol = ((l >> 6) << 8) + (int)rank * 64 + (l & 63);
        whs[k * 128 + cp] = packbf(Wh[k * G4 + gcol], Wh[k * G4 + gcol + 1]);
    }
    for (int i = tid; i < 2048; i += 256) hsb[i] = 0.f;

    int kh = tid >> 7, cp = tid & 127;
    int pb = tid >> 6, pj = tid & 63;
    int bb = b0 + pb;
    float c_r = 0.f, op_r = 0.f;

    uint32_t ha[2][4];
    {
        uint32_t loc;
        const void* p = (const void*)&hsb[pb * 256 + (int)rank * 64 + pj];
        asm("{ .reg .u64 t; cvta.to.shared.u64 t, %1; cvt.u32.u64 %0, t; }"
            : "=r"(loc) : "l"(p));
#pragma unroll
        for (int bf = 0; bf < 2; bf++) {
            uint32_t off = loc + bf * 4096;
#pragma unroll
            for (int r = 0; r < 4; r++)
                asm("mapa.shared::cluster.u32 %0, %1, %2;"
                    : "=r"(ha[bf][r]) : "r"(off), "r"(r));
        }
    }

    asm volatile("barrier.cluster.arrive.aligned;" ::: "memory");
    asm volatile("barrier.cluster.wait.aligned;"   ::: "memory");

    int buf = 0;
    for (int s = 0; s < TN; s++) {
        int t = dir ? (TN - 1 - s) : s;
        size_t gb = ((size_t)(bb * TN + t)) * G4 + (size_t)rank * 64 + pj;
        float gx0 = gx[gb], gx1 = gx[gb + 256], gx2 = gx[gb + 512], gx3 = gx[gb + 768];
        int mv = amask[bb * TN + t];

        const float* hcur = hsb + buf * 1024;
        const uint32_t* wrow = whs + (kh << 7) * 128 + cp;
        const float* hb_ = hcur + (kh << 7);
        float aL0=0,aH0=0,aL1=0,aH1=0,aL2=0,aH2=0,aL3=0,aH3=0;
#pragma unroll 4
        for (int k4 = 0; k4 < 128; k4 += 4) {
            float4 H0 = *reinterpret_cast<const float4*>(hb_ + k4);
            float4 H1 = *reinterpret_cast<const float4*>(hb_ + 256 + k4);
            float4 H2 = *reinterpret_cast<const float4*>(hb_ + 512 + k4);
            float4 H3 = *reinterpret_cast<const float4*>(hb_ + 768 + k4);
#pragma unroll
            for (int q = 0; q < 4; q++) {
                uint32_t u = wrow[(k4 + q) * 128];
                float wl = __uint_as_float(u << 16);
                float wh = __uint_as_float(u & 0xffff0000u);
                float h0 = (&H0.x)[q], h1 = (&H1.x)[q], h2 = (&H2.x)[q], h3 = (&H3.x)[q];
                aL0 += wl * h0; aH0 += wh * h0;
                aL1 += wl * h1; aH1 += wh * h1;
                aL2 += wl * h2; aH2 += wh * h2;
                aL3 += wl * h3; aH3 += wh * h3;
            }
        }
        float2* zp2 = (float2*)zp;
        zp2[((kh << 2) + 0) * 128 + cp] = make_float2(aL0, aH0);
        zp2[((kh << 2) + 1) * 128 + cp] = make_float2(aL1, aH1);
        zp2[((kh << 2) + 2) * 128 + cp] = make_float2(aL2, aH2);
        zp2[((kh << 2) + 3) * 128 + cp] = make_float2(aL3, aH3);
        __syncthreads();

        {
            float zi = zp[pb * 256 + pj      ] + zp[(4 + pb) * 256 + pj      ] + gx0;
            float zf = zp[pb * 256 + pj +  64] + zp[(4 + pb) * 256 + pj +  64] + gx1;
            float zg = zp[pb * 256 + pj + 128] + zp[(4 + pb) * 256 + pj + 128] + gx2;
            float zo = zp[pb * 256 + pj + 192] + zp[(4 + pb) * 256 + pj + 192] + gx3;
            float ii = 1.f / (1.f + expf(-zi));
            float ff = 1.f / (1.f + expf(-zf));
            float gg = tanhf(zg);
            float oo = 1.f / (1.f + expf(-zo));
            float cn = ff * c_r + ii * gg;
            float hn = oo * tanhf(cn);
            bool m = mv != 0;
            float hold = hcur[pb * 256 + (int)rank * 64 + pj];
            float hq = m ? hn : hold;
            c_r  = m ? cn : c_r;
            op_r = m ? hn : op_r;
            hout[((size_t)(bb * TN + t)) * (2 * HN) + dir * HN + (int)rank * 64 + pj] = op_r;
            int nb = buf ^ 1;
#pragma unroll
            for (int r = 0; r < 4; r++)
                asm volatile("st.shared::cluster.f32 [%0], %1;"
                             :: "r"(ha[nb][r]), "f"(hq) : "memory");
        }
        asm volatile("barrier.cluster.arrive.aligned;" ::: "memory");
        asm volatile("barrier.cluster.wait.aligned;"   ::: "memory");
        buf ^= 1;
    }
}

// ---------------- CRF ----------------------------------------------------------
__global__ __launch_bounds__(32) void crf_kernel(
    const int* __restrict__ inputs, const int* __restrict__ targets,
    const float* __restrict__ trans, const float* __restrict__ logits,
    float* __restrict__ out)
{
    int b = blockIdx.x;
    int lane = threadIdx.x;
    __shared__ float tr[LBL * LBL];
    __shared__ float alpha[LBL];
    for (int i = lane; i < LBL * LBL; i += 32) tr[i] = trans[i];
    int cnt = 0;
    for (int t = lane; t < TN; t += 32) cnt += (inputs[b * TN + t] != 0);
#pragma unroll
    for (int o = 16; o; o >>= 1) cnt += __shfl_xor_sync(0xffffffffu, cnt, o);
    int seqlen = cnt;
    const float* lg = logits + (size_t)b * TN * LBL;
    const int*   tg = targets + b * TN;
    float us = 0.f, bs = 0.f;
    for (int t = lane; t < TN; t += 32) {
        if (t < seqlen) us += lg[t * LBL + tg[t]];
        if (t >= 1 && t < seqlen) bs += tr[tg[t - 1] * LBL + tg[t]];
    }
#pragma unroll
    for (int o = 16; o; o >>= 1) {
        us += __shfl_xor_sync(0xffffffffu, us, o);
        bs += __shfl_xor_sync(0xffffffffu, bs, o);
    }
    __syncwarp();
    if (lane < LBL) alpha[lane] = lg[lane];
    __syncwarp();
    for (int t = 1; t < TN; t++) {
        float newv = 0.f;
        if (lane < LBL) {
            float m = -1e30f;
#pragma unroll
            for (int i = 0; i < LBL; i++) m = fmaxf(m, alpha[i] + tr[i * LBL + lane]);
            float ss = 0.f;
#pragma unroll
            for (int i = 0; i < LBL; i++) ss += expf(alpha[i] + tr[i * LBL + lane] - m);
            newv = m + logf(ss) + lg[t * LBL + lane];
        }
        __syncwarp();
        if (lane < LBL && t < seqlen) alpha[lane] = newv;
        __syncwarp();
    }
    float a = (lane < LBL) ? alpha[lane] : -1e30f;
    float mx = a;
#pragma unroll
    for (int o = 16; o; o >>= 1) mx = fmaxf(mx, __shfl_xor_sync(0xffffffffu, mx, o));
    float e = (lane < LBL) ? expf(a - mx) : 0.f;
#pragma unroll
    for (int o = 16; o; o >>= 1) e += __shfl_xor_sync(0xffffffffu, e, o);
    float lognorm = mx + logf(e);
    if (lane == 0) out[b] = us + bs - lognorm;
}

// ---------------- launch --------------------------------------------------------
extern "C" void kernel_launch(void* const* d_in, const int* in_sizes, int n_in,
                              void* d_out, int out_size)
{
    const int*   inputs = (const int*)  d_in[0];
    const int*   amask  = (const int*)  d_in[1];
    const int*   targets= (const int*)  d_in[2];
    const float* hid_a  = (const float*)d_in[3];
    const float* hid_b  = (const float*)d_in[4];
    const float* ln1_g  = (const float*)d_in[5];
    const float* ln1_b  = (const float*)d_in[6];
    const float* w1 = (const float*)d_in[7];
    const float* b1 = (const float*)d_in[8];
    const float* w2 = (const float*)d_in[9];
    const float* b2 = (const float*)d_in[10];
    const float* w3 = (const float*)d_in[11];
    const float* b3 = (const float*)d_in[12];
    const float* w4 = (const float*)d_in[13];
    const float* b4 = (const float*)d_in[14];
    const float* ln2_g = (const float*)d_in[15];
    const float* ln2_b = (const float*)d_in[16];
    const float* wx_f  = (const float*)d_in[17];
    const float* wh_f  = (const float*)d_in[18];
    const float* bf    = (const float*)d_in[19];
    const float* wx_b  = (const float*)d_in[20];
    const float* wh_b  = (const float*)d_in[21];
    const float* bb    = (const float*)d_in[22];
    const float* wd    = (const float*)d_in[23];
    const float* bd    = (const float*)d_in[24];
    const float* trans = (const float*)d_in[25];

    uint32_t *xnb, *cob, *wxpf, *wxpb, *cwp;
    float *cv, *gxf, *gxb, *hh, *lg;
    cudaGetSymbolAddress((void**)&xnb,  g_xnb);
    cudaGetSymbolAddress((void**)&cv,   g_cv);
    cudaGetSymbolAddress((void**)&cob,  g_cob);
    cudaGetSymbolAddress((void**)&gxf,  g_gxf);
    cudaGetSymbolAddress((void**)&gxb,  g_gxb);
    cudaGetSymbolAddress((void**)&hh,   g_h);
    cudaGetSymbolAddress((void**)&lg,   g_lg);
    cudaGetSymbolAddress((void**)&wxpf, g_wxpf);
    cudaGetSymbolAddress((void**)&wxpb, g_wxpb);
    cudaGetSymbolAddress((void**)&cwp,  g_cwp);

    cudaFuncSetAttribute(lstm_cluster_kernel,
                         cudaFuncAttributeMaxDynamicSharedMemorySize, LS_TOTAL);

    // weight prepack (cheap, deterministic, graph-capturable)
    {
        int n1 = (C4T / 2) * G4;                   // 393216
        pack_pairs_kernel<<<(n1 + 255) / 256, 256>>>(wx_f, wxpf, C4T / 2, G4);
        pack_pairs_kernel<<<(n1 + 255) / 256, 256>>>(wx_b, wxpb, C4T / 2, G4);
        // conv weights, flattened over taps: w1(1 tap), w2(2), w3(3), w4(4)
        int nc1 = 1 * (DN / 2) * C1, nc2 = 2 * (DN / 2) * C1;
        int nc3 = 3 * (DN / 2) * C1, nc4 = 4 * (DN / 2) * C1;
        pack_pairs_kernel<<<(nc1 + 255) / 256, 256>>>(w1, cwp,                          1 * (DN / 2), C1);
        pack_pairs_kernel<<<(nc2 + 255) / 256, 256>>>(w2, cwp + (size_t)1 * 768 * C1,   2 * (DN / 2), C1);
        pack_pairs_kernel<<<(nc3 + 255) / 256, 256>>>(w3, cwp + (size_t)3 * 768 * C1,   3 * (DN / 2), C1);
        pack_pairs_kernel<<<(nc4 + 255) / 256, 256>>>(w4, cwp + (size_t)6 * 768 * C1,   4 * (DN / 2), C1);
    }

    ln1_kernel<<<BT, 256>>>(hid_a, hid_b, ln1_g, ln1_b, xnb);
    conv_bf16_kernel<<<dim3(BT / 128, 12), 256>>>(xnb, cwp, b1, b2, b3, b4, cv);
    ln2_kernel<<<BT, 256>>>(cv, ln2_g, ln2_b, cob);
    gemm_bf16_kernel<<<dim3(BT / 128, 16), 256>>>(cob, wxpf, bf, gxf, BT, G4, C4T);
    gemm_bf16_kernel<<<dim3(BT / 128, 16), 256>>>(cob, wxpb, bb, gxb, BT, G4, C4T);
    lstm_cluster_kernel<<<128, 256, LS_TOTAL>>>(gxf, gxb, wh_f, wh_b, amask, hh);
    gemm_tf32_kernel<<<dim3(BT / 128, 1), 256>>>(hh, wd, bd, lg, BT, LBL, 2 * HN);
    crf_kernel<<<BN, 32>>>(inputs, targets, trans, lg, (float*)d_out);
}

// round 8
// speedup vs baseline: 3.3863x; 1.2088x over previous
#include <cuda_runtime.h>
#include <math.h>
#include <stdint.h>

#define BN   64
#define TN   512
#define BT   32768
#define DN   1536
#define C1   192
#define C4T  768
#define HN   256
#define G4   1024
#define LBL  20

// ---------------- scratch (static device memory) ------------------------------
__device__ uint32_t g_xnb[ (size_t)BT * DN / 2 ];
__device__ float    g_cv [ (size_t)BT * C4T    ];
__device__ uint32_t g_cob[ (size_t)BT * C4T / 2];
__device__ float    g_gxf[ (size_t)BT * G4     ];
__device__ float    g_gxb[ (size_t)BT * G4     ];
__device__ float    g_h  [ (size_t)BT * 2 * HN ];
__device__ float    g_lg [ (size_t)BT * LBL    ];
__device__ uint32_t g_wxpf[ (C4T / 2) * G4 ];
__device__ uint32_t g_wxpb[ (C4T / 2) * G4 ];
__device__ uint32_t g_cwp [ 10 * (DN / 2) * C1 ];

// ---------------- helpers -----------------------------------------------------
__device__ __forceinline__ uint32_t packbf(float lo, float hi) {
    uint32_t u;
    asm("cvt.rn.bf16x2.f32 %0, %1, %2;" : "=r"(u) : "f"(hi), "f"(lo));
    return u;
}
__device__ __forceinline__ uint32_t f2tf32(float f) {
    uint32_t u;
    asm("cvt.rna.tf32.f32 %0, %1;" : "=r"(u) : "f"(f));
    return u;
}
__device__ __forceinline__ void mma_bf16(float* c, uint32_t a0, uint32_t a1,
                                         uint32_t a2, uint32_t a3,
                                         uint32_t b0, uint32_t b1) {
    asm volatile(
        "mma.sync.aligned.m16n8k16.row.col.f32.bf16.bf16.f32 "
        "{%0,%1,%2,%3}, {%4,%5,%6,%7}, {%8,%9}, {%0,%1,%2,%3};\n"
        : "+f"(c[0]), "+f"(c[1]), "+f"(c[2]), "+f"(c[3])
        : "r"(a0), "r"(a1), "r"(a2), "r"(a3), "r"(b0), "r"(b1));
}
__device__ __forceinline__ void mma_tf32(float* c, uint32_t a0, uint32_t a1,
                                         uint32_t a2, uint32_t a3,
                                         uint32_t b0, uint32_t b1) {
    asm volatile(
        "mma.sync.aligned.m16n8k8.row.col.f32.tf32.tf32.f32 "
        "{%0,%1,%2,%3}, {%4,%5,%6,%7}, {%8,%9}, {%0,%1,%2,%3};\n"
        : "+f"(c[0]), "+f"(c[1]), "+f"(c[2]), "+f"(c[3])
        : "r"(a0), "r"(a1), "r"(a2), "r"(a3), "r"(b0), "r"(b1));
}

#define AST2 20
#define BST2 72
#define AST 36
#define BST 68

// ---------------- weight prepack ------------------------------------------------
__global__ __launch_bounds__(256) void pack_pairs_kernel(
    const float* __restrict__ W, uint32_t* __restrict__ Wp, int KP, int N)
{
    int idx = blockIdx.x * 256 + threadIdx.x;
    if (idx >= KP * N) return;
    int kp = idx / N, n = idx - kp * N;
    Wp[idx] = packbf(W[(size_t)(2 * kp) * N + n], W[(size_t)(2 * kp + 1) * N + n]);
}

// ---------------- LayerNorm 1 -> packed bf16 ------------------------------------
__global__ __launch_bounds__(256) void ln1_kernel(
    const float* __restrict__ ha, const float* __restrict__ hb,
    const float* __restrict__ g,  const float* __restrict__ be,
    uint32_t* __restrict__ out2)
{
    int row = blockIdx.x;
    const float* A = ha + (size_t)row * 768;
    const float* B = hb + (size_t)row * 768;
    float s = 0.f, s2 = 0.f;
    for (int d = threadIdx.x; d < DN; d += 256) {
        float v = (d < 768) ? A[d] : B[d - 768];
        s += v; s2 += v * v;
    }
    __shared__ float rs[256], rq[256];
    rs[threadIdx.x] = s; rq[threadIdx.x] = s2;
    __syncthreads();
    for (int off = 128; off > 0; off >>= 1) {
        if (threadIdx.x < off) {
            rs[threadIdx.x] += rs[threadIdx.x + off];
            rq[threadIdx.x] += rq[threadIdx.x + off];
        }
        __syncthreads();
    }
    float mean = rs[0] * (1.f / DN);
    float var  = rq[0] * (1.f / DN) - mean * mean;
    float rstd = rsqrtf(var + 1e-5f);
    uint32_t* O = out2 + (size_t)row * (DN / 2);
    for (int d2 = threadIdx.x; d2 < DN / 2; d2 += 256) {
        int d = d2 << 1;
        float v0 = (d < 768) ? A[d] : B[d - 768];
        float v1 = (d + 1 < 768) ? A[d + 1] : B[d + 1 - 768];
        float o0 = (v0 - mean) * rstd * g[d] + be[d];
        float o1 = (v1 - mean) * rstd * g[d + 1] + be[d + 1];
        O[d2] = packbf(o0, o1);
    }
}

// ---------------- LayerNorm 2 -> packed bf16 ------------------------------------
__global__ __launch_bounds__(256) void ln2_kernel(
    const float* __restrict__ in, const float* __restrict__ g,
    const float* __restrict__ be, uint32_t* __restrict__ out2)
{
    int row = blockIdx.x;
    const float* X = in + (size_t)row * C4T;
    float s = 0.f, s2 = 0.f;
    for (int d = threadIdx.x; d < C4T; d += 256) {
        float v = X[d]; s += v; s2 += v * v;
    }
    __shared__ float rs[256], rq[256];
    rs[threadIdx.x] = s; rq[threadIdx.x] = s2;
    __syncthreads();
    for (int off = 128; off > 0; off >>= 1) {
        if (threadIdx.x < off) {
            rs[threadIdx.x] += rs[threadIdx.x + off];
            rq[threadIdx.x] += rq[threadIdx.x + off];
        }
        __syncthreads();
    }
    float mean = rs[0] * (1.f / C4T);
    float var  = rq[0] * (1.f / C4T) - mean * mean;
    float rstd = rsqrtf(var + 1e-5f);
    uint32_t* O = out2 + (size_t)row * (C4T / 2);
    for (int d2 = threadIdx.x; d2 < C4T / 2; d2 += 256) {
        int d = d2 << 1;
        float o0 = (X[d]     - mean) * rstd * g[d]     + be[d];
        float o1 = (X[d + 1] - mean) * rstd * g[d + 1] + be[d + 1];
        O[d2] = packbf(o0, o1);
    }
}

// ---------------- bf16 tensor-core GEMM -----------------------------------------
__global__ __launch_bounds__(256) void gemm_bf16_kernel(
    const uint32_t* __restrict__ A2, const uint32_t* __restrict__ Wp,
    const float* __restrict__ bias, float* __restrict__ C,
    int M, int N, int K)
{
    __shared__ uint32_t As[128 * AST2];
    __shared__ uint32_t Bs[16 * BST2];
    int tid = threadIdx.x;
    int m0 = blockIdx.x * 128, n0 = blockIdx.y * 64;
    int wid = tid >> 5, lane = tid & 31;
    int wm0 = (wid & 3) * 32, wn0 = (wid >> 2) * 32;
    int g = lane >> 2, tg = lane & 3;
    int K2 = K >> 1;

    float acc[2][4][4];
#pragma unroll
    for (int mt = 0; mt < 2; mt++)
#pragma unroll
        for (int nt = 0; nt < 4; nt++)
#pragma unroll
            for (int i = 0; i < 4; i++) acc[mt][nt][i] = 0.f;

    uint4 pa[2], pb;
    int nk = K / 32;
    auto loadA = [&](int kt) {
#pragma unroll
        for (int j = 0; j < 2; j++) {
            int idx4 = tid + j * 256;
            int row = idx4 >> 2, qc = (idx4 & 3) << 2;
            pa[j] = *reinterpret_cast<const uint4*>(A2 + (size_t)(m0 + row) * K2 + kt * 16 + qc);
        }
    };
    auto loadB = [&](int kt) {
        int kp = tid >> 4, nc = (tid & 15) << 2;
        pb = *reinterpret_cast<const uint4*>(Wp + (size_t)(kt * 16 + kp) * N + n0 + nc);
    };
    auto stage = [&]() {
#pragma unroll
        for (int j = 0; j < 2; j++) {
            int idx4 = tid + j * 256;
            int row = idx4 >> 2, qc = (idx4 & 3) << 2;
            *reinterpret_cast<uint4*>(&As[row * AST2 + qc]) = pa[j];
        }
        int kp = tid >> 4, nc = (tid & 15) << 2;
        *reinterpret_cast<uint4*>(&Bs[kp * BST2 + nc]) = pb;
    };

    loadA(0); loadB(0);
    for (int kt = 0; kt < nk; kt++) {
        __syncthreads();
        stage();
        __syncthreads();
        if (kt + 1 < nk) { loadA(kt + 1); loadB(kt + 1); }
#pragma unroll
        for (int ks = 0; ks < 2; ks++) {
            int kk2 = ks * 8;
            uint32_t a[2][4], b[4][2];
#pragma unroll
            for (int mt = 0; mt < 2; mt++) {
                int r0 = wm0 + mt * 16 + g;
                a[mt][0] = As[(r0    ) * AST2 + kk2 + tg];
                a[mt][1] = As[(r0 + 8) * AST2 + kk2 + tg];
                a[mt][2] = As[(r0    ) * AST2 + kk2 + tg + 4];
                a[mt][3] = As[(r0 + 8) * AST2 + kk2 + tg + 4];
            }
#pragma unroll
            for (int nt = 0; nt < 4; nt++) {
                int col = wn0 + nt * 8 + g;
                b[nt][0] = Bs[(kk2 + tg    ) * BST2 + col];
                b[nt][1] = Bs[(kk2 + tg + 4) * BST2 + col];
            }
#pragma unroll
            for (int mt = 0; mt < 2; mt++)
#pragma unroll
                for (int nt = 0; nt < 4; nt++)
                    mma_bf16(acc[mt][nt], a[mt][0], a[mt][1], a[mt][2], a[mt][3],
                             b[nt][0], b[nt][1]);
        }
    }
#pragma unroll
    for (int mt = 0; mt < 2; mt++)
#pragma unroll
        for (int nt = 0; nt < 4; nt++) {
            int col = n0 + wn0 + nt * 8 + 2 * tg;
#pragma unroll
            for (int i = 0; i < 4; i++) {
                int row = m0 + wm0 + mt * 16 + g + (i >> 1) * 8;
                int c = col + (i & 1);
                C[(size_t)row * N + c] = acc[mt][nt][i] + bias[c];
            }
        }
}

// ---------------- Conv as bf16 GEMM, fused bias+ReLU ----------------------------
__global__ __launch_bounds__(256) void conv_bf16_kernel(
    const uint32_t* __restrict__ xnb, const uint32_t* __restrict__ cwp,
    const float* __restrict__ b1, const float* __restrict__ b2,
    const float* __restrict__ b3, const float* __restrict__ b4,
    float* __restrict__ cv)
{
    __shared__ uint32_t As[128 * AST2];
    __shared__ uint32_t Bs[16 * BST2];
    int tid = threadIdx.x;
    int m0 = blockIdx.x * 128;
    int ct = blockIdx.y;
    int conv = ct / 3;
    int nloc0 = (ct % 3) * 64;
    int bidx = m0 >> 9;
    int t0   = m0 & 511;
    int tap0 = (conv == 0) ? 0 : (conv == 1) ? 1 : (conv == 2) ? 3 : 6;
    const float* bias = (conv == 0) ? b1 : (conv == 1) ? b2 : (conv == 2) ? b3 : b4;
    int ntaps = conv + 1;
    int dmin  = (conv < 2) ? 1 : 0;

    int wid = tid >> 5, lane = tid & 31;
    int wm0 = (wid & 3) * 32, wn0 = (wid >> 2) * 32;
    int g = lane >> 2, tg = lane & 3;

    float acc[2][4][4];
#pragma unroll
    for (int mt = 0; mt < 2; mt++)
#pragma unroll
        for (int nt = 0; nt < 4; nt++)
#pragma unroll
            for (int i = 0; i < 4; i++) acc[mt][nt][i] = 0.f;

    const int nk = DN / 32;
    int total = ntaps * nk;
    const int K2 = DN / 2;

    uint4 pa[2], pb;
    auto loadA = [&](int it) {
        int ti = it / nk, kt = it - ti * nk;
        int shift = dmin + ti - 1;
#pragma unroll
        for (int j = 0; j < 2; j++) {
            int idx4 = tid + j * 256;
            int row = idx4 >> 2, qc = (idx4 & 3) << 2;
            int tsrc = t0 + row + shift;
            if (tsrc >= 0 && tsrc < TN)
                pa[j] = *reinterpret_cast<const uint4*>(
                    xnb + (size_t)((bidx << 9) + tsrc) * K2 + kt * 16 + qc);
            else
                pa[j] = make_uint4(0u, 0u, 0u, 0u);
        }
    };
    auto loadB = [&](int it) {
        int ti = it / nk, kt = it - ti * nk;
        int kp = tid >> 4, nc = (tid & 15) << 2;
        pb = *reinterpret_cast<const uint4*>(
            cwp + ((size_t)(tap0 + ti) * 768 + kt * 16 + kp) * C1 + nloc0 + nc);
    };
    auto stage = [&]() {
#pragma unroll
        for (int j = 0; j < 2; j++) {
            int idx4 = tid + j * 256;
            int row = idx4 >> 2, qc = (idx4 & 3) << 2;
            *reinterpret_cast<uint4*>(&As[row * AST2 + qc]) = pa[j];
        }
        int kp = tid >> 4, nc = (tid & 15) << 2;
        *reinterpret_cast<uint4*>(&Bs[kp * BST2 + nc]) = pb;
    };

    loadA(0); loadB(0);
    for (int it = 0; it < total; it++) {
        __syncthreads();
        stage();
        __syncthreads();
        if (it + 1 < total) { loadA(it + 1); loadB(it + 1); }
#pragma unroll
        for (int ks = 0; ks < 2; ks++) {
            int kk2 = ks * 8;
            uint32_t a[2][4], b[4][2];
#pragma unroll
            for (int mt = 0; mt < 2; mt++) {
                int r0 = wm0 + mt * 16 + g;
                a[mt][0] = As[(r0    ) * AST2 + kk2 + tg];
                a[mt][1] = As[(r0 + 8) * AST2 + kk2 + tg];
                a[mt][2] = As[(r0    ) * AST2 + kk2 + tg + 4];
                a[mt][3] = As[(r0 + 8) * AST2 + kk2 + tg + 4];
            }
#pragma unroll
            for (int nt = 0; nt < 4; nt++) {
                int col = wn0 + nt * 8 + g;
                b[nt][0] = Bs[(kk2 + tg    ) * BST2 + col];
                b[nt][1] = Bs[(kk2 + tg + 4) * BST2 + col];
            }
#pragma unroll
            for (int mt = 0; mt < 2; mt++)
#pragma unroll
                for (int nt = 0; nt < 4; nt++)
                    mma_bf16(acc[mt][nt], a[mt][0], a[mt][1], a[mt][2], a[mt][3],
                             b[nt][0], b[nt][1]);
        }
    }
#pragma unroll
    for (int mt = 0; mt < 2; mt++)
#pragma unroll
        for (int nt = 0; nt < 4; nt++) {
            int cl = wn0 + nt * 8 + 2 * tg;
#pragma unroll
            for (int i = 0; i < 4; i++) {
                int row = m0 + wm0 + mt * 16 + g + (i >> 1) * 8;
                int c   = cl + (i & 1);
                float v = acc[mt][nt][i] + bias[nloc0 + c];
                cv[(size_t)row * C4T + conv * C1 + nloc0 + c] = fmaxf(v, 0.f);
            }
        }
}

// ---------------- TF32 GEMM (logits) --------------------------------------------
__global__ __launch_bounds__(256) void gemm_tf32_kernel(
    const float* __restrict__ A, const float* __restrict__ W,
    const float* __restrict__ bias, float* __restrict__ C,
    int M, int N, int K)
{
    __shared__ uint32_t As[128 * AST];
    __shared__ uint32_t Bs[32 * BST];
    int tid = threadIdx.x;
    int m0 = blockIdx.x * 128, n0 = blockIdx.y * 64;
    int wid = tid >> 5, lane = tid & 31;
    int wm0 = (wid & 3) * 32, wn0 = (wid >> 2) * 32;
    int g = lane >> 2, tg = lane & 3;
    float acc[2][4][4];
#pragma unroll
    for (int mt = 0; mt < 2; mt++)
#pragma unroll
        for (int nt = 0; nt < 4; nt++)
#pragma unroll
            for (int i = 0; i < 4; i++) acc[mt][nt][i] = 0.f;
    float4 pa[4], pb[2];
    int nk = K / 32;
    auto loadA = [&](int kt) {
#pragma unroll
        for (int j = 0; j < 4; j++) {
            int idx4 = tid + j * 256;
            int row = idx4 >> 3, kc = (idx4 & 7) << 2;
            pa[j] = *reinterpret_cast<const float4*>(A + (size_t)(m0 + row) * K + kt * 32 + kc);
        }
    };
    auto loadB = [&](int kt) {
#pragma unroll
        for (int j = 0; j < 2; j++) {
            int idx4 = tid + j * 256;
            int row = idx4 >> 4, nc = (idx4 & 15) << 2;
            int ncol = n0 + nc;
            const float* Wr = W + (size_t)(kt * 32 + row) * N;
            float4 v;
            if (ncol + 3 < N) v = *reinterpret_cast<const float4*>(Wr + ncol);
            else {
                v.x = (ncol + 0 < N) ? Wr[ncol + 0] : 0.f;
                v.y = (ncol + 1 < N) ? Wr[ncol + 1] : 0.f;
                v.z = (ncol + 2 < N) ? Wr[ncol + 2] : 0.f;
                v.w = (ncol + 3 < N) ? Wr[ncol + 3] : 0.f;
            }
            pb[j] = v;
        }
    };
    auto stage = [&]() {
#pragma unroll
        for (int j = 0; j < 4; j++) {
            int idx4 = tid + j * 256;
            int row = idx4 >> 3, kc = (idx4 & 7) << 2;
            As[row * AST + kc + 0] = f2tf32(pa[j].x);
            As[row * AST + kc + 1] = f2tf32(pa[j].y);
            As[row * AST + kc + 2] = f2tf32(pa[j].z);
            As[row * AST + kc + 3] = f2tf32(pa[j].w);
        }
#pragma unroll
        for (int j = 0; j < 2; j++) {
            int idx4 = tid + j * 256;
            int row = idx4 >> 4, nc = (idx4 & 15) << 2;
            Bs[row * BST + nc + 0] = f2tf32(pb[j].x);
            Bs[row * BST + nc + 1] = f2tf32(pb[j].y);
            Bs[row * BST + nc + 2] = f2tf32(pb[j].z);
            Bs[row * BST + nc + 3] = f2tf32(pb[j].w);
        }
    };
    loadA(0); loadB(0);
    for (int kt = 0; kt < nk; kt++) {
        __syncthreads();
        stage();
        __syncthreads();
        if (kt + 1 < nk) { loadA(kt + 1); loadB(kt + 1); }
#pragma unroll
        for (int ks = 0; ks < 4; ks++) {
            int kk = ks * 8;
            uint32_t a[2][4], b[4][2];
#pragma unroll
            for (int mt = 0; mt < 2; mt++) {
                int r0 = wm0 + mt * 16 + g;
                a[mt][0] = As[(r0    ) * AST + kk + tg];
                a[mt][1] = As[(r0 + 8) * AST + kk + tg];
                a[mt][2] = As[(r0    ) * AST + kk + tg + 4];
                a[mt][3] = As[(r0 + 8) * AST + kk + tg + 4];
            }
#pragma unroll
            for (int nt = 0; nt < 4; nt++) {
                int col = wn0 + nt * 8 + g;
                b[nt][0] = Bs[(kk + tg    ) * BST + col];
                b[nt][1] = Bs[(kk + tg + 4) * BST + col];
            }
#pragma unroll
            for (int mt = 0; mt < 2; mt++)
#pragma unroll
                for (int nt = 0; nt < 4; nt++)
                    mma_tf32(acc[mt][nt], a[mt][0], a[mt][1], a[mt][2], a[mt][3],
                             b[nt][0], b[nt][1]);
        }
    }
#pragma unroll
    for (int mt = 0; mt < 2; mt++)
#pragma unroll
        for (int nt = 0; nt < 4; nt++) {
            int col = n0 + wn0 + nt * 8 + 2 * tg;
#pragma unroll
            for (int i = 0; i < 4; i++) {
                int row = m0 + wm0 + mt * 16 + g + (i >> 1) * 8;
                int c = col + (i & 1);
                if (c < N) C[(size_t)row * N + c] = acc[mt][nt][i] + bias[c];
            }
        }
}

// ---------------- LSTM: 4-CTA cluster, tensor-core z-phase ----------------------
// Cluster = (dir, 4-batch group). CTA rank owns lcol = gate*64+hid (256 cols).
// Weights SMEM-resident transposed: whs2[lcol][kpair] bf16 pairs, stride 132.
// Per step: D[256 x 4] = Whs2 @ h (m16n8k16 bf16, h bf16 [kpair][8], batches 4-7
// zero), extract to zbuf fp32, pointwise, h_new bf16 DSMEM-broadcast (dbl-buf).
#define LSW   (256 * 132 * 4)            // 135168
#define LSH2  (2 * 128 * 8 * 4)          // 8192
#define LSZ   (256 * 5 * 4)              // 5120
#define LS_TOTAL (LSW + LSH2 + LSZ)

__global__ void __cluster_dims__(4, 1, 1) __launch_bounds__(256)
lstm_cluster_kernel(
    const float* __restrict__ gxf, const float* __restrict__ gxb,
    const float* __restrict__ wh_f, const float* __restrict__ wh_b,
    const int* __restrict__ amask, float* __restrict__ hout)
{
    extern __shared__ char sm_[];
    uint32_t* whs2 = (uint32_t*)sm_;                 // [256 lcol][132]
    uint32_t* h2   = (uint32_t*)(sm_ + LSW);         // [2 buf][128 kp][8 n]
    float*    zbuf = (float*)(sm_ + LSW + LSH2);     // [256 lcol][5]

    int tid = threadIdx.x;
    uint32_t rank;
    asm("mov.u32 %0, %%cluster_ctarank;" : "=r"(rank));
    int grp = blockIdx.x >> 2;
    int dir = grp >> 4;
    int b0  = (grp & 15) * 4;
    const float* __restrict__ Wh = dir ? wh_b : wh_f;
    const float* __restrict__ gx = dir ? gxb : gxf;

    // Wh slice transposed into smem: whs2[lcol][kp] = {Wh[2kp][gcol], Wh[2kp+1][gcol]}
    for (int i = tid; i < 256 * 128; i += 256) {
        int lcol = i >> 7, kp = i & 127;
        int gcol = ((lcol >> 6) << 8) + (int)rank * 64 + (lcol & 63);
        whs2[lcol * 132 + kp] = packbf(Wh[(2 * kp) * G4 + gcol],
                                       Wh[(2 * kp + 1) * G4 + gcol]);
    }
    for (int i = tid; i < 2048; i += 256) h2[i] = 0u;

    int lane = tid & 31, wrp = tid >> 5;
    int g = lane >> 2, tg = lane & 3;
    int pb = tid >> 6, pj = tid & 63;
    int bb = b0 + pb;
    float h_r = 0.f, c_r = 0.f, op_r = 0.f;

    // DSMEM write addresses for this thread's h (bf16 halfword, both buffers, 4 CTAs)
    uint32_t ha[2][4];
    {
        int k = (int)rank * 64 + pj;
        uint32_t loc;
        const void* p = (const void*)((const char*)h2 + ((k >> 1) * 8 + pb) * 4 + (k & 1) * 2);
        asm("{ .reg .u64 t; cvta.to.shared.u64 t, %1; cvt.u32.u64 %0, t; }"
            : "=r"(loc) : "l"(p));
#pragma unroll
        for (int bf = 0; bf < 2; bf++) {
            uint32_t off = loc + bf * 4096;
#pragma unroll
            for (int r = 0; r < 4; r++)
                asm("mapa.shared::cluster.u32 %0, %1, %2;"
                    : "=r"(ha[bf][r]) : "r"(off), "r"(r));
        }
    }

    asm volatile("barrier.cluster.arrive.aligned;" ::: "memory");
    asm volatile("barrier.cluster.wait.aligned;"   ::: "memory");

    int buf = 0;
    for (int s = 0; s < TN; s++) {
        int t = dir ? (TN - 1 - s) : s;
        size_t gb = ((size_t)(bb * TN + t)) * G4 + (size_t)rank * 64 + pj;
        float gx0 = gx[gb], gx1 = gx[gb + 256], gx2 = gx[gb + 512], gx3 = gx[gb + 768];
        int mv = amask[bb * TN + t];

        // ---- z-phase: warp wrp covers lcols [32w, 32w+32) over K=256 ----
        const uint32_t* h2c = h2 + buf * 1024;
        float d0[4] = {0.f, 0.f, 0.f, 0.f}, d1[4] = {0.f, 0.f, 0.f, 0.f};
        int r0 = wrp * 32 + g;
#pragma unroll
        for (int kt = 0; kt < 16; kt++) {
            int kk2 = kt * 8;
            uint32_t bq0 = h2c[(kk2 + tg) * 8 + g];
            uint32_t bq1 = h2c[(kk2 + tg + 4) * 8 + g];
            uint32_t a0 = whs2[(r0     ) * 132 + kk2 + tg];
            uint32_t a1 = whs2[(r0 +  8) * 132 + kk2 + tg];
            uint32_t a2 = whs2[(r0     ) * 132 + kk2 + tg + 4];
            uint32_t a3 = whs2[(r0 +  8) * 132 + kk2 + tg + 4];
            mma_bf16(d0, a0, a1, a2, a3, bq0, bq1);
            a0 = whs2[(r0 + 16) * 132 + kk2 + tg];
            a1 = whs2[(r0 + 24) * 132 + kk2 + tg];
            a2 = whs2[(r0 + 16) * 132 + kk2 + tg + 4];
            a3 = whs2[(r0 + 24) * 132 + kk2 + tg + 4];
            mma_bf16(d1, a0, a1, a2, a3, bq0, bq1);
        }
        if (tg < 2) {
#pragma unroll
            for (int i = 0; i < 4; i++) {
                int col = 2 * tg + (i & 1);
                zbuf[(r0 + (i >> 1) * 8     ) * 5 + col] = d0[i];
                zbuf[(r0 + (i >> 1) * 8 + 16) * 5 + col] = d1[i];
            }
        }
        __syncthreads();

        // ---- pointwise: (pb, pj) ----
        {
            float zi = zbuf[(      pj) * 5 + pb] + gx0;
            float zf = zbuf[( 64 + pj) * 5 + pb] + gx1;
            float zg = zbuf[(128 + pj) * 5 + pb] + gx2;
            float zo = zbuf[(192 + pj) * 5 + pb] + gx3;
            float ii = 1.f / (1.f + expf(-zi));
            float ff = 1.f / (1.f + expf(-zf));
            float gg = tanhf(zg);
            float oo = 1.f / (1.f + expf(-zo));
            float cn = ff * c_r + ii * gg;
            float hn = oo * tanhf(cn);
            bool m = mv != 0;
            float hq = m ? hn : h_r;
            c_r  = m ? cn : c_r;
            op_r = m ? hn : op_r;
            h_r  = hq;
            hout[((size_t)(bb * TN + t)) * (2 * HN) + dir * HN + (int)rank * 64 + pj] = op_r;
            uint16_t hb16;
            asm("cvt.rn.bf16.f32 %0, %1;" : "=h"(hb16) : "f"(hq));
            int nb = buf ^ 1;
#pragma unroll
            for (int r = 0; r < 4; r++)
                asm volatile("st.shared::cluster.b16 [%0], %1;"
                             :: "r"(ha[nb][r]), "h"(hb16) : "memory");
        }
        asm volatile("barrier.cluster.arrive.aligned;" ::: "memory");
        asm volatile("barrier.cluster.wait.aligned;"   ::: "memory");
        buf ^= 1;
    }
}

// ---------------- CRF ------------------------------------------------------------
__global__ __launch_bounds__(32) void crf_kernel(
    const int* __restrict__ inputs, const int* __restrict__ targets,
    const float* __restrict__ trans, const float* __restrict__ logits,
    float* __restrict__ out)
{
    int b = blockIdx.x;
    int lane = threadIdx.x;
    __shared__ float tr[LBL * LBL];
    __shared__ float alpha[LBL];
    for (int i = lane; i < LBL * LBL; i += 32) tr[i] = trans[i];
    int cnt = 0;
    for (int t = lane; t < TN; t += 32) cnt += (inputs[b * TN + t] != 0);
#pragma unroll
    for (int o = 16; o; o >>= 1) cnt += __shfl_xor_sync(0xffffffffu, cnt, o);
    int seqlen = cnt;
    const float* lg = logits + (size_t)b * TN * LBL;
    const int*   tg = targets + b * TN;
    float us = 0.f, bs = 0.f;
    for (int t = lane; t < TN; t += 32) {
        if (t < seqlen) us += lg[t * LBL + tg[t]];
        if (t >= 1 && t < seqlen) bs += tr[tg[t - 1] * LBL + tg[t]];
    }
#pragma unroll
    for (int o = 16; o; o >>= 1) {
        us += __shfl_xor_sync(0xffffffffu, us, o);
        bs += __shfl_xor_sync(0xffffffffu, bs, o);
    }
    __syncwarp();
    if (lane < LBL) alpha[lane] = lg[lane];
    __syncwarp();
    for (int t = 1; t < TN; t++) {
        float newv = 0.f;
        if (lane < LBL) {
            float m = -1e30f;
#pragma unroll
            for (int i = 0; i < LBL; i++) m = fmaxf(m, alpha[i] + tr[i * LBL + lane]);
            float ss = 0.f;
#pragma unroll
            for (int i = 0; i < LBL; i++) ss += expf(alpha[i] + tr[i * LBL + lane] - m);
            newv = m + logf(ss) + lg[t * LBL + lane];
        }
        __syncwarp();
        if (lane < LBL && t < seqlen) alpha[lane] = newv;
        __syncwarp();
    }
    float a = (lane < LBL) ? alpha[lane] : -1e30f;
    float mx = a;
#pragma unroll
    for (int o = 16; o; o >>= 1) mx = fmaxf(mx, __shfl_xor_sync(0xffffffffu, mx, o));
    float e = (lane < LBL) ? expf(a - mx) : 0.f;
#pragma unroll
    for (int o = 16; o; o >>= 1) e += __shfl_xor_sync(0xffffffffu, e, o);
    float lognorm = mx + logf(e);
    if (lane == 0) out[b] = us + bs - lognorm;
}

// ---------------- launch -----------------------------------------------------------
extern "C" void kernel_launch(void* const* d_in, const int* in_sizes, int n_in,
                              void* d_out, int out_size)
{
    const int*   inputs = (const int*)  d_in[0];
    const int*   amask  = (const int*)  d_in[1];
    const int*   targets= (const int*)  d_in[2];
    const float* hid_a  = (const float*)d_in[3];
    const float* hid_b  = (const float*)d_in[4];
    const float* ln1_g  = (const float*)d_in[5];
    const float* ln1_b  = (const float*)d_in[6];
    const float* w1 = (const float*)d_in[7];
    const float* b1 = (const float*)d_in[8];
    const float* w2 = (const float*)d_in[9];
    const float* b2 = (const float*)d_in[10];
    const float* w3 = (const float*)d_in[11];
    const float* b3 = (const float*)d_in[12];
    const float* w4 = (const float*)d_in[13];
    const float* b4 = (const float*)d_in[14];
    const float* ln2_g = (const float*)d_in[15];
    const float* ln2_b = (const float*)d_in[16];
    const float* wx_f  = (const float*)d_in[17];
    const float* wh_f  = (const float*)d_in[18];
    const float* bf    = (const float*)d_in[19];
    const float* wx_b  = (const float*)d_in[20];
    const float* wh_b  = (const float*)d_in[21];
    const float* bb    = (const float*)d_in[22];
    const float* wd    = (const float*)d_in[23];
    const float* bd    = (const float*)d_in[24];
    const float* trans = (const float*)d_in[25];

    uint32_t *xnb, *cob, *wxpf, *wxpb, *cwp;
    float *cv, *gxf, *gxb, *hh, *lg;
    cudaGetSymbolAddress((void**)&xnb,  g_xnb);
    cudaGetSymbolAddress((void**)&cv,   g_cv);
    cudaGetSymbolAddress((void**)&cob,  g_cob);
    cudaGetSymbolAddress((void**)&gxf,  g_gxf);
    cudaGetSymbolAddress((void**)&gxb,  g_gxb);
    cudaGetSymbolAddress((void**)&hh,   g_h);
    cudaGetSymbolAddress((void**)&lg,   g_lg);
    cudaGetSymbolAddress((void**)&wxpf, g_wxpf);
    cudaGetSymbolAddress((void**)&wxpb, g_wxpb);
    cudaGetSymbolAddress((void**)&cwp,  g_cwp);

    cudaFuncSetAttribute(lstm_cluster_kernel,
                         cudaFuncAttributeMaxDynamicSharedMemorySize, LS_TOTAL);

    {
        int n1 = (C4T / 2) * G4;
        pack_pairs_kernel<<<(n1 + 255) / 256, 256>>>(wx_f, wxpf, C4T / 2, G4);
        pack_pairs_kernel<<<(n1 + 255) / 256, 256>>>(wx_b, wxpb, C4T / 2, G4);
        int nc1 = 1 * (DN / 2) * C1, nc2 = 2 * (DN / 2) * C1;
        int nc3 = 3 * (DN / 2) * C1, nc4 = 4 * (DN / 2) * C1;
        pack_pairs_kernel<<<(nc1 + 255) / 256, 256>>>(w1, cwp,                        1 * (DN / 2), C1);
        pack_pairs_kernel<<<(nc2 + 255) / 256, 256>>>(w2, cwp + (size_t)1 * 768 * C1, 2 * (DN / 2), C1);
        pack_pairs_kernel<<<(nc3 + 255) / 256, 256>>>(w3, cwp + (size_t)3 * 768 * C1, 3 * (DN / 2), C1);
        pack_pairs_kernel<<<(nc4 + 255) / 256, 256>>>(w4, cwp + (size_t)6 * 768 * C1, 4 * (DN / 2), C1);
    }

    ln1_kernel<<<BT, 256>>>(hid_a, hid_b, ln1_g, ln1_b, xnb);
    conv_bf16_kernel<<<dim3(BT / 128, 12), 256>>>(xnb, cwp, b1, b2, b3, b4, cv);
    ln2_kernel<<<BT, 256>>>(cv, ln2_g, ln2_b, cob);
    gemm_bf16_kernel<<<dim3(BT / 128, 16), 256>>>(cob, wxpf, bf, gxf, BT, G4, C4T);
    gemm_bf16_kernel<<<dim3(BT / 128, 16), 256>>>(cob, wxpb, bb, gxb, BT, G4, C4T);
    lstm_cluster_kernel<<<128, 256, LS_TOTAL>>>(gxf, gxb, wh_f, wh_b, amask, hh);
    gemm_tf32_kernel<<<dim3(BT / 128, 1), 256>>>(hh, wd, bd, lg, BT, LBL, 2 * HN);
    crf_kernel<<<BN, 32>>>(inputs, targets, trans, lg, (float*)d_out);
}

// round 10
// speedup vs baseline: 3.4423x; 1.0165x over previous
#include <cuda_runtime.h>
#include <math.h>
#include <stdint.h>

#define BN   64
#define TN   512
#define BT   32768
#define DN   1536
#define C1   192
#define C4T  768
#define HN   256
#define G4   1024
#define LBL  20

// ---------------- scratch (static device memory) ------------------------------
__device__ uint32_t g_xnb[ (size_t)BT * DN / 2 ];
__device__ float    g_cv [ (size_t)BT * C4T    ];
__device__ uint32_t g_cob[ (size_t)BT * C4T / 2];
__device__ float    g_gxf[ (size_t)BT * G4     ];
__device__ float    g_gxb[ (size_t)BT * G4     ];
__device__ float    g_h  [ (size_t)BT * 2 * HN ];
__device__ float    g_lg [ (size_t)BT * LBL    ];
__device__ uint32_t g_wxpf[ (C4T / 2) * G4 ];
__device__ uint32_t g_wxpb[ (C4T / 2) * G4 ];
__device__ uint32_t g_cwp [ 10 * (DN / 2) * C1 ];

// ---------------- helpers -----------------------------------------------------
__device__ __forceinline__ uint32_t packbf(float lo, float hi) {
    uint32_t u;
    asm("cvt.rn.bf16x2.f32 %0, %1, %2;" : "=r"(u) : "f"(hi), "f"(lo));
    return u;
}
__device__ __forceinline__ uint32_t f2tf32(float f) {
    uint32_t u;
    asm("cvt.rna.tf32.f32 %0, %1;" : "=r"(u) : "f"(f));
    return u;
}
__device__ __forceinline__ void mma_bf16(float* c, uint32_t a0, uint32_t a1,
                                         uint32_t a2, uint32_t a3,
                                         uint32_t b0, uint32_t b1) {
    asm volatile(
        "mma.sync.aligned.m16n8k16.row.col.f32.bf16.bf16.f32 "
        "{%0,%1,%2,%3}, {%4,%5,%6,%7}, {%8,%9}, {%0,%1,%2,%3};\n"
        : "+f"(c[0]), "+f"(c[1]), "+f"(c[2]), "+f"(c[3])
        : "r"(a0), "r"(a1), "r"(a2), "r"(a3), "r"(b0), "r"(b1));
}
__device__ __forceinline__ void mma_tf32(float* c, uint32_t a0, uint32_t a1,
                                         uint32_t a2, uint32_t a3,
                                         uint32_t b0, uint32_t b1) {
    asm volatile(
        "mma.sync.aligned.m16n8k8.row.col.f32.tf32.tf32.f32 "
        "{%0,%1,%2,%3}, {%4,%5,%6,%7}, {%8,%9}, {%0,%1,%2,%3};\n"
        : "+f"(c[0]), "+f"(c[1]), "+f"(c[2]), "+f"(c[3])
        : "r"(a0), "r"(a1), "r"(a2), "r"(a3), "r"(b0), "r"(b1));
}
__device__ __forceinline__ void ldsm4(uint32_t* a, uint32_t saddr) {
    asm volatile("ldmatrix.sync.aligned.m8n8.x4.shared.b16 {%0,%1,%2,%3}, [%4];"
                 : "=r"(a[0]), "=r"(a[1]), "=r"(a[2]), "=r"(a[3]) : "r"(saddr));
}

#define AST2 20
#define BST2 72
#define AST 36
#define BST 68

// ---------------- weight prepack ------------------------------------------------
__global__ __launch_bounds__(256) void pack_pairs_kernel(
    const float* __restrict__ W, uint32_t* __restrict__ Wp, int KP, int Nc)
{
    int idx = blockIdx.x * 256 + threadIdx.x;
    if (idx >= KP * Nc) return;
    int kp = idx / Nc, n = idx - kp * Nc;
    Wp[idx] = packbf(W[(size_t)(2 * kp) * Nc + n], W[(size_t)(2 * kp + 1) * Nc + n]);
}

// ---------------- LayerNorm 1 -> packed bf16 ------------------------------------
__global__ __launch_bounds__(256) void ln1_kernel(
    const float* __restrict__ ha, const float* __restrict__ hb,
    const float* __restrict__ g,  const float* __restrict__ be,
    uint32_t* __restrict__ out2)
{
    int row = blockIdx.x;
    const float* A = ha + (size_t)row * 768;
    const float* B = hb + (size_t)row * 768;
    float s = 0.f, s2 = 0.f;
    for (int d = threadIdx.x; d < DN; d += 256) {
        float v = (d < 768) ? A[d] : B[d - 768];
        s += v; s2 += v * v;
    }
    __shared__ float rs[256], rq[256];
    rs[threadIdx.x] = s; rq[threadIdx.x] = s2;
    __syncthreads();
    for (int off = 128; off > 0; off >>= 1) {
        if (threadIdx.x < off) {
            rs[threadIdx.x] += rs[threadIdx.x + off];
            rq[threadIdx.x] += rq[threadIdx.x + off];
        }
        __syncthreads();
    }
    float mean = rs[0] * (1.f / DN);
    float var  = rq[0] * (1.f / DN) - mean * mean;
    float rstd = rsqrtf(var + 1e-5f);
    uint32_t* O = out2 + (size_t)row * (DN / 2);
    for (int d2 = threadIdx.x; d2 < DN / 2; d2 += 256) {
        int d = d2 << 1;
        float v0 = (d < 768) ? A[d] : B[d - 768];
        float v1 = (d + 1 < 768) ? A[d + 1] : B[d + 1 - 768];
        float o0 = (v0 - mean) * rstd * g[d] + be[d];
        float o1 = (v1 - mean) * rstd * g[d + 1] + be[d + 1];
        O[d2] = packbf(o0, o1);
    }
}

// ---------------- LayerNorm 2 -> packed bf16 ------------------------------------
__global__ __launch_bounds__(256) void ln2_kernel(
    const float* __restrict__ in, const float* __restrict__ g,
    const float* __restrict__ be, uint32_t* __restrict__ out2)
{
    int row = blockIdx.x;
    const float* X = in + (size_t)row * C4T;
    float s = 0.f, s2 = 0.f;
    for (int d = threadIdx.x; d < C4T; d += 256) {
        float v = X[d]; s += v; s2 += v * v;
    }
    __shared__ float rs[256], rq[256];
    rs[threadIdx.x] = s; rq[threadIdx.x] = s2;
    __syncthreads();
    for (int off = 128; off > 0; off >>= 1) {
        if (threadIdx.x < off) {
            rs[threadIdx.x] += rs[threadIdx.x + off];
            rq[threadIdx.x] += rq[threadIdx.x + off];
        }
        __syncthreads();
    }
    float mean = rs[0] * (1.f / C4T);
    float var  = rq[0] * (1.f / C4T) - mean * mean;
    float rstd = rsqrtf(var + 1e-5f);
    uint32_t* O = out2 + (size_t)row * (C4T / 2);
    for (int d2 = threadIdx.x; d2 < C4T / 2; d2 += 256) {
        int d = d2 << 1;
        float o0 = (X[d]     - mean) * rstd * g[d]     + be[d];
        float o1 = (X[d + 1] - mean) * rstd * g[d + 1] + be[d + 1];
        O[d2] = packbf(o0, o1);
    }
}

// ---------------- bf16 GEMM, 2-stage pipeline + ldmatrix -----------------------
// Dual-weight: grid.y in [0, 2*nhalf); half selects (Wp, bias, C) set.
// Fixed shapes: M=BT, N=G4, K=C4T.
__global__ __launch_bounds__(256) void gemm_bf16_dual_kernel(
    const uint32_t* __restrict__ A2,
    const uint32_t* __restrict__ Wpf, const uint32_t* __restrict__ Wpb,
    const float* __restrict__ biasf, const float* __restrict__ biasb,
    float* __restrict__ Cf, float* __restrict__ Cb, int nhalf)
{
    const int Nn = G4, Kk = C4T;
    __shared__ uint32_t As[2][128 * AST2];
    __shared__ uint32_t Bs[2][16 * BST2];
    int tid = threadIdx.x;
    int half = blockIdx.y / nhalf;
    int n0 = (blockIdx.y - half * nhalf) * 64;
    const uint32_t* Wp   = half ? Wpb : Wpf;
    const float*    bias = half ? biasb : biasf;
    float*          Cc   = half ? Cb : Cf;
    int m0 = blockIdx.x * 128;
    int wid = tid >> 5, lane = tid & 31;
    int wm0 = (wid & 3) * 32, wn0 = (wid >> 2) * 32;
    int g = lane >> 2, tg = lane & 3;
    const int K2 = Kk >> 1;

    float acc[2][4][4];
#pragma unroll
    for (int mt = 0; mt < 2; mt++)
#pragma unroll
        for (int nt = 0; nt < 4; nt++)
#pragma unroll
            for (int i = 0; i < 4; i++) acc[mt][nt][i] = 0.f;

    uint32_t abase[2];
#pragma unroll
    for (int sb = 0; sb < 2; sb++)
        abase[sb] = (uint32_t)__cvta_generic_to_shared(
            &As[sb][(wm0 + (lane & 15)) * AST2 + (lane >> 4) * 4]);

    uint4 pa[2], pb;
    const int nk = Kk / 32;
    auto loadA = [&](int kt) {
#pragma unroll
        for (int j = 0; j < 2; j++) {
            int idx4 = tid + j * 256;
            int row = idx4 >> 2, qc = (idx4 & 3) << 2;
            pa[j] = *reinterpret_cast<const uint4*>(A2 + (size_t)(m0 + row) * K2 + kt * 16 + qc);
        }
    };
    auto loadB = [&](int kt) {
        int kp = tid >> 4, nc = (tid & 15) << 2;
        pb = *reinterpret_cast<const uint4*>(Wp + (size_t)(kt * 16 + kp) * Nn + n0 + nc);
    };
    auto stage = [&](int sb) {
#pragma unroll
        for (int j = 0; j < 2; j++) {
            int idx4 = tid + j * 256;
            int row = idx4 >> 2, qc = (idx4 & 3) << 2;
            *reinterpret_cast<uint4*>(&As[sb][row * AST2 + qc]) = pa[j];
        }
        int kp = tid >> 4, nc = (tid & 15) << 2;
        *reinterpret_cast<uint4*>(&Bs[sb][kp * BST2 + nc]) = pb;
    };

    loadA(0); loadB(0);
    stage(0);
    __syncthreads();
    for (int kt = 0; kt < nk; kt++) {
        int cur = kt & 1;
        if (kt + 1 < nk) { loadA(kt + 1); loadB(kt + 1); }
        const uint32_t* Bc = Bs[cur];
        uint32_t ab = abase[cur];
#pragma unroll
        for (int ks = 0; ks < 2; ks++) {
            int kk2 = ks * 8;
            uint32_t a[2][4], b[4][2];
#pragma unroll
            for (int mt = 0; mt < 2; mt++)
                ldsm4(a[mt], ab + (uint32_t)((mt * 16 * AST2 + kk2) * 4));
#pragma unroll
            for (int nt = 0; nt < 4; nt++) {
                int col = wn0 + nt * 8 + g;
                b[nt][0] = Bc[(kk2 + tg    ) * BST2 + col];
                b[nt][1] = Bc[(kk2 + tg + 4) * BST2 + col];
            }
#pragma unroll
            for (int mt = 0; mt < 2; mt++)
#pragma unroll
                for (int nt = 0; nt < 4; nt++)
                    mma_bf16(acc[mt][nt], a[mt][0], a[mt][1], a[mt][2], a[mt][3],
                             b[nt][0], b[nt][1]);
        }
        if (kt + 1 < nk) {
            stage(cur ^ 1);
            __syncthreads();
        }
    }
#pragma unroll
    for (int mt = 0; mt < 2; mt++)
#pragma unroll
        for (int nt = 0; nt < 4; nt++) {
            int col = n0 + wn0 + nt * 8 + 2 * tg;
#pragma unroll
            for (int i = 0; i < 4; i++) {
                int row = m0 + wm0 + mt * 16 + g + (i >> 1) * 8;
                int c = col + (i & 1);
                Cc[(size_t)row * Nn + c] = acc[mt][nt][i] + bias[c];
            }
        }
}

// ---------------- Conv as bf16 GEMM, 2-stage pipeline + ldmatrix ---------------
__global__ __launch_bounds__(256) void conv_bf16_kernel(
    const uint32_t* __restrict__ xnb, const uint32_t* __restrict__ cwp,
    const float* __restrict__ cb1, const float* __restrict__ cb2,
    const float* __restrict__ cb3, const float* __restrict__ cb4,
    float* __restrict__ cv)
{
    __shared__ uint32_t As[2][128 * AST2];
    __shared__ uint32_t Bs[2][16 * BST2];
    int tid = threadIdx.x;
    int m0 = blockIdx.x * 128;
    int ct = blockIdx.y;
    int conv = ct / 3;
    int nloc0 = (ct % 3) * 64;
    int bidx = m0 >> 9;
    int t0   = m0 & 511;
    int tap0 = (conv == 0) ? 0 : (conv == 1) ? 1 : (conv == 2) ? 3 : 6;
    const float* bias = (conv == 0) ? cb1 : (conv == 1) ? cb2 : (conv == 2) ? cb3 : cb4;
    int ntaps = conv + 1;
    int dmin  = (conv < 2) ? 1 : 0;

    int wid = tid >> 5, lane = tid & 31;
    int wm0 = (wid & 3) * 32, wn0 = (wid >> 2) * 32;
    int g = lane >> 2, tg = lane & 3;

    float acc[2][4][4];
#pragma unroll
    for (int mt = 0; mt < 2; mt++)
#pragma unroll
        for (int nt = 0; nt < 4; nt++)
#pragma unroll
            for (int i = 0; i < 4; i++) acc[mt][nt][i] = 0.f;

    uint32_t abase[2];
#pragma unroll
    for (int sb = 0; sb < 2; sb++)
        abase[sb] = (uint32_t)__cvta_generic_to_shared(
            &As[sb][(wm0 + (lane & 15)) * AST2 + (lane >> 4) * 4]);

    const int nk = DN / 32;
    int total = ntaps * nk;
    const int K2 = DN / 2;

    uint4 pa[2], pb;
    auto loadA = [&](int it) {
        int ti = it / nk, kt = it - ti * nk;
        int shift = dmin + ti - 1;
#pragma unroll
        for (int j = 0; j < 2; j++) {
            int idx4 = tid + j * 256;
            int row = idx4 >> 2, qc = (idx4 & 3) << 2;
            int tsrc = t0 + row + shift;
            if (tsrc >= 0 && tsrc < TN)
                pa[j] = *reinterpret_cast<const uint4*>(
                    xnb + (size_t)((bidx << 9) + tsrc) * K2 + kt * 16 + qc);
            else
                pa[j] = make_uint4(0u, 0u, 0u, 0u);
        }
    };
    auto loadB = [&](int it) {
        int ti = it / nk, kt = it - ti * nk;
        int kp = tid >> 4, nc = (tid & 15) << 2;
        pb = *reinterpret_cast<const uint4*>(
            cwp + ((size_t)(tap0 + ti) * 768 + kt * 16 + kp) * C1 + nloc0 + nc);
    };
    auto stage = [&](int sb) {
#pragma unroll
        for (int j = 0; j < 2; j++) {
            int idx4 = tid + j * 256;
            int row = idx4 >> 2, qc = (idx4 & 3) << 2;
            *reinterpret_cast<uint4*>(&As[sb][row * AST2 + qc]) = pa[j];
        }
        int kp = tid >> 4, nc = (tid & 15) << 2;
        *reinterpret_cast<uint4*>(&Bs[sb][kp * BST2 + nc]) = pb;
    };

    loadA(0); loadB(0);
    stage(0);
    __syncthreads();
    for (int it = 0; it < total; it++) {
        int cur = it & 1;
        if (it + 1 < total) { loadA(it + 1); loadB(it + 1); }
        const uint32_t* Bc = Bs[cur];
        uint32_t ab = abase[cur];
#pragma unroll
        for (int ks = 0; ks < 2; ks++) {
            int kk2 = ks * 8;
            uint32_t a[2][4], b[4][2];
#pragma unroll
            for (int mt = 0; mt < 2; mt++)
                ldsm4(a[mt], ab + (uint32_t)((mt * 16 * AST2 + kk2) * 4));
#pragma unroll
            for (int nt = 0; nt < 4; nt++) {
                int col = wn0 + nt * 8 + g;
                b[nt][0] = Bc[(kk2 + tg    ) * BST2 + col];
                b[nt][1] = Bc[(kk2 + tg + 4) * BST2 + col];
            }
#pragma unroll
            for (int mt = 0; mt < 2; mt++)
#pragma unroll
                for (int nt = 0; nt < 4; nt++)
                    mma_bf16(acc[mt][nt], a[mt][0], a[mt][1], a[mt][2], a[mt][3],
                             b[nt][0], b[nt][1]);
        }
        if (it + 1 < total) {
            stage(cur ^ 1);
            __syncthreads();
        }
    }
#pragma unroll
    for (int mt = 0; mt < 2; mt++)
#pragma unroll
        for (int nt = 0; nt < 4; nt++) {
            int cl = wn0 + nt * 8 + 2 * tg;
#pragma unroll
            for (int i = 0; i < 4; i++) {
                int row = m0 + wm0 + mt * 16 + g + (i >> 1) * 8;
                int c   = cl + (i & 1);
                float v = acc[mt][nt][i] + bias[nloc0 + c];
                cv[(size_t)row * C4T + conv * C1 + nloc0 + c] = fmaxf(v, 0.f);
            }
        }
}

// ---------------- TF32 GEMM (logits) --------------------------------------------
__global__ __launch_bounds__(256) void gemm_tf32_kernel(
    const float* __restrict__ A, const float* __restrict__ W,
    const float* __restrict__ bias, float* __restrict__ Cc,
    int M, int Nn, int Kk)
{
    __shared__ uint32_t As[128 * AST];
    __shared__ uint32_t Bs[32 * BST];
    int tid = threadIdx.x;
    int m0 = blockIdx.x * 128, n0 = blockIdx.y * 64;
    int wid = tid >> 5, lane = tid & 31;
    int wm0 = (wid & 3) * 32, wn0 = (wid >> 2) * 32;
    int g = lane >> 2, tg = lane & 3;
    float acc[2][4][4];
#pragma unroll
    for (int mt = 0; mt < 2; mt++)
#pragma unroll
        for (int nt = 0; nt < 4; nt++)
#pragma unroll
            for (int i = 0; i < 4; i++) acc[mt][nt][i] = 0.f;
    float4 pa[4], pb[2];
    int nk = Kk / 32;
    auto loadA = [&](int kt) {
#pragma unroll
        for (int j = 0; j < 4; j++) {
            int idx4 = tid + j * 256;
            int row = idx4 >> 3, kc = (idx4 & 7) << 2;
            pa[j] = *reinterpret_cast<const float4*>(A + (size_t)(m0 + row) * Kk + kt * 32 + kc);
        }
    };
    auto loadB = [&](int kt) {
#pragma unroll
        for (int j = 0; j < 2; j++) {
            int idx4 = tid + j * 256;
            int row = idx4 >> 4, nc = (idx4 & 15) << 2;
            int ncol = n0 + nc;
            const float* Wr = W + (size_t)(kt * 32 + row) * Nn;
            float4 v;
            if (ncol + 3 < Nn) v = *reinterpret_cast<const float4*>(Wr + ncol);
            else {
                v.x = (ncol + 0 < Nn) ? Wr[ncol + 0] : 0.f;
                v.y = (ncol + 1 < Nn) ? Wr[ncol + 1] : 0.f;
                v.z = (ncol + 2 < Nn) ? Wr[ncol + 2] : 0.f;
                v.w = (ncol + 3 < Nn) ? Wr[ncol + 3] : 0.f;
            }
            pb[j] = v;
        }
    };
    auto stage = [&]() {
#pragma unroll
        for (int j = 0; j < 4; j++) {
            int idx4 = tid + j * 256;
            int row = idx4 >> 3, kc = (idx4 & 7) << 2;
            As[row * AST + kc + 0] = f2tf32(pa[j].x);
            As[row * AST + kc + 1] = f2tf32(pa[j].y);
            As[row * AST + kc + 2] = f2tf32(pa[j].z);
            As[row * AST + kc + 3] = f2tf32(pa[j].w);
        }
#pragma unroll
        for (int j = 0; j < 2; j++) {
            int idx4 = tid + j * 256;
            int row = idx4 >> 4, nc = (idx4 & 15) << 2;
            Bs[row * BST + nc + 0] = f2tf32(pb[j].x);
            Bs[row * BST + nc + 1] = f2tf32(pb[j].y);
            Bs[row * BST + nc + 2] = f2tf32(pb[j].z);
            Bs[row * BST + nc + 3] = f2tf32(pb[j].w);
        }
    };
    loadA(0); loadB(0);
    for (int kt = 0; kt < nk; kt++) {
        __syncthreads();
        stage();
        __syncthreads();
        if (kt + 1 < nk) { loadA(kt + 1); loadB(kt + 1); }
#pragma unroll
        for (int ks = 0; ks < 4; ks++) {
            int kk = ks * 8;
            uint32_t a[2][4], b[4][2];
#pragma unroll
            for (int mt = 0; mt < 2; mt++) {
                int r0 = wm0 + mt * 16 + g;
                a[mt][0] = As[(r0    ) * AST + kk + tg];
                a[mt][1] = As[(r0 + 8) * AST + kk + tg];
                a[mt][2] = As[(r0    ) * AST + kk + tg + 4];
                a[mt][3] = As[(r0 + 8) * AST + kk + tg + 4];
            }
#pragma unroll
            for (int nt = 0; nt < 4; nt++) {
                int col = wn0 + nt * 8 + g;
                b[nt][0] = Bs[(kk + tg    ) * BST + col];
                b[nt][1] = Bs[(kk + tg + 4) * BST + col];
            }
#pragma unroll
            for (int mt = 0; mt < 2; mt++)
#pragma unroll
                for (int nt = 0; nt < 4; nt++)
                    mma_tf32(acc[mt][nt], a[mt][0], a[mt][1], a[mt][2], a[mt][3],
                             b[nt][0], b[nt][1]);
        }
    }
#pragma unroll
    for (int mt = 0; mt < 2; mt++)
#pragma unroll
        for (int nt = 0; nt < 4; nt++) {
            int col = n0 + wn0 + nt * 8 + 2 * tg;
#pragma unroll
            for (int i = 0; i < 4; i++) {
                int row = m0 + wm0 + mt * 16 + g + (i >> 1) * 8;
                int c = col + (i & 1);
                if (c < Nn) Cc[(size_t)row * Nn + c] = acc[mt][nt][i] + bias[c];
            }
        }
}

// ---------------- LSTM: 4-CTA cluster, tensor-core z-phase ----------------------
#define LSW   (256 * 132 * 4)
#define LSH2  (2 * 128 * 8 * 4)
#define LSZ   (256 * 5 * 4)
#define LS_TOTAL (LSW + LSH2 + LSZ)

__global__ void __cluster_dims__(4, 1, 1) __launch_bounds__(256)
lstm_cluster_kernel(
    const float* __restrict__ gxf, const float* __restrict__ gxb,
    const float* __restrict__ wh_f, const float* __restrict__ wh_b,
    const int* __restrict__ amask, float* __restrict__ hout)
{
    extern __shared__ char sm_[];
    uint32_t* whs2 = (uint32_t*)sm_;
    uint32_t* h2   = (uint32_t*)(sm_ + LSW);
    float*    zbuf = (float*)(sm_ + LSW + LSH2);

    int tid = threadIdx.x;
    uint32_t rank;
    asm("mov.u32 %0, %%cluster_ctarank;" : "=r"(rank));
    int grp = blockIdx.x >> 2;
    int dir = grp >> 4;
    int b0  = (grp & 15) * 4;
    const float* __restrict__ Wh = dir ? wh_b : wh_f;
    const float* __restrict__ gx = dir ? gxb : gxf;

    for (int i = tid; i < 256 * 128; i += 256) {
        int lcol = i >> 7, kp = i & 127;
        int gcol = ((lcol >> 6) << 8) + (int)rank * 64 + (lcol & 63);
        whs2[lcol * 132 + kp] = packbf(Wh[(2 * kp) * G4 + gcol],
                                       Wh[(2 * kp + 1) * G4 + gcol]);
    }
    for (int i = tid; i < 2048; i += 256) h2[i] = 0u;

    int lane = tid & 31, wrp = tid >> 5;
    int g = lane >> 2, tg = lane & 3;
    int pb = tid >> 6, pj = tid & 63;
    int bb = b0 + pb;
    float h_r = 0.f, c_r = 0.f, op_r = 0.f;

    uint32_t ha[2][4];
    {
        int k = (int)rank * 64 + pj;
        uint32_t loc;
        const void* p = (const void*)((const char*)h2 + ((k >> 1) * 8 + pb) * 4 + (k & 1) * 2);
        asm("{ .reg .u64 t; cvta.to.shared.u64 t, %1; cvt.u32.u64 %0, t; }"
            : "=r"(loc) : "l"(p));
#pragma unroll
        for (int bf = 0; bf < 2; bf++) {
            uint32_t off = loc + bf * 4096;
#pragma unroll
            for (int r = 0; r < 4; r++)
                asm("mapa.shared::cluster.u32 %0, %1, %2;"
                    : "=r"(ha[bf][r]) : "r"(off), "r"(r));
        }
    }

    asm volatile("barrier.cluster.arrive.aligned;" ::: "memory");
    asm volatile("barrier.cluster.wait.aligned;"   ::: "memory");

    int buf = 0;
    for (int s = 0; s < TN; s++) {
        int t = dir ? (TN - 1 - s) : s;
        size_t gb = ((size_t)(bb * TN + t)) * G4 + (size_t)rank * 64 + pj;
        float gx0 = gx[gb], gx1 = gx[gb + 256], gx2 = gx[gb + 512], gx3 = gx[gb + 768];
        int mv = amask[bb * TN + t];

        const uint32_t* h2c = h2 + buf * 1024;
        float d0[4] = {0.f, 0.f, 0.f, 0.f}, d1[4] = {0.f, 0.f, 0.f, 0.f};
        int r0 = wrp * 32 + g;
#pragma unroll
        for (int kt = 0; kt < 16; kt++) {
            int kk2 = kt * 8;
            uint32_t bq0 = h2c[(kk2 + tg) * 8 + g];
            uint32_t bq1 = h2c[(kk2 + tg + 4) * 8 + g];
            uint32_t a0 = whs2[(r0     ) * 132 + kk2 + tg];
            uint32_t a1 = whs2[(r0 +  8) * 132 + kk2 + tg];
            uint32_t a2 = whs2[(r0     ) * 132 + kk2 + tg + 4];
            uint32_t a3 = whs2[(r0 +  8) * 132 + kk2 + tg + 4];
            mma_bf16(d0, a0, a1, a2, a3, bq0, bq1);
            a0 = whs2[(r0 + 16) * 132 + kk2 + tg];
            a1 = whs2[(r0 + 24) * 132 + kk2 + tg];
            a2 = whs2[(r0 + 16) * 132 + kk2 + tg + 4];
            a3 = whs2[(r0 + 24) * 132 + kk2 + tg + 4];
            mma_bf16(d1, a0, a1, a2, a3, bq0, bq1);
        }
        if (tg < 2) {
#pragma unroll
            for (int i = 0; i < 4; i++) {
                int col = 2 * tg + (i & 1);
                zbuf[(r0 + (i >> 1) * 8     ) * 5 + col] = d0[i];
                zbuf[(r0 + (i >> 1) * 8 + 16) * 5 + col] = d1[i];
            }
        }
        __syncthreads();

        {
            float zi = zbuf[(      pj) * 5 + pb] + gx0;
            float zf = zbuf[( 64 + pj) * 5 + pb] + gx1;
            float zg = zbuf[(128 + pj) * 5 + pb] + gx2;
            float zo = zbuf[(192 + pj) * 5 + pb] + gx3;
            float ii = 1.f / (1.f + expf(-zi));
            float ff = 1.f / (1.f + expf(-zf));
            float gg = tanhf(zg);
            float oo = 1.f / (1.f + expf(-zo));
            float cn = ff * c_r + ii * gg;
            float hn = oo * tanhf(cn);
            bool m = mv != 0;
            float hq = m ? hn : h_r;
            c_r  = m ? cn : c_r;
            op_r = m ? hn : op_r;
            h_r  = hq;
            hout[((size_t)(bb * TN + t)) * (2 * HN) + dir * HN + (int)rank * 64 + pj] = op_r;
            uint16_t hb16;
            asm("cvt.rn.bf16.f32 %0, %1;" : "=h"(hb16) : "f"(hq));
            int nb = buf ^ 1;
#pragma unroll
            for (int r = 0; r < 4; r++)
                asm volatile("st.shared::cluster.b16 [%0], %1;"
                             :: "r"(ha[nb][r]), "h"(hb16) : "memory");
        }
        asm volatile("barrier.cluster.arrive.aligned;" ::: "memory");
        asm volatile("barrier.cluster.wait.aligned;"   ::: "memory");
        buf ^= 1;
    }
}

// ---------------- CRF ------------------------------------------------------------
__global__ __launch_bounds__(32) void crf_kernel(
    const int* __restrict__ inputs, const int* __restrict__ targets,
    const float* __restrict__ trans, const float* __restrict__ logits,
    float* __restrict__ out)
{
    int b = blockIdx.x;
    int lane = threadIdx.x;
    __shared__ float tr[LBL * LBL];
    __shared__ float alpha[LBL];
    for (int i = lane; i < LBL * LBL; i += 32) tr[i] = trans[i];
    int cnt = 0;
    for (int t = lane; t < TN; t += 32) cnt += (inputs[b * TN + t] != 0);
#pragma unroll
    for (int o = 16; o; o >>= 1) cnt += __shfl_xor_sync(0xffffffffu, cnt, o);
    int seqlen = cnt;
    const float* lg = logits + (size_t)b * TN * LBL;
    const int*   tg = targets + b * TN;
    float us = 0.f, bs = 0.f;
    for (int t = lane; t < TN; t += 32) {
        if (t < seqlen) us += lg[t * LBL + tg[t]];
        if (t >= 1 && t < seqlen) bs += tr[tg[t - 1] * LBL + tg[t]];
    }
#pragma unroll
    for (int o = 16; o; o >>= 1) {
        us += __shfl_xor_sync(0xffffffffu, us, o);
        bs += __shfl_xor_sync(0xffffffffu, bs, o);
    }
    __syncwarp();
    if (lane < LBL) alpha[lane] = lg[lane];
    __syncwarp();
    for (int t = 1; t < TN; t++) {
        float newv = 0.f;
        if (lane < LBL) {
            float m = -1e30f;
#pragma unroll
            for (int i = 0; i < LBL; i++) m = fmaxf(m, alpha[i] + tr[i * LBL + lane]);
            float ss = 0.f;
#pragma unroll
            for (int i = 0; i < LBL; i++) ss += expf(alpha[i] + tr[i * LBL + lane] - m);
            newv = m + logf(ss) + lg[t * LBL + lane];
        }
        __syncwarp();
        if (lane < LBL && t < seqlen) alpha[lane] = newv;
        __syncwarp();
    }
    float a = (lane < LBL) ? alpha[lane] : -1e30f;
    float mx = a;
#pragma unroll
    for (int o = 16; o; o >>= 1) mx = fmaxf(mx, __shfl_xor_sync(0xffffffffu, mx, o));
    float e = (lane < LBL) ? expf(a - mx) : 0.f;
#pragma unroll
    for (int o = 16; o; o >>= 1) e += __shfl_xor_sync(0xffffffffu, e, o);
    float lognorm = mx + logf(e);
    if (lane == 0) out[b] = us + bs - lognorm;
}

// ---------------- launch -----------------------------------------------------------
extern "C" void kernel_launch(void* const* d_in, const int* in_sizes, int n_in,
                              void* d_out, int out_size)
{
    const int*   inputs = (const int*)  d_in[0];
    const int*   amask  = (const int*)  d_in[1];
    const int*   targets= (const int*)  d_in[2];
    const float* hid_a  = (const float*)d_in[3];
    const float* hid_b  = (const float*)d_in[4];
    const float* ln1_g  = (const float*)d_in[5];
    const float* ln1_b  = (const float*)d_in[6];
    const float* w1 = (const float*)d_in[7];
    const float* b1 = (const float*)d_in[8];
    const float* w2 = (const float*)d_in[9];
    const float* b2 = (const float*)d_in[10];
    const float* w3 = (const float*)d_in[11];
    const float* b3 = (const float*)d_in[12];
    const float* w4 = (const float*)d_in[13];
    const float* b4 = (const float*)d_in[14];
    const float* ln2_g = (const float*)d_in[15];
    const float* ln2_b = (const float*)d_in[16];
    const float* wx_f  = (const float*)d_in[17];
    const float* wh_f  = (const float*)d_in[18];
    const float* bf    = (const float*)d_in[19];
    const float* wx_b  = (const float*)d_in[20];
    const float* wh_b  = (const float*)d_in[21];
    const float* bb    = (const float*)d_in[22];
    const float* wd    = (const float*)d_in[23];
    const float* bd    = (const float*)d_in[24];
    const float* trans = (const float*)d_in[25];

    uint32_t *xnb, *cob, *wxpf, *wxpb, *cwp;
    float *cv, *gxf, *gxb, *hh, *lg;
    cudaGetSymbolAddress((void**)&xnb,  g_xnb);
    cudaGetSymbolAddress((void**)&cv,   g_cv);
    cudaGetSymbolAddress((void**)&cob,  g_cob);
    cudaGetSymbolAddress((void**)&gxf,  g_gxf);
    cudaGetSymbolAddress((void**)&gxb,  g_gxb);
    cudaGetSymbolAddress((void**)&hh,   g_h);
    cudaGetSymbolAddress((void**)&lg,   g_lg);
    cudaGetSymbolAddress((void**)&wxpf, g_wxpf);
    cudaGetSymbolAddress((void**)&wxpb, g_wxpb);
    cudaGetSymbolAddress((void**)&cwp,  g_cwp);

    cudaFuncSetAttribute(lstm_cluster_kernel,
                         cudaFuncAttributeMaxDynamicSharedMemorySize, LS_TOTAL);

    {
        int n1 = (C4T / 2) * G4;
        pack_pairs_kernel<<<(n1 + 255) / 256, 256>>>(wx_f, wxpf, C4T / 2, G4);
        pack_pairs_kernel<<<(n1 + 255) / 256, 256>>>(wx_b, wxpb, C4T / 2, G4);
        int nc1 = 1 * (DN / 2) * C1, nc2 = 2 * (DN / 2) * C1;
        int nc3 = 3 * (DN / 2) * C1, nc4 = 4 * (DN / 2) * C1;
        pack_pairs_kernel<<<(nc1 + 255) / 256, 256>>>(w1, cwp,                        1 * (DN / 2), C1);
        pack_pairs_kernel<<<(nc2 + 255) / 256, 256>>>(w2, cwp + (size_t)1 * 768 * C1, 2 * (DN / 2), C1);
        pack_pairs_kernel<<<(nc3 + 255) / 256, 256>>>(w3, cwp + (size_t)3 * 768 * C1, 3 * (DN / 2), C1);
        pack_pairs_kernel<<<(nc4 + 255) / 256, 256>>>(w4, cwp + (size_t)6 * 768 * C1, 4 * (DN / 2), C1);
    }

    ln1_kernel<<<BT, 256>>>(hid_a, hid_b, ln1_g, ln1_b, xnb);
    conv_bf16_kernel<<<dim3(BT / 128, 12), 256>>>(xnb, cwp, b1, b2, b3, b4, cv);
    ln2_kernel<<<BT, 256>>>(cv, ln2_g, ln2_b, cob);
    gemm_bf16_dual_kernel<<<dim3(BT / 128, 32), 256>>>(
        cob, wxpf, wxpb, bf, bb, gxf, gxb, 16);
    lstm_cluster_kernel<<<128, 256, LS_TOTAL>>>(gxf, gxb, wh_f, wh_b, amask, hh);
    gemm_tf32_kernel<<<dim3(BT / 128, 1), 256>>>(hh, wd, bd, lg, BT, LBL, 2 * HN);
    crf_kernel<<<BN, 32>>>(inputs, targets, trans, lg, (float*)d_out);
}

// round 11
// speedup vs baseline: 3.5334x; 1.0265x over previous
#include <cuda_runtime.h>
#include <math.h>
#include <stdint.h>

#define BN   64
#define TN   512
#define BT   32768
#define DN   1536
#define C1   192
#define C4T  768
#define HN   256
#define G4   1024
#define LBL  20

// ---------------- scratch (static device memory) ------------------------------
__device__ uint32_t g_xnb[ (size_t)BT * DN / 2 ];
__device__ float    g_cv [ (size_t)BT * C4T    ];
__device__ uint32_t g_cob[ (size_t)BT * C4T / 2];
__device__ float    g_gxf[ (size_t)BT * G4     ];
__device__ float    g_gxb[ (size_t)BT * G4     ];
__device__ float    g_h  [ (size_t)BT * 2 * HN ];
__device__ float    g_lg [ (size_t)BT * LBL    ];
__device__ uint32_t g_wxpf[ (C4T / 2) * G4 ];
__device__ uint32_t g_wxpb[ (C4T / 2) * G4 ];
__device__ uint32_t g_cwp [ 10 * (DN / 2) * C1 ];

// ---------------- helpers -----------------------------------------------------
__device__ __forceinline__ uint32_t packbf(float lo, float hi) {
    uint32_t u;
    asm("cvt.rn.bf16x2.f32 %0, %1, %2;" : "=r"(u) : "f"(hi), "f"(lo));
    return u;
}
__device__ __forceinline__ uint32_t f2tf32(float f) {
    uint32_t u;
    asm("cvt.rna.tf32.f32 %0, %1;" : "=r"(u) : "f"(f));
    return u;
}
__device__ __forceinline__ void mma_bf16(float* c, uint32_t a0, uint32_t a1,
                                         uint32_t a2, uint32_t a3,
                                         uint32_t b0, uint32_t b1) {
    asm volatile(
        "mma.sync.aligned.m16n8k16.row.col.f32.bf16.bf16.f32 "
        "{%0,%1,%2,%3}, {%4,%5,%6,%7}, {%8,%9}, {%0,%1,%2,%3};\n"
        : "+f"(c[0]), "+f"(c[1]), "+f"(c[2]), "+f"(c[3])
        : "r"(a0), "r"(a1), "r"(a2), "r"(a3), "r"(b0), "r"(b1));
}
__device__ __forceinline__ void mma_tf32(float* c, uint32_t a0, uint32_t a1,
                                         uint32_t a2, uint32_t a3,
                                         uint32_t b0, uint32_t b1) {
    asm volatile(
        "mma.sync.aligned.m16n8k8.row.col.f32.tf32.tf32.f32 "
        "{%0,%1,%2,%3}, {%4,%5,%6,%7}, {%8,%9}, {%0,%1,%2,%3};\n"
        : "+f"(c[0]), "+f"(c[1]), "+f"(c[2]), "+f"(c[3])
        : "r"(a0), "r"(a1), "r"(a2), "r"(a3), "r"(b0), "r"(b1));
}
__device__ __forceinline__ void ldsm4(uint32_t* a, uint32_t saddr) {
    asm volatile("ldmatrix.sync.aligned.m8n8.x4.shared.b16 {%0,%1,%2,%3}, [%4];"
                 : "=r"(a[0]), "=r"(a[1]), "=r"(a[2]), "=r"(a[3]) : "r"(saddr));
}

#define AST2 20
#define BSTX 136   // xWx B stride (128 cols + 8)   -> (136%32==8) conflict-free
#define BST3 200   // conv B stride (192 cols + 8)  -> (200%32==8) conflict-free
#define AST 36
#define BST 68

// ---------------- merged weight prepack (single launch) -------------------------
__global__ __launch_bounds__(256) void pack_all_kernel(
    const float* __restrict__ wx_f, const float* __restrict__ wx_b,
    const float* __restrict__ w1, const float* __restrict__ w2,
    const float* __restrict__ w3, const float* __restrict__ w4,
    uint32_t* __restrict__ wxpf, uint32_t* __restrict__ wxpb,
    uint32_t* __restrict__ cwp)
{
    int idx = blockIdx.x * 256 + threadIdx.x;
    const int SX = (C4T / 2) * G4;            // 393216 per wx weight
    if (idx < SX) {
        int kp = idx >> 10, n = idx & 1023;
        wxpf[idx] = packbf(wx_f[(size_t)(2 * kp) * G4 + n],
                           wx_f[(size_t)(2 * kp + 1) * G4 + n]);
        return;
    }
    idx -= SX;
    if (idx < SX) {
        int kp = idx >> 10, n = idx & 1023;
        wxpb[idx] = packbf(wx_b[(size_t)(2 * kp) * G4 + n],
                           wx_b[(size_t)(2 * kp + 1) * G4 + n]);
        return;
    }
    idx -= SX;
    const int T1 = (DN / 2) * C1;             // 147456 per tap
    const float* src;
    uint32_t* dst;
    if (idx < 1 * T1)      { src = w1; dst = cwp;          }
    else if (idx < 3 * T1) { src = w2; dst = cwp + 1 * T1; idx -= 1 * T1; }
    else if (idx < 6 * T1) { src = w3; dst = cwp + 3 * T1; idx -= 3 * T1; }
    else if (idx < 10 * T1){ src = w4; dst = cwp + 6 * T1; idx -= 6 * T1; }
    else return;
    int kp = idx / C1, n = idx - kp * C1;
    dst[idx] = packbf(src[(size_t)(2 * kp) * C1 + n],
                      src[(size_t)(2 * kp + 1) * C1 + n]);
}

// ---------------- LayerNorm 1 -> packed bf16 ------------------------------------
__global__ __launch_bounds__(256) void ln1_kernel(
    const float* __restrict__ ha, const float* __restrict__ hb,
    const float* __restrict__ g,  const float* __restrict__ be,
    uint32_t* __restrict__ out2)
{
    int row = blockIdx.x;
    const float* A = ha + (size_t)row * 768;
    const float* B = hb + (size_t)row * 768;
    float s = 0.f, s2 = 0.f;
    for (int d = threadIdx.x; d < DN; d += 256) {
        float v = (d < 768) ? A[d] : B[d - 768];
        s += v; s2 += v * v;
    }
    __shared__ float rs[256], rq[256];
    rs[threadIdx.x] = s; rq[threadIdx.x] = s2;
    __syncthreads();
    for (int off = 128; off > 0; off >>= 1) {
        if (threadIdx.x < off) {
            rs[threadIdx.x] += rs[threadIdx.x + off];
            rq[threadIdx.x] += rq[threadIdx.x + off];
        }
        __syncthreads();
    }
    float mean = rs[0] * (1.f / DN);
    float var  = rq[0] * (1.f / DN) - mean * mean;
    float rstd = rsqrtf(var + 1e-5f);
    uint32_t* O = out2 + (size_t)row * (DN / 2);
    for (int d2 = threadIdx.x; d2 < DN / 2; d2 += 256) {
        int d = d2 << 1;
        float v0 = (d < 768) ? A[d] : B[d - 768];
        float v1 = (d + 1 < 768) ? A[d + 1] : B[d + 1 - 768];
        float o0 = (v0 - mean) * rstd * g[d] + be[d];
        float o1 = (v1 - mean) * rstd * g[d + 1] + be[d + 1];
        O[d2] = packbf(o0, o1);
    }
}

// ---------------- LayerNorm 2 -> packed bf16 ------------------------------------
__global__ __launch_bounds__(256) void ln2_kernel(
    const float* __restrict__ in, const float* __restrict__ g,
    const float* __restrict__ be, uint32_t* __restrict__ out2)
{
    int row = blockIdx.x;
    const float* X = in + (size_t)row * C4T;
    float s = 0.f, s2 = 0.f;
    for (int d = threadIdx.x; d < C4T; d += 256) {
        float v = X[d]; s += v; s2 += v * v;
    }
    __shared__ float rs[256], rq[256];
    rs[threadIdx.x] = s; rq[threadIdx.x] = s2;
    __syncthreads();
    for (int off = 128; off > 0; off >>= 1) {
        if (threadIdx.x < off) {
            rs[threadIdx.x] += rs[threadIdx.x + off];
            rq[threadIdx.x] += rq[threadIdx.x + off];
        }
        __syncthreads();
    }
    float mean = rs[0] * (1.f / C4T);
    float var  = rq[0] * (1.f / C4T) - mean * mean;
    float rstd = rsqrtf(var + 1e-5f);
    uint32_t* O = out2 + (size_t)row * (C4T / 2);
    for (int d2 = threadIdx.x; d2 < C4T / 2; d2 += 256) {
        int d = d2 << 1;
        float o0 = (X[d]     - mean) * rstd * g[d]     + be[d];
        float o1 = (X[d + 1] - mean) * rstd * g[d + 1] + be[d + 1];
        O[d2] = packbf(o0, o1);
    }
}

// ---------------- bf16 dual GEMM: 128x128 tile, 2-stage + ldmatrix --------------
// grid.y in [0,16): half = y/8 selects (Wp,bias,C); n0 = (y%8)*128.
__global__ __launch_bounds__(256) void gemm_bf16_dual_kernel(
    const uint32_t* __restrict__ A2,
    const uint32_t* __restrict__ Wpf, const uint32_t* __restrict__ Wpb,
    const float* __restrict__ biasf, const float* __restrict__ biasb,
    float* __restrict__ Cf, float* __restrict__ Cb)
{
    const int Nn = G4;
    __shared__ uint32_t As[2][128 * AST2];
    __shared__ uint32_t Bs[2][16 * BSTX];
    int tid = threadIdx.x;
    int half = blockIdx.y >> 3;
    int n0 = (blockIdx.y & 7) * 128;
    const uint32_t* Wp   = half ? Wpb : Wpf;
    const float*    bias = half ? biasb : biasf;
    float*          Cc   = half ? Cb : Cf;
    int m0 = blockIdx.x * 128;
    int wid = tid >> 5, lane = tid & 31;
    int wm0 = (wid & 3) * 32, wn0 = (wid >> 2) * 64;
    int g = lane >> 2, tg = lane & 3;
    const int K2 = C4T >> 1;

    float acc[2][8][4];
#pragma unroll
    for (int mt = 0; mt < 2; mt++)
#pragma unroll
        for (int nt = 0; nt < 8; nt++)
#pragma unroll
            for (int i = 0; i < 4; i++) acc[mt][nt][i] = 0.f;

    uint32_t abase[2];
#pragma unroll
    for (int sb = 0; sb < 2; sb++)
        abase[sb] = (uint32_t)__cvta_generic_to_shared(
            &As[sb][(wm0 + (lane & 15)) * AST2 + (lane >> 4) * 4]);

    uint4 pa[2], pb[2];
    const int nk = C4T / 32;   // 24
    auto loadA = [&](int kt) {
#pragma unroll
        for (int j = 0; j < 2; j++) {
            int idx4 = tid + j * 256;
            int row = idx4 >> 2, qc = (idx4 & 3) << 2;
            pa[j] = *reinterpret_cast<const uint4*>(A2 + (size_t)(m0 + row) * K2 + kt * 16 + qc);
        }
    };
    auto loadB = [&](int kt) {
#pragma unroll
        for (int j = 0; j < 2; j++) {
            int idx4 = tid + j * 256;
            int kp = idx4 >> 5, nc = (idx4 & 31) << 2;
            pb[j] = *reinterpret_cast<const uint4*>(Wp + (size_t)(kt * 16 + kp) * Nn + n0 + nc);
        }
    };
    auto stage = [&](int sb) {
#pragma unroll
        for (int j = 0; j < 2; j++) {
            int idx4 = tid + j * 256;
            int row = idx4 >> 2, qc = (idx4 & 3) << 2;
            *reinterpret_cast<uint4*>(&As[sb][row * AST2 + qc]) = pa[j];
        }
#pragma unroll
        for (int j = 0; j < 2; j++) {
            int idx4 = tid + j * 256;
            int kp = idx4 >> 5, nc = (idx4 & 31) << 2;
            *reinterpret_cast<uint4*>(&Bs[sb][kp * BSTX + nc]) = pb[j];
        }
    };

    loadA(0); loadB(0);
    stage(0);
    __syncthreads();
    for (int kt = 0; kt < nk; kt++) {
        int cur = kt & 1;
        if (kt + 1 < nk) { loadA(kt + 1); loadB(kt + 1); }
        const uint32_t* Bc = Bs[cur];
        uint32_t ab = abase[cur];
#pragma unroll
        for (int ks = 0; ks < 2; ks++) {
            int kk2 = ks * 8;
            uint32_t a[2][4], b[8][2];
#pragma unroll
            for (int mt = 0; mt < 2; mt++)
                ldsm4(a[mt], ab + (uint32_t)((mt * 16 * AST2 + kk2) * 4));
#pragma unroll
            for (int nt = 0; nt < 8; nt++) {
                int col = wn0 + nt * 8 + g;
                b[nt][0] = Bc[(kk2 + tg    ) * BSTX + col];
                b[nt][1] = Bc[(kk2 + tg + 4) * BSTX + col];
            }
#pragma unroll
            for (int mt = 0; mt < 2; mt++)
#pragma unroll
                for (int nt = 0; nt < 8; nt++)
                    mma_bf16(acc[mt][nt], a[mt][0], a[mt][1], a[mt][2], a[mt][3],
                             b[nt][0], b[nt][1]);
        }
        if (kt + 1 < nk) {
            stage(cur ^ 1);
            __syncthreads();
        }
    }
#pragma unroll
    for (int mt = 0; mt < 2; mt++)
#pragma unroll
        for (int nt = 0; nt < 8; nt++) {
            int col = n0 + wn0 + nt * 8 + 2 * tg;
#pragma unroll
            for (int i = 0; i < 4; i++) {
                int row = m0 + wm0 + mt * 16 + g + (i >> 1) * 8;
                int c = col + (i & 1);
                Cc[(size_t)row * Nn + c] = acc[mt][nt][i] + bias[c];
            }
        }
}

// ---------------- Conv: 128x192 tile (full conv width), 2-stage + ldmatrix ------
// grid = (BT/128, 4); blockIdx.y = conv index. A read once per tap (was 3x).
__global__ __launch_bounds__(256) void conv_bf16_kernel(
    const uint32_t* __restrict__ xnb, const uint32_t* __restrict__ cwp,
    const float* __restrict__ cb1, const float* __restrict__ cb2,
    const float* __restrict__ cb3, const float* __restrict__ cb4,
    float* __restrict__ cv)
{
    __shared__ uint32_t As[2][128 * AST2];
    __shared__ uint32_t Bs[2][16 * BST3];
    int tid = threadIdx.x;
    int m0 = blockIdx.x * 128;
    int conv = blockIdx.y;
    int bidx = m0 >> 9;
    int t0   = m0 & 511;
    int tap0 = (conv == 0) ? 0 : (conv == 1) ? 1 : (conv == 2) ? 3 : 6;
    const float* bias = (conv == 0) ? cb1 : (conv == 1) ? cb2 : (conv == 2) ? cb3 : cb4;
    int ntaps = conv + 1;
    int dmin  = (conv < 2) ? 1 : 0;

    int wid = tid >> 5, lane = tid & 31;
    int wm0 = (wid & 3) * 32, wn0 = (wid >> 2) * 96;
    int g = lane >> 2, tg = lane & 3;

    float acc[2][12][4];
#pragma unroll
    for (int mt = 0; mt < 2; mt++)
#pragma unroll
        for (int nt = 0; nt < 12; nt++)
#pragma unroll
            for (int i = 0; i < 4; i++) acc[mt][nt][i] = 0.f;

    uint32_t abase[2];
#pragma unroll
    for (int sb = 0; sb < 2; sb++)
        abase[sb] = (uint32_t)__cvta_generic_to_shared(
            &As[sb][(wm0 + (lane & 15)) * AST2 + (lane >> 4) * 4]);

    const int nk = DN / 32;           // 48
    int total = ntaps * nk;
    const int K2 = DN / 2;

    uint4 pa[2], pb[3];
    auto loadA = [&](int it) {
        int ti = it / nk, kt = it - ti * nk;
        int shift = dmin + ti - 1;
#pragma unroll
        for (int j = 0; j < 2; j++) {
            int idx4 = tid + j * 256;
            int row = idx4 >> 2, qc = (idx4 & 3) << 2;
            int tsrc = t0 + row + shift;
            if (tsrc >= 0 && tsrc < TN)
                pa[j] = *reinterpret_cast<const uint4*>(
                    xnb + (size_t)((bidx << 9) + tsrc) * K2 + kt * 16 + qc);
            else
                pa[j] = make_uint4(0u, 0u, 0u, 0u);
        }
    };
    auto loadB = [&](int it) {
        int ti = it / nk, kt = it - ti * nk;
#pragma unroll
        for (int j = 0; j < 3; j++) {
            int idx4 = tid + j * 256;
            int kp = idx4 / 48, nc = (idx4 % 48) << 2;
            pb[j] = *reinterpret_cast<const uint4*>(
                cwp + ((size_t)(tap0 + ti) * 768 + kt * 16 + kp) * C1 + nc);
        }
    };
    auto stage = [&](int sb) {
#pragma unroll
        for (int j = 0; j < 2; j++) {
            int idx4 = tid + j * 256;
            int row = idx4 >> 2, qc = (idx4 & 3) << 2;
            *reinterpret_cast<uint4*>(&As[sb][row * AST2 + qc]) = pa[j];
        }
#pragma unroll
        for (int j = 0; j < 3; j++) {
            int idx4 = tid + j * 256;
            int kp = idx4 / 48, nc = (idx4 % 48) << 2;
            *reinterpret_cast<uint4*>(&Bs[sb][kp * BST3 + nc]) = pb[j];
        }
    };

    loadA(0); loadB(0);
    stage(0);
    __syncthreads();
    for (int it = 0; it < total; it++) {
        int cur = it & 1;
        if (it + 1 < total) { loadA(it + 1); loadB(it + 1); }
        const uint32_t* Bc = Bs[cur];
        uint32_t ab = abase[cur];
#pragma unroll
        for (int ks = 0; ks < 2; ks++) {
            int kk2 = ks * 8;
            uint32_t a[2][4], b[12][2];
#pragma unroll
            for (int mt = 0; mt < 2; mt++)
                ldsm4(a[mt], ab + (uint32_t)((mt * 16 * AST2 + kk2) * 4));
#pragma unroll
            for (int nt = 0; nt < 12; nt++) {
                int col = wn0 + nt * 8 + g;
                b[nt][0] = Bc[(kk2 + tg    ) * BST3 + col];
                b[nt][1] = Bc[(kk2 + tg + 4) * BST3 + col];
            }
#pragma unroll
            for (int mt = 0; mt < 2; mt++)
#pragma unroll
                for (int nt = 0; nt < 12; nt++)
                    mma_bf16(acc[mt][nt], a[mt][0], a[mt][1], a[mt][2], a[mt][3],
                             b[nt][0], b[nt][1]);
        }
        if (it + 1 < total) {
            stage(cur ^ 1);
            __syncthreads();
        }
    }
#pragma unroll
    for (int mt = 0; mt < 2; mt++)
#pragma unroll
        for (int nt = 0; nt < 12; nt++) {
            int cl = wn0 + nt * 8 + 2 * tg;
#pragma unroll
            for (int i = 0; i < 4; i++) {
                int row = m0 + wm0 + mt * 16 + g + (i >> 1) * 8;
                int c   = cl + (i & 1);
                float v = acc[mt][nt][i] + bias[c];
                cv[(size_t)row * C4T + conv * C1 + c] = fmaxf(v, 0.f);
            }
        }
}

// ---------------- TF32 GEMM (logits) --------------------------------------------
__global__ __launch_bounds__(256) void gemm_tf32_kernel(
    const float* __restrict__ A, const float* __restrict__ W,
    const float* __restrict__ bias, float* __restrict__ Cc,
    int M, int Nn, int Kk)
{
    __shared__ uint32_t As[128 * AST];
    __shared__ uint32_t Bs[32 * BST];
    int tid = threadIdx.x;
    int m0 = blockIdx.x * 128, n0 = blockIdx.y * 64;
    int wid = tid >> 5, lane = tid & 31;
    int wm0 = (wid & 3) * 32, wn0 = (wid >> 2) * 32;
    int g = lane >> 2, tg = lane & 3;
    float acc[2][4][4];
#pragma unroll
    for (int mt = 0; mt < 2; mt++)
#pragma unroll
        for (int nt = 0; nt < 4; nt++)
#pragma unroll
            for (int i = 0; i < 4; i++) acc[mt][nt][i] = 0.f;
    float4 pa[4], pb[2];
    int nk = Kk / 32;
    auto loadA = [&](int kt) {
#pragma unroll
        for (int j = 0; j < 4; j++) {
            int idx4 = tid + j * 256;
            int row = idx4 >> 3, kc = (idx4 & 7) << 2;
            pa[j] = *reinterpret_cast<const float4*>(A + (size_t)(m0 + row) * Kk + kt * 32 + kc);
        }
    };
    auto loadB = [&](int kt) {
#pragma unroll
        for (int j = 0; j < 2; j++) {
            int idx4 = tid + j * 256;
            int row = idx4 >> 4, nc = (idx4 & 15) << 2;
            int ncol = n0 + nc;
            const float* Wr = W + (size_t)(kt * 32 + row) * Nn;
            float4 v;
            if (ncol + 3 < Nn) v = *reinterpret_cast<const float4*>(Wr + ncol);
            else {
                v.x = (ncol + 0 < Nn) ? Wr[ncol + 0] : 0.f;
                v.y = (ncol + 1 < Nn) ? Wr[ncol + 1] : 0.f;
                v.z = (ncol + 2 < Nn) ? Wr[ncol + 2] : 0.f;
                v.w = (ncol + 3 < Nn) ? Wr[ncol + 3] : 0.f;
            }
            pb[j] = v;
        }
    };
    auto stage = [&]() {
#pragma unroll
        for (int j = 0; j < 4; j++) {
            int idx4 = tid + j * 256;
            int row = idx4 >> 3, kc = (idx4 & 7) << 2;
            As[row * AST + kc + 0] = f2tf32(pa[j].x);
            As[row * AST + kc + 1] = f2tf32(pa[j].y);
            As[row * AST + kc + 2] = f2tf32(pa[j].z);
            As[row * AST + kc + 3] = f2tf32(pa[j].w);
        }
#pragma unroll
        for (int j = 0; j < 2; j++) {
            int idx4 = tid + j * 256;
            int row = idx4 >> 4, nc = (idx4 & 15) << 2;
            Bs[row * BST + nc + 0] = f2tf32(pb[j].x);
            Bs[row * BST + nc + 1] = f2tf32(pb[j].y);
            Bs[row * BST + nc + 2] = f2tf32(pb[j].z);
            Bs[row * BST + nc + 3] = f2tf32(pb[j].w);
        }
    };
    loadA(0); loadB(0);
    for (int kt = 0; kt < nk; kt++) {
        __syncthreads();
        stage();
        __syncthreads();
        if (kt + 1 < nk) { loadA(kt + 1); loadB(kt + 1); }
#pragma unroll
        for (int ks = 0; ks < 4; ks++) {
            int kk = ks * 8;
            uint32_t a[2][4], b[4][2];
#pragma unroll
            for (int mt = 0; mt < 2; mt++) {
                int r0 = wm0 + mt * 16 + g;
                a[mt][0] = As[(r0    ) * AST + kk + tg];
                a[mt][1] = As[(r0 + 8) * AST + kk + tg];
                a[mt][2] = As[(r0    ) * AST + kk + tg + 4];
                a[mt][3] = As[(r0 + 8) * AST + kk + tg + 4];
            }
#pragma unroll
            for (int nt = 0; nt < 4; nt++) {
                int col = wn0 + nt * 8 + g;
                b[nt][0] = Bs[(kk + tg    ) * BST + col];
                b[nt][1] = Bs[(kk + tg + 4) * BST + col];
            }
#pragma unroll
            for (int mt = 0; mt < 2; mt++)
#pragma unroll
                for (int nt = 0; nt < 4; nt++)
                    mma_tf32(acc[mt][nt], a[mt][0], a[mt][1], a[mt][2], a[mt][3],
                             b[nt][0], b[nt][1]);
        }
    }
#pragma unroll
    for (int mt = 0; mt < 2; mt++)
#pragma unroll
        for (int nt = 0; nt < 4; nt++) {
            int col = n0 + wn0 + nt * 8 + 2 * tg;
#pragma unroll
            for (int i = 0; i < 4; i++) {
                int row = m0 + wm0 + mt * 16 + g + (i >> 1) * 8;
                int c = col + (i & 1);
                if (c < Nn) Cc[(size_t)row * Nn + c] = acc[mt][nt][i] + bias[c];
            }
        }
}

// ---------------- LSTM: 4-CTA cluster, tensor-core z-phase ----------------------
#define LSW   (256 * 132 * 4)
#define LSH2  (2 * 128 * 8 * 4)
#define LSZ   (256 * 5 * 4)
#define LS_TOTAL (LSW + LSH2 + LSZ)

__global__ void __cluster_dims__(4, 1, 1) __launch_bounds__(256)
lstm_cluster_kernel(
    const float* __restrict__ gxf, const float* __restrict__ gxb,
    const float* __restrict__ wh_f, const float* __restrict__ wh_b,
    const int* __restrict__ amask, float* __restrict__ hout)
{
    extern __shared__ char sm_[];
    uint32_t* whs2 = (uint32_t*)sm_;
    uint32_t* h2   = (uint32_t*)(sm_ + LSW);
    float*    zbuf = (float*)(sm_ + LSW + LSH2);

    int tid = threadIdx.x;
    uint32_t rank;
    asm("mov.u32 %0, %%cluster_ctarank;" : "=r"(rank));
    int grp = blockIdx.x >> 2;
    int dir = grp >> 4;
    int b0  = (grp & 15) * 4;
    const float* __restrict__ Wh = dir ? wh_b : wh_f;
    const float* __restrict__ gx = dir ? gxb : gxf;

    for (int i = tid; i < 256 * 128; i += 256) {
        int lcol = i >> 7, kp = i & 127;
        int gcol = ((lcol >> 6) << 8) + (int)rank * 64 + (lcol & 63);
        whs2[lcol * 132 + kp] = packbf(Wh[(2 * kp) * G4 + gcol],
                                       Wh[(2 * kp + 1) * G4 + gcol]);
    }
    for (int i = tid; i < 2048; i += 256) h2[i] = 0u;

    int lane = tid & 31, wrp = tid >> 5;
    int g = lane >> 2, tg = lane & 3;
    int pb = tid >> 6, pj = tid & 63;
    int bb = b0 + pb;
    float h_r = 0.f, c_r = 0.f, op_r = 0.f;

    uint32_t ha[2][4];
    {
        int k = (int)rank * 64 + pj;
        uint32_t loc;
        const void* p = (const void*)((const char*)h2 + ((k >> 1) * 8 + pb) * 4 + (k & 1) * 2);
        asm("{ .reg .u64 t; cvta.to.shared.u64 t, %1; cvt.u32.u64 %0, t; }"
            : "=r"(loc) : "l"(p));
#pragma unroll
        for (int bf = 0; bf < 2; bf++) {
            uint32_t off = loc + bf * 4096;
#pragma unroll
            for (int r = 0; r < 4; r++)
                asm("mapa.shared::cluster.u32 %0, %1, %2;"
                    : "=r"(ha[bf][r]) : "r"(off), "r"(r));
        }
    }

    asm volatile("barrier.cluster.arrive.aligned;" ::: "memory");
    asm volatile("barrier.cluster.wait.aligned;"   ::: "memory");

    int buf = 0;
    for (int s = 0; s < TN; s++) {
        int t = dir ? (TN - 1 - s) : s;
        size_t gb = ((size_t)(bb * TN + t)) * G4 + (size_t)rank * 64 + pj;
        float gx0 = gx[gb], gx1 = gx[gb + 256], gx2 = gx[gb + 512], gx3 = gx[gb + 768];
        int mv = amask[bb * TN + t];

        const uint32_t* h2c = h2 + buf * 1024;
        float d0[4] = {0.f, 0.f, 0.f, 0.f}, d1[4] = {0.f, 0.f, 0.f, 0.f};
        int r0 = wrp * 32 + g;
#pragma unroll
        for (int kt = 0; kt < 16; kt++) {
            int kk2 = kt * 8;
            uint32_t bq0 = h2c[(kk2 + tg) * 8 + g];
            uint32_t bq1 = h2c[(kk2 + tg + 4) * 8 + g];
            uint32_t a0 = whs2[(r0     ) * 132 + kk2 + tg];
            uint32_t a1 = whs2[(r0 +  8) * 132 + kk2 + tg];
            uint32_t a2 = whs2[(r0     ) * 132 + kk2 + tg + 4];
            uint32_t a3 = whs2[(r0 +  8) * 132 + kk2 + tg + 4];
            mma_bf16(d0, a0, a1, a2, a3, bq0, bq1);
            a0 = whs2[(r0 + 16) * 132 + kk2 + tg];
            a1 = whs2[(r0 + 24) * 132 + kk2 + tg];
            a2 = whs2[(r0 + 16) * 132 + kk2 + tg + 4];
            a3 = whs2[(r0 + 24) * 132 + kk2 + tg + 4];
            mma_bf16(d1, a0, a1, a2, a3, bq0, bq1);
        }
        if (tg < 2) {
#pragma unroll
            for (int i = 0; i < 4; i++) {
                int col = 2 * tg + (i & 1);
                zbuf[(r0 + (i >> 1) * 8     ) * 5 + col] = d0[i];
                zbuf[(r0 + (i >> 1) * 8 + 16) * 5 + col] = d1[i];
            }
        }
        __syncthreads();

        {
            float zi = zbuf[(      pj) * 5 + pb] + gx0;
            float zf = zbuf[( 64 + pj) * 5 + pb] + gx1;
            float zg = zbuf[(128 + pj) * 5 + pb] + gx2;
            float zo = zbuf[(192 + pj) * 5 + pb] + gx3;
            float ii = 1.f / (1.f + expf(-zi));
            float ff = 1.f / (1.f + expf(-zf));
            float gg = tanhf(zg);
            float oo = 1.f / (1.f + expf(-zo));
            float cn = ff * c_r + ii * gg;
            float hn = oo * tanhf(cn);
            bool m = mv != 0;
            float hq = m ? hn : h_r;
            c_r  = m ? cn : c_r;
            op_r = m ? hn : op_r;
            h_r  = hq;
            hout[((size_t)(bb * TN + t)) * (2 * HN) + dir * HN + (int)rank * 64 + pj] = op_r;
            uint16_t hb16;
            asm("cvt.rn.bf16.f32 %0, %1;" : "=h"(hb16) : "f"(hq));
            int nb = buf ^ 1;
#pragma unroll
            for (int r = 0; r < 4; r++)
                asm volatile("st.shared::cluster.b16 [%0], %1;"
                             :: "r"(ha[nb][r]), "h"(hb16) : "memory");
        }
        asm volatile("barrier.cluster.arrive.aligned;" ::: "memory");
        asm volatile("barrier.cluster.wait.aligned;"   ::: "memory");
        buf ^= 1;
    }
}

// ---------------- CRF ------------------------------------------------------------
__global__ __launch_bounds__(32) void crf_kernel(
    const int* __restrict__ inputs, const int* __restrict__ targets,
    const float* __restrict__ trans, const float* __restrict__ logits,
    float* __restrict__ out)
{
    int b = blockIdx.x;
    int lane = threadIdx.x;
    __shared__ float tr[LBL * LBL];
    __shared__ float alpha[LBL];
    for (int i = lane; i < LBL * LBL; i += 32) tr[i] = trans[i];
    int cnt = 0;
    for (int t = lane; t < TN; t += 32) cnt += (inputs[b * TN + t] != 0);
#pragma unroll
    for (int o = 16; o; o >>= 1) cnt += __shfl_xor_sync(0xffffffffu, cnt, o);
    int seqlen = cnt;
    const float* lg = logits + (size_t)b * TN * LBL;
    const int*   tg = targets + b * TN;
    float us = 0.f, bs = 0.f;
    for (int t = lane; t < TN; t += 32) {
        if (t < seqlen) us += lg[t * LBL + tg[t]];
        if (t >= 1 && t < seqlen) bs += tr[tg[t - 1] * LBL + tg[t]];
    }
#pragma unroll
    for (int o = 16; o; o >>= 1) {
        us += __shfl_xor_sync(0xffffffffu, us, o);
        bs += __shfl_xor_sync(0xffffffffu, bs, o);
    }
    __syncwarp();
    if (lane < LBL) alpha[lane] = lg[lane];
    __syncwarp();
    for (int t = 1; t < TN; t++) {
        float newv = 0.f;
        if (lane < LBL) {
            float m = -1e30f;
#pragma unroll
            for (int i = 0; i < LBL; i++) m = fmaxf(m, alpha[i] + tr[i * LBL + lane]);
            float ss = 0.f;
#pragma unroll
            for (int i = 0; i < LBL; i++) ss += expf(alpha[i] + tr[i * LBL + lane] - m);
            newv = m + logf(ss) + lg[t * LBL + lane];
        }
        __syncwarp();
        if (lane < LBL && t < seqlen) alpha[lane] = newv;
        __syncwarp();
    }
    float a = (lane < LBL) ? alpha[lane] : -1e30f;
    float mx = a;
#pragma unroll
    for (int o = 16; o; o >>= 1) mx = fmaxf(mx, __shfl_xor_sync(0xffffffffu, mx, o));
    float e = (lane < LBL) ? expf(a - mx) : 0.f;
#pragma unroll
    for (int o = 16; o; o >>= 1) e += __shfl_xor_sync(0xffffffffu, e, o);
    float lognorm = mx + logf(e);
    if (lane == 0) out[b] = us + bs - lognorm;
}

// ---------------- launch -----------------------------------------------------------
extern "C" void kernel_launch(void* const* d_in, const int* in_sizes, int n_in,
                              void* d_out, int out_size)
{
    const int*   inputs = (const int*)  d_in[0];
    const int*   amask  = (const int*)  d_in[1];
    const int*   targets= (const int*)  d_in[2];
    const float* hid_a  = (const float*)d_in[3];
    const float* hid_b  = (const float*)d_in[4];
    const float* ln1_g  = (const float*)d_in[5];
    const float* ln1_b  = (const float*)d_in[6];
    const float* w1 = (const float*)d_in[7];
    const float* b1 = (const float*)d_in[8];
    const float* w2 = (const float*)d_in[9];
    const float* b2 = (const float*)d_in[10];
    const float* w3 = (const float*)d_in[11];
    const float* b3 = (const float*)d_in[12];
    const float* w4 = (const float*)d_in[13];
    const float* b4 = (const float*)d_in[14];
    const float* ln2_g = (const float*)d_in[15];
    const float* ln2_b = (const float*)d_in[16];
    const float* wx_f  = (const float*)d_in[17];
    const float* wh_f  = (const float*)d_in[18];
    const float* bf    = (const float*)d_in[19];
    const float* wx_b  = (const float*)d_in[20];
    const float* wh_b  = (const float*)d_in[21];
    const float* bb    = (const float*)d_in[22];
    const float* wd    = (const float*)d_in[23];
    const float* bd    = (const float*)d_in[24];
    const float* trans = (const float*)d_in[25];

    uint32_t *xnb, *cob, *wxpf, *wxpb, *cwp;
    float *cv, *gxf, *gxb, *hh, *lg;
    cudaGetSymbolAddress((void**)&xnb,  g_xnb);
    cudaGetSymbolAddress((void**)&cv,   g_cv);
    cudaGetSymbolAddress((void**)&cob,  g_cob);
    cudaGetSymbolAddress((void**)&gxf,  g_gxf);
    cudaGetSymbolAddress((void**)&gxb,  g_gxb);
    cudaGetSymbolAddress((void**)&hh,   g_h);
    cudaGetSymbolAddress((void**)&lg,   g_lg);
    cudaGetSymbolAddress((void**)&wxpf, g_wxpf);
    cudaGetSymbolAddress((void**)&wxpb, g_wxpb);
    cudaGetSymbolAddress((void**)&cwp,  g_cwp);

    cudaFuncSetAttribute(lstm_cluster_kernel,
                         cudaFuncAttributeMaxDynamicSharedMemorySize, LS_TOTAL);

    // single merged pack launch (2,260,992 elements)
    {
        int ntot = 2 * ((C4T / 2) * G4) + 10 * (DN / 2) * C1;
        pack_all_kernel<<<(ntot + 255) / 256, 256>>>(
            wx_f, wx_b, w1, w2, w3, w4, wxpf, wxpb, cwp);
    }

    ln1_kernel<<<BT, 256>>>(hid_a, hid_b, ln1_g, ln1_b, xnb);
    conv_bf16_kernel<<<dim3(BT / 128, 4), 256>>>(xnb, cwp, b1, b2, b3, b4, cv);
    ln2_kernel<<<BT, 256>>>(cv, ln2_g, ln2_b, cob);
    gemm_bf16_dual_kernel<<<dim3(BT / 128, 16), 256>>>(
        cob, wxpf, wxpb, bf, bb, gxf, gxb);
    lstm_cluster_kernel<<<128, 256, LS_TOTAL>>>(gxf, gxb, wh_f, wh_b, amask, hh);
    gemm_tf32_kernel<<<dim3(BT / 128, 1), 256>>>(hh, wd, bd, lg, BT, LBL, 2 * HN);
    crf_kernel<<<BN, 32>>>(inputs, targets, trans, lg, (float*)d_out);
}

// round 13
// speedup vs baseline: 3.6236x; 1.0255x over previous
#include <cuda_runtime.h>
#include <math.h>
#include <stdint.h>

#define BN   64
#define TN   512
#define BT   32768
#define DN   1536
#define C1   192
#define C4T  768
#define HN   256
#define G4   1024
#define LBL  20

// ---------------- scratch (static device memory) ------------------------------
__device__ uint32_t g_xnq [ (size_t)BT * DN / 4 ];    // LN1 out, fp8 k-quads
__device__ float    g_cv  [ (size_t)BT * C4T    ];
__device__ uint32_t g_coq [ (size_t)BT * C4T / 4];    // LN2 out, fp8 k-quads
__device__ float    g_gxf [ (size_t)BT * G4     ];
__device__ float    g_gxb [ (size_t)BT * G4     ];
__device__ float    g_h   [ (size_t)BT * 2 * HN ];
__device__ float    g_lg  [ (size_t)BT * LBL    ];
__device__ uint32_t g_wxqf[ (C4T / 4) * G4 ];         // fp8 quads [kq][N]
__device__ uint32_t g_wxqb[ (C4T / 4) * G4 ];
__device__ uint32_t g_cwq [ 10 * (DN / 4) * C1 ];     // fp8 quads per tap

// ---------------- helpers -----------------------------------------------------
__device__ __forceinline__ uint32_t packbf(float lo, float hi) {
    uint32_t u;
    asm("cvt.rn.bf16x2.f32 %0, %1, %2;" : "=r"(u) : "f"(hi), "f"(lo));
    return u;
}
__device__ __forceinline__ uint32_t pack4e4m3(float e0, float e1, float e2, float e3) {
    uint16_t lo, hi;
    asm("cvt.rn.satfinite.e4m3x2.f32 %0, %1, %2;" : "=h"(lo) : "f"(e1), "f"(e0));
    asm("cvt.rn.satfinite.e4m3x2.f32 %0, %1, %2;" : "=h"(hi) : "f"(e3), "f"(e2));
    return (uint32_t)lo | ((uint32_t)hi << 16);
}
__device__ __forceinline__ uint32_t f2tf32(float f) {
    uint32_t u;
    asm("cvt.rna.tf32.f32 %0, %1;" : "=r"(u) : "f"(f));
    return u;
}
__device__ __forceinline__ void mma_fp8(float* c, uint32_t a0, uint32_t a1,
                                        uint32_t a2, uint32_t a3,
                                        uint32_t b0, uint32_t b1) {
    asm volatile(
        "mma.sync.aligned.m16n8k32.row.col.f32.e4m3.e4m3.f32 "
        "{%0,%1,%2,%3}, {%4,%5,%6,%7}, {%8,%9}, {%0,%1,%2,%3};\n"
        : "+f"(c[0]), "+f"(c[1]), "+f"(c[2]), "+f"(c[3])
        : "r"(a0), "r"(a1), "r"(a2), "r"(a3), "r"(b0), "r"(b1));
}
__device__ __forceinline__ void mma_bf16(float* c, uint32_t a0, uint32_t a1,
                                         uint32_t a2, uint32_t a3,
                                         uint32_t b0, uint32_t b1) {
    asm volatile(
        "mma.sync.aligned.m16n8k16.row.col.f32.bf16.bf16.f32 "
        "{%0,%1,%2,%3}, {%4,%5,%6,%7}, {%8,%9}, {%0,%1,%2,%3};\n"
        : "+f"(c[0]), "+f"(c[1]), "+f"(c[2]), "+f"(c[3])
        : "r"(a0), "r"(a1), "r"(a2), "r"(a3), "r"(b0), "r"(b1));
}
__device__ __forceinline__ void mma_tf32(float* c, uint32_t a0, uint32_t a1,
                                         uint32_t a2, uint32_t a3,
                                         uint32_t b0, uint32_t b1) {
    asm volatile(
        "mma.sync.aligned.m16n8k8.row.col.f32.tf32.tf32.f32 "
        "{%0,%1,%2,%3}, {%4,%5,%6,%7}, {%8,%9}, {%0,%1,%2,%3};\n"
        : "+f"(c[0]), "+f"(c[1]), "+f"(c[2]), "+f"(c[3])
        : "r"(a0), "r"(a1), "r"(a2), "r"(a3), "r"(b0), "r"(b1));
}
__device__ __forceinline__ void ldsm4(uint32_t* a, uint32_t saddr) {
    asm volatile("ldmatrix.sync.aligned.m8n8.x4.shared.b16 {%0,%1,%2,%3}, [%4];"
                 : "=r"(a[0]), "=r"(a[1]), "=r"(a[2]), "=r"(a[3]) : "r"(saddr));
}

#define AST2 20
#define BSTX 136
#define BST3 200
#define AST 36
#define BST 68

// ---------------- merged fp8 weight prepack (single launch) ---------------------
__global__ __launch_bounds__(256) void pack_all_kernel(
    const float* __restrict__ wx_f, const float* __restrict__ wx_b,
    const float* __restrict__ w1, const float* __restrict__ w2,
    const float* __restrict__ w3, const float* __restrict__ w4,
    uint32_t* __restrict__ wxqf, uint32_t* __restrict__ wxqb,
    uint32_t* __restrict__ cwq)
{
    int idx = blockIdx.x * 256 + threadIdx.x;
    const int SX = (C4T / 4) * G4;             // 196608
    if (idx < SX) {
        int kq = idx >> 10, n = idx & 1023;
        const float* s = wx_f + (size_t)(4 * kq) * G4 + n;
        wxqf[idx] = pack4e4m3(s[0], s[G4], s[2 * G4], s[3 * G4]);
        return;
    }
    idx -= SX;
    if (idx < SX) {
        int kq = idx >> 10, n = idx & 1023;
        const float* s = wx_b + (size_t)(4 * kq) * G4 + n;
        wxqb[idx] = pack4e4m3(s[0], s[G4], s[2 * G4], s[3 * G4]);
        return;
    }
    idx -= SX;
    const int T1 = (DN / 4) * C1;              // 73728 per tap
    const float* src;
    uint32_t* dst;
    if (idx < 1 * T1)      { src = w1; dst = cwq; }
    else if (idx < 3 * T1) { src = w2; dst = cwq + (size_t)1 * T1; idx -= 1 * T1; }
    else if (idx < 6 * T1) { src = w3; dst = cwq + (size_t)3 * T1; idx -= 3 * T1; }
    else if (idx < 10 * T1){ src = w4; dst = cwq + (size_t)6 * T1; idx -= 6 * T1; }
    else return;
    int kqg = idx / C1, n = idx - kqg * C1;    // kqg spans taps*384
    const float* s = src + (size_t)(4 * kqg) * C1 + n;
    dst[idx] = pack4e4m3(s[0], s[C1], s[2 * C1], s[3 * C1]);
}

// ---------------- LayerNorm 1 -> packed fp8 quads --------------------------------
__global__ __launch_bounds__(256) void ln1_kernel(
    const float* __restrict__ ha, const float* __restrict__ hb,
    const float* __restrict__ g,  const float* __restrict__ be,
    uint32_t* __restrict__ out4)
{
    int row = blockIdx.x;
    const float* A = ha + (size_t)row * 768;
    const float* B = hb + (size_t)row * 768;
    float s = 0.f, s2 = 0.f;
    for (int d = threadIdx.x; d < DN; d += 256) {
        float v = (d < 768) ? A[d] : B[d - 768];
        s += v; s2 += v * v;
    }
    __shared__ float rs[256], rq[256];
    rs[threadIdx.x] = s; rq[threadIdx.x] = s2;
    __syncthreads();
    for (int off = 128; off > 0; off >>= 1) {
        if (threadIdx.x < off) {
            rs[threadIdx.x] += rs[threadIdx.x + off];
            rq[threadIdx.x] += rq[threadIdx.x + off];
        }
        __syncthreads();
    }
    float mean = rs[0] * (1.f / DN);
    float var  = rq[0] * (1.f / DN) - mean * mean;
    float rstd = rsqrtf(var + 1e-5f);
    uint32_t* O = out4 + (size_t)row * (DN / 4);
    for (int d4 = threadIdx.x; d4 < DN / 4; d4 += 256) {
        int d = d4 << 2;
        float o[4];
#pragma unroll
        for (int j = 0; j < 4; j++) {
            int dd = d + j;
            float v = (dd < 768) ? A[dd] : B[dd - 768];
            o[j] = (v - mean) * rstd * g[dd] + be[dd];
        }
        O[d4] = pack4e4m3(o[0], o[1], o[2], o[3]);
    }
}

// ---------------- LayerNorm 2 -> packed fp8 quads --------------------------------
__global__ __launch_bounds__(256) void ln2_kernel(
    const float* __restrict__ in, const float* __restrict__ g,
    const float* __restrict__ be, uint32_t* __restrict__ out4)
{
    int row = blockIdx.x;
    const float* X = in + (size_t)row * C4T;
    float s = 0.f, s2 = 0.f;
    for (int d = threadIdx.x; d < C4T; d += 256) {
        float v = X[d]; s += v; s2 += v * v;
    }
    __shared__ float rs[256], rq[256];
    rs[threadIdx.x] = s; rq[threadIdx.x] = s2;
    __syncthreads();
    for (int off = 128; off > 0; off >>= 1) {
        if (threadIdx.x < off) {
            rs[threadIdx.x] += rs[threadIdx.x + off];
            rq[threadIdx.x] += rq[threadIdx.x + off];
        }
        __syncthreads();
    }
    float mean = rs[0] * (1.f / C4T);
    float var  = rq[0] * (1.f / C4T) - mean * mean;
    float rstd = rsqrtf(var + 1e-5f);
    uint32_t* O = out4 + (size_t)row * (C4T / 4);
    for (int d4 = threadIdx.x; d4 < C4T / 4; d4 += 256) {
        int d = d4 << 2;
        float o[4];
#pragma unroll
        for (int j = 0; j < 4; j++) {
            int dd = d + j;
            o[j] = (X[dd] - mean) * rstd * g[dd] + be[dd];
        }
        O[d4] = pack4e4m3(o[0], o[1], o[2], o[3]);
    }
}

// ---------------- fp8 dual xWx GEMM: 128x128 tile, K=768 (12 ktiles of 64) ------
__global__ __launch_bounds__(256) void gemm_fp8_dual_kernel(
    const uint32_t* __restrict__ A4,
    const uint32_t* __restrict__ Wqf, const uint32_t* __restrict__ Wqb,
    const float* __restrict__ biasf, const float* __restrict__ biasb,
    float* __restrict__ Cf, float* __restrict__ Cb)
{
    const int Nn = G4;
    __shared__ uint32_t As[2][128 * AST2];
    __shared__ uint32_t Bs[2][16 * BSTX];
    int tid = threadIdx.x;
    int half = blockIdx.y >> 3;
    int n0 = (blockIdx.y & 7) * 128;
    const uint32_t* Wq   = half ? Wqb : Wqf;
    const float*    bias = half ? biasb : biasf;
    float*          Cc   = half ? Cb : Cf;
    int m0 = blockIdx.x * 128;
    int wid = tid >> 5, lane = tid & 31;
    int wm0 = (wid & 3) * 32, wn0 = (wid >> 2) * 64;
    int g = lane >> 2, tg = lane & 3;
    const int K4 = C4T >> 2;           // 192 quads per A row

    float acc[2][8][4];
#pragma unroll
    for (int mt = 0; mt < 2; mt++)
#pragma unroll
        for (int nt = 0; nt < 8; nt++)
#pragma unroll
            for (int i = 0; i < 4; i++) acc[mt][nt][i] = 0.f;

    uint32_t abase[2];
#pragma unroll
    for (int sb = 0; sb < 2; sb++)
        abase[sb] = (uint32_t)__cvta_generic_to_shared(
            &As[sb][(wm0 + (lane & 15)) * AST2 + (lane >> 4) * 4]);

    uint4 pa[2], pb[2];
    const int nk = C4T / 64;           // 12
    auto loadA = [&](int kt) {
#pragma unroll
        for (int j = 0; j < 2; j++) {
            int idx4 = tid + j * 256;
            int row = idx4 >> 2, qc = (idx4 & 3) << 2;
            pa[j] = *reinterpret_cast<const uint4*>(A4 + (size_t)(m0 + row) * K4 + kt * 16 + qc);
        }
    };
    auto loadB = [&](int kt) {
#pragma unroll
        for (int j = 0; j < 2; j++) {
            int idx4 = tid + j * 256;
            int kp = idx4 >> 5, nc = (idx4 & 31) << 2;
            pb[j] = *reinterpret_cast<const uint4*>(Wq + (size_t)(kt * 16 + kp) * Nn + n0 + nc);
        }
    };
    auto stage = [&](int sb) {
#pragma unroll
        for (int j = 0; j < 2; j++) {
            int idx4 = tid + j * 256;
            int row = idx4 >> 2, qc = (idx4 & 3) << 2;
            *reinterpret_cast<uint4*>(&As[sb][row * AST2 + qc]) = pa[j];
        }
#pragma unroll
        for (int j = 0; j < 2; j++) {
            int idx4 = tid + j * 256;
            int kp = idx4 >> 5, nc = (idx4 & 31) << 2;
            *reinterpret_cast<uint4*>(&Bs[sb][kp * BSTX + nc]) = pb[j];
        }
    };

    loadA(0); loadB(0);
    stage(0);
    __syncthreads();
    for (int kt = 0; kt < nk; kt++) {
        int cur = kt & 1;
        if (kt + 1 < nk) { loadA(kt + 1); loadB(kt + 1); }
        const uint32_t* Bc = Bs[cur];
        uint32_t ab = abase[cur];
#pragma unroll
        for (int ks = 0; ks < 2; ks++) {
            int kk4 = ks * 8;          // quad offset
            uint32_t a[2][4], b[8][2];
#pragma unroll
            for (int mt = 0; mt < 2; mt++)
                ldsm4(a[mt], ab + (uint32_t)((mt * 16 * AST2 + kk4) * 4));
#pragma unroll
            for (int nt = 0; nt < 8; nt++) {
                int col = wn0 + nt * 8 + g;
                b[nt][0] = Bc[(kk4 + tg    ) * BSTX + col];
                b[nt][1] = Bc[(kk4 + tg + 4) * BSTX + col];
            }
#pragma unroll
            for (int mt = 0; mt < 2; mt++)
#pragma unroll
                for (int nt = 0; nt < 8; nt++)
                    mma_fp8(acc[mt][nt], a[mt][0], a[mt][1], a[mt][2], a[mt][3],
                            b[nt][0], b[nt][1]);
        }
        if (kt + 1 < nk) {
            stage(cur ^ 1);
            __syncthreads();
        }
    }
#pragma unroll
    for (int mt = 0; mt < 2; mt++)
#pragma unroll
        for (int nt = 0; nt < 8; nt++) {
            int col = n0 + wn0 + nt * 8 + 2 * tg;
#pragma unroll
            for (int i = 0; i < 4; i++) {
                int row = m0 + wm0 + mt * 16 + g + (i >> 1) * 8;
                int c = col + (i & 1);
                Cc[(size_t)row * Nn + c] = acc[mt][nt][i] + bias[c];
            }
        }
}

// ---------------- Conv fp8: 128x192 tile, K = ntaps*1536 (24 ktiles/tap) --------
__global__ __launch_bounds__(256) void conv_fp8_kernel(
    const uint32_t* __restrict__ xnq, const uint32_t* __restrict__ cwq,
    const float* __restrict__ cb1, const float* __restrict__ cb2,
    const float* __restrict__ cb3, const float* __restrict__ cb4,
    float* __restrict__ cv)
{
    __shared__ uint32_t As[2][128 * AST2];
    __shared__ uint32_t Bs[2][16 * BST3];
    int tid = threadIdx.x;
    int m0 = blockIdx.x * 128;
    int conv = blockIdx.y;
    int bidx = m0 >> 9;
    int t0   = m0 & 511;
    int tap0 = (conv == 0) ? 0 : (conv == 1) ? 1 : (conv == 2) ? 3 : 6;
    const float* bias = (conv == 0) ? cb1 : (conv == 1) ? cb2 : (conv == 2) ? cb3 : cb4;
    int ntaps = conv + 1;
    int dmin  = (conv < 2) ? 1 : 0;

    int wid = tid >> 5, lane = tid & 31;
    int wm0 = (wid & 3) * 32, wn0 = (wid >> 2) * 96;
    int g = lane >> 2, tg = lane & 3;

    float acc[2][12][4];
#pragma unroll
    for (int mt = 0; mt < 2; mt++)
#pragma unroll
        for (int nt = 0; nt < 12; nt++)
#pragma unroll
            for (int i = 0; i < 4; i++) acc[mt][nt][i] = 0.f;

    uint32_t abase[2];
#pragma unroll
    for (int sb = 0; sb < 2; sb++)
        abase[sb] = (uint32_t)__cvta_generic_to_shared(
            &As[sb][(wm0 + (lane & 15)) * AST2 + (lane >> 4) * 4]);

    const int nkt = DN / 64;           // 24 per tap
    int total = ntaps * nkt;
    const int K4 = DN / 4;             // 384 quads per row

    uint4 pa[2], pb[3];
    auto loadA = [&](int it) {
        int ti = it / nkt, kt = it - ti * nkt;
        int shift = dmin + ti - 1;
#pragma unroll
        for (int j = 0; j < 2; j++) {
            int idx4 = tid + j * 256;
            int row = idx4 >> 2, qc = (idx4 & 3) << 2;
            int tsrc = t0 + row + shift;
            if (tsrc >= 0 && tsrc < TN)
                pa[j] = *reinterpret_cast<const uint4*>(
                    xnq + (size_t)((bidx << 9) + tsrc) * K4 + kt * 16 + qc);
            else
                pa[j] = make_uint4(0u, 0u, 0u, 0u);
        }
    };
    auto loadB = [&](int it) {
        int ti = it / nkt, kt = it - ti * nkt;
#pragma unroll
        for (int j = 0; j < 3; j++) {
            int idx4 = tid + j * 256;
            int kp = idx4 / 48, nc = (idx4 % 48) << 2;
            pb[j] = *reinterpret_cast<const uint4*>(
                cwq + ((size_t)(tap0 + ti) * (DN / 4) + kt * 16 + kp) * C1 + nc);
        }
    };
    auto stage = [&](int sb) {
#pragma unroll
        for (int j = 0; j < 2; j++) {
            int idx4 = tid + j * 256;
            int row = idx4 >> 2, qc = (idx4 & 3) << 2;
            *reinterpret_cast<uint4*>(&As[sb][row * AST2 + qc]) = pa[j];
        }
#pragma unroll
        for (int j = 0; j < 3; j++) {
            int idx4 = tid + j * 256;
            int kp = idx4 / 48, nc = (idx4 % 48) << 2;
            *reinterpret_cast<uint4*>(&Bs[sb][kp * BST3 + nc]) = pb[j];
        }
    };

    loadA(0); loadB(0);
    stage(0);
    __syncthreads();
    for (int it = 0; it < total; it++) {
        int cur = it & 1;
        if (it + 1 < total) { loadA(it + 1); loadB(it + 1); }
        const uint32_t* Bc = Bs[cur];
        uint32_t ab = abase[cur];
#pragma unroll
        for (int ks = 0; ks < 2; ks++) {
            int kk4 = ks * 8;
            uint32_t a[2][4], b[12][2];
#pragma unroll
            for (int mt = 0; mt < 2; mt++)
                ldsm4(a[mt], ab + (uint32_t)((mt * 16 * AST2 + kk4) * 4));
#pragma unroll
            for (int nt = 0; nt < 12; nt++) {
                int col = wn0 + nt * 8 + g;
                b[nt][0] = Bc[(kk4 + tg    ) * BST3 + col];
                b[nt][1] = Bc[(kk4 + tg + 4) * BST3 + col];
            }
#pragma unroll
            for (int mt = 0; mt < 2; mt++)
#pragma unroll
                for (int nt = 0; nt < 12; nt++)
                    mma_fp8(acc[mt][nt], a[mt][0], a[mt][1], a[mt][2], a[mt][3],
                            b[nt][0], b[nt][1]);
        }
        if (it + 1 < total) {
            stage(cur ^ 1);
            __syncthreads();
        }
    }
#pragma unroll
    for (int mt = 0; mt < 2; mt++)
#pragma unroll
        for (int nt = 0; nt < 12; nt++) {
            int cl = wn0 + nt * 8 + 2 * tg;
#pragma unroll
            for (int i = 0; i < 4; i++) {
                int row = m0 + wm0 + mt * 16 + g + (i >> 1) * 8;
                int c   = cl + (i & 1);
                float v = acc[mt][nt][i] + bias[c];
                cv[(size_t)row * C4T + conv * C1 + c] = fmaxf(v, 0.f);
            }
        }
}

// ---------------- TF32 GEMM (logits) --------------------------------------------
__global__ __launch_bounds__(256) void gemm_tf32_kernel(
    const float* __restrict__ A, const float* __restrict__ W,
    const float* __restrict__ bias, float* __restrict__ Cc,
    int M, int Nn, int Kk)
{
    __shared__ uint32_t As[128 * AST];
    __shared__ uint32_t Bs[32 * BST];
    int tid = threadIdx.x;
    int m0 = blockIdx.x * 128, n0 = blockIdx.y * 64;
    int wid = tid >> 5, lane = tid & 31;
    int wm0 = (wid & 3) * 32, wn0 = (wid >> 2) * 32;
    int g = lane >> 2, tg = lane & 3;
    float acc[2][4][4];
#pragma unroll
    for (int mt = 0; mt < 2; mt++)
#pragma unroll
        for (int nt = 0; nt < 4; nt++)
#pragma unroll
            for (int i = 0; i < 4; i++) acc[mt][nt][i] = 0.f;
    float4 pa[4], pb[2];
    int nk = Kk / 32;
    auto loadA = [&](int kt) {
#pragma unroll
        for (int j = 0; j < 4; j++) {
            int idx4 = tid + j * 256;
            int row = idx4 >> 3, kc = (idx4 & 7) << 2;
            pa[j] = *reinterpret_cast<const float4*>(A + (size_t)(m0 + row) * Kk + kt * 32 + kc);
        }
    };
    auto loadB = [&](int kt) {
#pragma unroll
        for (int j = 0; j < 2; j++) {
            int idx4 = tid + j * 256;
            int row = idx4 >> 4, nc = (idx4 & 15) << 2;
            int ncol = n0 + nc;
            const float* Wr = W + (size_t)(kt * 32 + row) * Nn;
            float4 v;
            if (ncol + 3 < Nn) v = *reinterpret_cast<const float4*>(Wr + ncol);
            else {
                v.x = (ncol + 0 < Nn) ? Wr[ncol + 0] : 0.f;
                v.y = (ncol + 1 < Nn) ? Wr[ncol + 1] : 0.f;
                v.z = (ncol + 2 < Nn) ? Wr[ncol + 2] : 0.f;
                v.w = (ncol + 3 < Nn) ? Wr[ncol + 3] : 0.f;
            }
            pb[j] = v;
        }
    };
    auto stage = [&]() {
#pragma unroll
        for (int j = 0; j < 4; j++) {
            int idx4 = tid + j * 256;
            int row = idx4 >> 3, kc = (idx4 & 7) << 2;
            As[row * AST + kc + 0] = f2tf32(pa[j].x);
            As[row * AST + kc + 1] = f2tf32(pa[j].y);
            As[row * AST + kc + 2] = f2tf32(pa[j].z);
            As[row * AST + kc + 3] = f2tf32(pa[j].w);
        }
#pragma unroll
        for (int j = 0; j < 2; j++) {
            int idx4 = tid + j * 256;
            int row = idx4 >> 4, nc = (idx4 & 15) << 2;
            Bs[row * BST + nc + 0] = f2tf32(pb[j].x);
            Bs[row * BST + nc + 1] = f2tf32(pb[j].y);
            Bs[row * BST + nc + 2] = f2tf32(pb[j].z);
            Bs[row * BST + nc + 3] = f2tf32(pb[j].w);
        }
    };
    loadA(0); loadB(0);
    for (int kt = 0; kt < nk; kt++) {
        __syncthreads();
        stage();
        __syncthreads();
        if (kt + 1 < nk) { loadA(kt + 1); loadB(kt + 1); }
#pragma unroll
        for (int ks = 0; ks < 4; ks++) {
            int kk = ks * 8;
            uint32_t a[2][4], b[4][2];
#pragma unroll
            for (int mt = 0; mt < 2; mt++) {
                int r0 = wm0 + mt * 16 + g;
                a[mt][0] = As[(r0    ) * AST + kk + tg];
                a[mt][1] = As[(r0 + 8) * AST + kk + tg];
                a[mt][2] = As[(r0    ) * AST + kk + tg + 4];
                a[mt][3] = As[(r0 + 8) * AST + kk + tg + 4];
            }
#pragma unroll
            for (int nt = 0; nt < 4; nt++) {
                int col = wn0 + nt * 8 + g;
                b[nt][0] = Bs[(kk + tg    ) * BST + col];
                b[nt][1] = Bs[(kk + tg + 4) * BST + col];
            }
#pragma unroll
            for (int mt = 0; mt < 2; mt++)
#pragma unroll
                for (int nt = 0; nt < 4; nt++)
                    mma_tf32(acc[mt][nt], a[mt][0], a[mt][1], a[mt][2], a[mt][3],
                             b[nt][0], b[nt][1]);
        }
    }
#pragma unroll
    for (int mt = 0; mt < 2; mt++)
#pragma unroll
        for (int nt = 0; nt < 4; nt++) {
            int col = n0 + wn0 + nt * 8 + 2 * tg;
#pragma unroll
            for (int i = 0; i < 4; i++) {
                int row = m0 + wm0 + mt * 16 + g + (i >> 1) * 8;
                int c = col + (i & 1);
                if (c < Nn) Cc[(size_t)row * Nn + c] = acc[mt][nt][i] + bias[c];
            }
        }
}

// ---------------- LSTM: 4-CTA cluster, bf16 mma z-phase (unchanged) -------------
#define LSW   (256 * 132 * 4)
#define LSH2  (2 * 128 * 8 * 4)
#define LSZ   (256 * 5 * 4)
#define LS_TOTAL (LSW + LSH2 + LSZ)

__global__ void __cluster_dims__(4, 1, 1) __launch_bounds__(256)
lstm_cluster_kernel(
    const float* __restrict__ gxf, const float* __restrict__ gxb,
    const float* __restrict__ wh_f, const float* __restrict__ wh_b,
    const int* __restrict__ amask, float* __restrict__ hout)
{
    extern __shared__ char sm_[];
    uint32_t* whs2 = (uint32_t*)sm_;
    uint32_t* h2   = (uint32_t*)(sm_ + LSW);
    float*    zbuf = (float*)(sm_ + LSW + LSH2);

    int tid = threadIdx.x;
    uint32_t rank;
    asm("mov.u32 %0, %%cluster_ctarank;" : "=r"(rank));
    int grp = blockIdx.x >> 2;
    int dir = grp >> 4;
    int b0  = (grp & 15) * 4;
    const float* __restrict__ Wh = dir ? wh_b : wh_f;
    const float* __restrict__ gx = dir ? gxb : gxf;

    for (int i = tid; i < 256 * 128; i += 256) {
        int lcol = i >> 7, kp = i & 127;
        int gcol = ((lcol >> 6) << 8) + (int)rank * 64 + (lcol & 63);
        whs2[lcol * 132 + kp] = packbf(Wh[(2 * kp) * G4 + gcol],
                                       Wh[(2 * kp + 1) * G4 + gcol]);
    }
    for (int i = tid; i < 2048; i += 256) h2[i] = 0u;

    int lane = tid & 31, wrp = tid >> 5;
    int g = lane >> 2, tg = lane & 3;
    int pb = tid >> 6, pj = tid & 63;
    int bb = b0 + pb;
    float h_r = 0.f, c_r = 0.f, op_r = 0.f;

    uint32_t ha[2][4];
    {
        int k = (int)rank * 64 + pj;
        uint32_t loc;
        const void* p = (const void*)((const char*)h2 + ((k >> 1) * 8 + pb) * 4 + (k & 1) * 2);
        asm("{ .reg .u64 t; cvta.to.shared.u64 t, %1; cvt.u32.u64 %0, t; }"
            : "=r"(loc) : "l"(p));
#pragma unroll
        for (int bf = 0; bf < 2; bf++) {
            uint32_t off = loc + bf * 4096;
#pragma unroll
            for (int r = 0; r < 4; r++)
                asm("mapa.shared::cluster.u32 %0, %1, %2;"
                    : "=r"(ha[bf][r]) : "r"(off), "r"(r));
        }
    }

    asm volatile("barrier.cluster.arrive.aligned;" ::: "memory");
    asm volatile("barrier.cluster.wait.aligned;"   ::: "memory");

    int buf = 0;
    for (int s = 0; s < TN; s++) {
        int t = dir ? (TN - 1 - s) : s;
        size_t gb = ((size_t)(bb * TN + t)) * G4 + (size_t)rank * 64 + pj;
        float gx0 = gx[gb], gx1 = gx[gb + 256], gx2 = gx[gb + 512], gx3 = gx[gb + 768];
        int mv = amask[bb * TN + t];

        const uint32_t* h2c = h2 + buf * 1024;
        float d0[4] = {0.f, 0.f, 0.f, 0.f}, d1[4] = {0.f, 0.f, 0.f, 0.f};
        int r0 = wrp * 32 + g;
#pragma unroll
        for (int kt = 0; kt < 16; kt++) {
            int kk2 = kt * 8;
            uint32_t bq0 = h2c[(kk2 + tg) * 8 + g];
            uint32_t bq1 = h2c[(kk2 + tg + 4) * 8 + g];
            uint32_t a0 = whs2[(r0     ) * 132 + kk2 + tg];
            uint32_t a1 = whs2[(r0 +  8) * 132 + kk2 + tg];
            uint32_t a2 = whs2[(r0     ) * 132 + kk2 + tg + 4];
            uint32_t a3 = whs2[(r0 +  8) * 132 + kk2 + tg + 4];
            mma_bf16(d0, a0, a1, a2, a3, bq0, bq1);
            a0 = whs2[(r0 + 16) * 132 + kk2 + tg];
            a1 = whs2[(r0 + 24) * 132 + kk2 + tg];
            a2 = whs2[(r0 + 16) * 132 + kk2 + tg + 4];
            a3 = whs2[(r0 + 24) * 132 + kk2 + tg + 4];
            mma_bf16(d1, a0, a1, a2, a3, bq0, bq1);
        }
        if (tg < 2) {
#pragma unroll
            for (int i = 0; i < 4; i++) {
                int col = 2 * tg + (i & 1);
                zbuf[(r0 + (i >> 1) * 8     ) * 5 + col] = d0[i];
                zbuf[(r0 + (i >> 1) * 8 + 16) * 5 + col] = d1[i];
            }
        }
        __syncthreads();

        {
            float zi = zbuf[(      pj) * 5 + pb] + gx0;
            float zf = zbuf[( 64 + pj) * 5 + pb] + gx1;
            float zg = zbuf[(128 + pj) * 5 + pb] + gx2;
            float zo = zbuf[(192 + pj) * 5 + pb] + gx3;
            float ii = 1.f / (1.f + expf(-zi));
            float ff = 1.f / (1.f + expf(-zf));
            float gg = tanhf(zg);
            float oo = 1.f / (1.f + expf(-zo));
            float cn = ff * c_r + ii * gg;
            float hn = oo * tanhf(cn);
            bool m = mv != 0;
            float hq = m ? hn : h_r;
            c_r  = m ? cn : c_r;
            op_r = m ? hn : op_r;
            h_r  = hq;
            hout[((size_t)(bb * TN + t)) * (2 * HN) + dir * HN + (int)rank * 64 + pj] = op_r;
            uint16_t hb16;
            asm("cvt.rn.bf16.f32 %0, %1;" : "=h"(hb16) : "f"(hq));
            int nb = buf ^ 1;
#pragma unroll
            for (int r = 0; r < 4; r++)
                asm volatile("st.shared::cluster.b16 [%0], %1;"
                             :: "r"(ha[nb][r]), "h"(hb16) : "memory");
        }
        asm volatile("barrier.cluster.arrive.aligned;" ::: "memory");
        asm volatile("barrier.cluster.wait.aligned;"   ::: "memory");
        buf ^= 1;
    }
}

// ---------------- CRF ------------------------------------------------------------
__global__ __launch_bounds__(32) void crf_kernel(
    const int* __restrict__ inputs, const int* __restrict__ targets,
    const float* __restrict__ trans, const float* __restrict__ logits,
    float* __restrict__ out)
{
    int b = blockIdx.x;
    int lane = threadIdx.x;
    __shared__ float tr[LBL * LBL];
    __shared__ float alpha[LBL];
    for (int i = lane; i < LBL * LBL; i += 32) tr[i] = trans[i];
    int cnt = 0;
    for (int t = lane; t < TN; t += 32) cnt += (inputs[b * TN + t] != 0);
#pragma unroll
    for (int o = 16; o; o >>= 1) cnt += __shfl_xor_sync(0xffffffffu, cnt, o);
    int seqlen = cnt;
    const float* lg = logits + (size_t)b * TN * LBL;
    const int*   tg = targets + b * TN;
    float us = 0.f, bs = 0.f;
    for (int t = lane; t < TN; t += 32) {
        if (t < seqlen) us += lg[t * LBL + tg[t]];
        if (t >= 1 && t < seqlen) bs += tr[tg[t - 1] * LBL + tg[t]];
    }
#pragma unroll
    for (int o = 16; o; o >>= 1) {
        us += __shfl_xor_sync(0xffffffffu, us, o);
        bs += __shfl_xor_sync(0xffffffffu, bs, o);
    }
    __syncwarp();
    if (lane < LBL) alpha[lane] = lg[lane];
    __syncwarp();
    for (int t = 1; t < TN; t++) {
        float newv = 0.f;
        if (lane < LBL) {
            float m = -1e30f;
#pragma unroll
            for (int i = 0; i < LBL; i++) m = fmaxf(m, alpha[i] + tr[i * LBL + lane]);
            float ss = 0.f;
#pragma unroll
            for (int i = 0; i < LBL; i++) ss += expf(alpha[i] + tr[i * LBL + lane] - m);
            newv = m + logf(ss) + lg[t * LBL + lane];
        }
        __syncwarp();
        if (lane < LBL && t < seqlen) alpha[lane] = newv;
        __syncwarp();
    }
    float a = (lane < LBL) ? alpha[lane] : -1e30f;
    float mx = a;
#pragma unroll
    for (int o = 16; o; o >>= 1) mx = fmaxf(mx, __shfl_xor_sync(0xffffffffu, mx, o));
    float e = (lane < LBL) ? expf(a - mx) : 0.f;
#pragma unroll
    for (int o = 16; o; o >>= 1) e += __shfl_xor_sync(0xffffffffu, e, o);
    float lognorm = mx + logf(e);
    if (lane == 0) out[b] = us + bs - lognorm;
}

// ---------------- launch -----------------------------------------------------------
extern "C" void kernel_launch(void* const* d_in, const int* in_sizes, int n_in,
                              void* d_out, int out_size)
{
    const int*   inputs = (const int*)  d_in[0];
    const int*   amask  = (const int*)  d_in[1];
    const int*   targets= (const int*)  d_in[2];
    const float* hid_a  = (const float*)d_in[3];
    const float* hid_b  = (const float*)d_in[4];
    const float* ln1_g  = (const float*)d_in[5];
    const float* ln1_b  = (const float*)d_in[6];
    const float* w1 = (const float*)d_in[7];
    const float* b1 = (const float*)d_in[8];
    const float* w2 = (const float*)d_in[9];
    const float* b2 = (const float*)d_in[10];
    const float* w3 = (const float*)d_in[11];
    const float* b3 = (const float*)d_in[12];
    const float* w4 = (const float*)d_in[13];
    const float* b4 = (const float*)d_in[14];
    const float* ln2_g = (const float*)d_in[15];
    const float* ln2_b = (const float*)d_in[16];
    const float* wx_f  = (const float*)d_in[17];
    const float* wh_f  = (const float*)d_in[18];
    const float* bf    = (const float*)d_in[19];
    const float* wx_b  = (const float*)d_in[20];
    const float* wh_b  = (const float*)d_in[21];
    const float* bb    = (const float*)d_in[22];
    const float* wd    = (const float*)d_in[23];
    const float* bd    = (const float*)d_in[24];
    const float* trans = (const float*)d_in[25];

    uint32_t *xnq, *coq, *wxqf, *wxqb, *cwq;
    float *cv, *gxf, *gxb, *hh, *lg;
    cudaGetSymbolAddress((void**)&xnq,  g_xnq);
    cudaGetSymbolAddress((void**)&cv,   g_cv);
    cudaGetSymbolAddress((void**)&coq,  g_coq);
    cudaGetSymbolAddress((void**)&gxf,  g_gxf);
    cudaGetSymbolAddress((void**)&gxb,  g_gxb);
    cudaGetSymbolAddress((void**)&hh,   g_h);
    cudaGetSymbolAddress((void**)&lg,   g_lg);
    cudaGetSymbolAddress((void**)&wxqf, g_wxqf);
    cudaGetSymbolAddress((void**)&wxqb, g_wxqb);
    cudaGetSymbolAddress((void**)&cwq,  g_cwq);

    cudaFuncSetAttribute(lstm_cluster_kernel,
                         cudaFuncAttributeMaxDynamicSharedMemorySize, LS_TOTAL);

    {
        int ntot = 2 * ((C4T / 4) * G4) + 10 * (DN / 4) * C1;   // 1,130,496
        pack_all_kernel<<<(ntot + 255) / 256, 256>>>(
            wx_f, wx_b, w1, w2, w3, w4, wxqf, wxqb, cwq);
    }

    ln1_kernel<<<BT, 256>>>(hid_a, hid_b, ln1_g, ln1_b, xnq);
    conv_fp8_kernel<<<dim3(BT / 128, 4), 256>>>(xnq, cwq, b1, b2, b3, b4, cv);
    ln2_kernel<<<BT, 256>>>(cv, ln2_g, ln2_b, coq);
    gemm_fp8_dual_kernel<<<dim3(BT / 128, 16), 256>>>(
        coq, wxqf, wxqb, bf, bb, gxf, gxb);
    lstm_cluster_kernel<<<128, 256, LS_TOTAL>>>(gxf, gxb, wh_f, wh_b, amask, hh);
    gemm_tf32_kernel<<<dim3(BT / 128, 1), 256>>>(hh, wd, bd, lg, BT, LBL, 2 * HN);
    crf_kernel<<<BN, 32>>>(inputs, targets, trans, lg, (float*)d_out);
}

// round 14
// speedup vs baseline: 4.1603x; 1.1481x over previous
#include <cuda_runtime.h>
#include <math.h>
#include <stdint.h>

#define BN   64
#define TN   512
#define BT   32768
#define DN   1536
#define C1   192
#define C4T  768
#define HN   256
#define G4   1024
#define LBL  20

// ---------------- scratch (static device memory) ------------------------------
__device__ uint32_t g_xnq [ (size_t)BT * DN / 4 ];
__device__ float    g_cv  [ (size_t)BT * C4T    ];
__device__ uint32_t g_coq [ (size_t)BT * C4T / 4];
__device__ float    g_gxf [ (size_t)BT * G4     ];
__device__ float    g_gxb [ (size_t)BT * G4     ];
__device__ float    g_h   [ (size_t)BT * 2 * HN ];
__device__ float    g_lg  [ (size_t)BT * LBL    ];
__device__ uint32_t g_wxqf[ (C4T / 4) * G4 ];
__device__ uint32_t g_wxqb[ (C4T / 4) * G4 ];
__device__ uint32_t g_cwq [ 10 * (DN / 4) * C1 ];

// ---------------- helpers -----------------------------------------------------
__device__ __forceinline__ uint32_t packbf(float lo, float hi) {
    uint32_t u;
    asm("cvt.rn.bf16x2.f32 %0, %1, %2;" : "=r"(u) : "f"(hi), "f"(lo));
    return u;
}
__device__ __forceinline__ uint32_t pack4e4m3(float e0, float e1, float e2, float e3) {
    uint16_t lo, hi;
    asm("cvt.rn.satfinite.e4m3x2.f32 %0, %1, %2;" : "=h"(lo) : "f"(e1), "f"(e0));
    asm("cvt.rn.satfinite.e4m3x2.f32 %0, %1, %2;" : "=h"(hi) : "f"(e3), "f"(e2));
    return (uint32_t)lo | ((uint32_t)hi << 16);
}
__device__ __forceinline__ uint32_t f2tf32(float f) {
    uint32_t u;
    asm("cvt.rna.tf32.f32 %0, %1;" : "=r"(u) : "f"(f));
    return u;
}
__device__ __forceinline__ float ftanh(float x) {
    float y;
    asm("tanh.approx.f32 %0, %1;" : "=f"(y) : "f"(x));
    return y;
}
__device__ __forceinline__ float fsig(float x) {
    return 0.5f * ftanh(0.5f * x) + 0.5f;
}
__device__ __forceinline__ void mma_fp8(float* c, uint32_t a0, uint32_t a1,
                                        uint32_t a2, uint32_t a3,
                                        uint32_t b0, uint32_t b1) {
    asm volatile(
        "mma.sync.aligned.m16n8k32.row.col.f32.e4m3.e4m3.f32 "
        "{%0,%1,%2,%3}, {%4,%5,%6,%7}, {%8,%9}, {%0,%1,%2,%3};\n"
        : "+f"(c[0]), "+f"(c[1]), "+f"(c[2]), "+f"(c[3])
        : "r"(a0), "r"(a1), "r"(a2), "r"(a3), "r"(b0), "r"(b1));
}
__device__ __forceinline__ void mma_bf16(float* c, uint32_t a0, uint32_t a1,
                                         uint32_t a2, uint32_t a3,
                                         uint32_t b0, uint32_t b1) {
    asm volatile(
        "mma.sync.aligned.m16n8k16.row.col.f32.bf16.bf16.f32 "
        "{%0,%1,%2,%3}, {%4,%5,%6,%7}, {%8,%9}, {%0,%1,%2,%3};\n"
        : "+f"(c[0]), "+f"(c[1]), "+f"(c[2]), "+f"(c[3])
        : "r"(a0), "r"(a1), "r"(a2), "r"(a3), "r"(b0), "r"(b1));
}
__device__ __forceinline__ void mma_tf32(float* c, uint32_t a0, uint32_t a1,
                                         uint32_t a2, uint32_t a3,
                                         uint32_t b0, uint32_t b1) {
    asm volatile(
        "mma.sync.aligned.m16n8k8.row.col.f32.tf32.tf32.f32 "
        "{%0,%1,%2,%3}, {%4,%5,%6,%7}, {%8,%9}, {%0,%1,%2,%3};\n"
        : "+f"(c[0]), "+f"(c[1]), "+f"(c[2]), "+f"(c[3])
        : "r"(a0), "r"(a1), "r"(a2), "r"(a3), "r"(b0), "r"(b1));
}
__device__ __forceinline__ void ldsm4(uint32_t* a, uint32_t saddr) {
    asm volatile("ldmatrix.sync.aligned.m8n8.x4.shared.b16 {%0,%1,%2,%3}, [%4];"
                 : "=r"(a[0]), "=r"(a[1]), "=r"(a[2]), "=r"(a[3]) : "r"(saddr));
}
__device__ __forceinline__ uint32_t smem_u32(const void* p) {
    uint32_t a;
    asm("{ .reg .u64 t; cvta.to.shared.u64 t, %1; cvt.u32.u64 %0, t; }"
        : "=r"(a) : "l"(p));
    return a;
}
#define MB_INIT(a, c) asm volatile("mbarrier.init.shared.b64 [%0], %1;" :: "r"(a), "r"((uint32_t)(c)) : "memory")
#define MB_WAIT(a, par) do { \
    asm volatile("{\n\t.reg .pred P1;\n\tWL%=:\n\t" \
        "mbarrier.try_wait.parity.acquire.cta.shared::cta.b64 P1, [%0], %1, 0x989680;\n\t" \
        "@P1 bra WD%=;\n\tbra WL%=;\n\tWD%=:\n\t}" :: "r"(a), "r"((uint32_t)(par)) : "memory"); } while (0)
#define MB_ARRIVE_REMOTE(a) \
    asm volatile("mbarrier.arrive.shared::cluster.b64 _, [%0];" :: "r"(a) : "memory")

#define AST2 20
#define BSTX 136
#define BST3 200
#define AST 36
#define BST 68

// ---------------- merged fp8 weight prepack -------------------------------------
__global__ __launch_bounds__(256) void pack_all_kernel(
    const float* __restrict__ wx_f, const float* __restrict__ wx_b,
    const float* __restrict__ w1, const float* __restrict__ w2,
    const float* __restrict__ w3, const float* __restrict__ w4,
    uint32_t* __restrict__ wxqf, uint32_t* __restrict__ wxqb,
    uint32_t* __restrict__ cwq)
{
    int idx = blockIdx.x * 256 + threadIdx.x;
    const int SX = (C4T / 4) * G4;
    if (idx < SX) {
        int kq = idx >> 10, n = idx & 1023;
        const float* s = wx_f + (size_t)(4 * kq) * G4 + n;
        wxqf[idx] = pack4e4m3(s[0], s[G4], s[2 * G4], s[3 * G4]);
        return;
    }
    idx -= SX;
    if (idx < SX) {
        int kq = idx >> 10, n = idx & 1023;
        const float* s = wx_b + (size_t)(4 * kq) * G4 + n;
        wxqb[idx] = pack4e4m3(s[0], s[G4], s[2 * G4], s[3 * G4]);
        return;
    }
    idx -= SX;
    const int T1 = (DN / 4) * C1;
    const float* src;
    uint32_t* dst;
    if (idx < 1 * T1)      { src = w1; dst = cwq; }
    else if (idx < 3 * T1) { src = w2; dst = cwq + (size_t)1 * T1; idx -= 1 * T1; }
    else if (idx < 6 * T1) { src = w3; dst = cwq + (size_t)3 * T1; idx -= 3 * T1; }
    else if (idx < 10 * T1){ src = w4; dst = cwq + (size_t)6 * T1; idx -= 6 * T1; }
    else return;
    int kqg = idx / C1, n = idx - kqg * C1;
    const float* s = src + (size_t)(4 * kqg) * C1 + n;
    dst[idx] = pack4e4m3(s[0], s[C1], s[2 * C1], s[3 * C1]);
}

// ---------------- LayerNorm 1: single-pass, register-cached, 192 thr ------------
__global__ __launch_bounds__(192) void ln1_kernel(
    const float* __restrict__ ha, const float* __restrict__ hb,
    const float* __restrict__ g,  const float* __restrict__ be,
    uint32_t* __restrict__ out4)
{
    int row = blockIdx.x;
    int tid = threadIdx.x;
    int d0 = tid * 8;
    float4 v0, v1;
    if (tid < 96) {
        const float* A = ha + (size_t)row * 768 + d0;
        v0 = *reinterpret_cast<const float4*>(A);
        v1 = *reinterpret_cast<const float4*>(A + 4);
    } else {
        const float* B = hb + (size_t)row * 768 + (d0 - 768);
        v0 = *reinterpret_cast<const float4*>(B);
        v1 = *reinterpret_cast<const float4*>(B + 4);
    }
    float s  = v0.x + v0.y + v0.z + v0.w + v1.x + v1.y + v1.z + v1.w;
    float s2 = v0.x*v0.x + v0.y*v0.y + v0.z*v0.z + v0.w*v0.w
             + v1.x*v1.x + v1.y*v1.y + v1.z*v1.z + v1.w*v1.w;
#pragma unroll
    for (int o = 16; o; o >>= 1) {
        s  += __shfl_xor_sync(0xffffffffu, s, o);
        s2 += __shfl_xor_sync(0xffffffffu, s2, o);
    }
    __shared__ float ws[6], wq[6];
    int wid = tid >> 5;
    if ((tid & 31) == 0) { ws[wid] = s; wq[wid] = s2; }
    __syncthreads();
    float S = ws[0] + ws[1] + ws[2] + ws[3] + ws[4] + ws[5];
    float Q = wq[0] + wq[1] + wq[2] + wq[3] + wq[4] + wq[5];
    float mean = S * (1.f / DN);
    float var  = Q * (1.f / DN) - mean * mean;
    float rstd = rsqrtf(var + 1e-5f);
    float4 g0 = *reinterpret_cast<const float4*>(g + d0);
    float4 g1 = *reinterpret_cast<const float4*>(g + d0 + 4);
    float4 b0 = *reinterpret_cast<const float4*>(be + d0);
    float4 b1 = *reinterpret_cast<const float4*>(be + d0 + 4);
    uint32_t* O = out4 + (size_t)row * (DN / 4) + tid * 2;
    O[0] = pack4e4m3((v0.x - mean) * rstd * g0.x + b0.x,
                     (v0.y - mean) * rstd * g0.y + b0.y,
                     (v0.z - mean) * rstd * g0.z + b0.z,
                     (v0.w - mean) * rstd * g0.w + b0.w);
    O[1] = pack4e4m3((v1.x - mean) * rstd * g1.x + b1.x,
                     (v1.y - mean) * rstd * g1.y + b1.y,
                     (v1.z - mean) * rstd * g1.z + b1.z,
                     (v1.w - mean) * rstd * g1.w + b1.w);
}

// ---------------- LayerNorm 2: single-pass, register-cached, 192 thr ------------
__global__ __launch_bounds__(192) void ln2_kernel(
    const float* __restrict__ in, const float* __restrict__ g,
    const float* __restrict__ be, uint32_t* __restrict__ out4)
{
    int row = blockIdx.x;
    int tid = threadIdx.x;
    int d0 = tid * 4;
    float4 v = *reinterpret_cast<const float4*>(in + (size_t)row * C4T + d0);
    float s  = v.x + v.y + v.z + v.w;
    float s2 = v.x*v.x + v.y*v.y + v.z*v.z + v.w*v.w;
#pragma unroll
    for (int o = 16; o; o >>= 1) {
        s  += __shfl_xor_sync(0xffffffffu, s, o);
        s2 += __shfl_xor_sync(0xffffffffu, s2, o);
    }
    __shared__ float ws[6], wq[6];
    int wid = tid >> 5;
    if ((tid & 31) == 0) { ws[wid] = s; wq[wid] = s2; }
    __syncthreads();
    float S = ws[0] + ws[1] + ws[2] + ws[3] + ws[4] + ws[5];
    float Q = wq[0] + wq[1] + wq[2] + wq[3] + wq[4] + wq[5];
    float mean = S * (1.f / C4T);
    float var  = Q * (1.f / C4T) - mean * mean;
    float rstd = rsqrtf(var + 1e-5f);
    float4 gg = *reinterpret_cast<const float4*>(g + d0);
    float4 bb = *reinterpret_cast<const float4*>(be + d0);
    out4[(size_t)row * (C4T / 4) + tid] =
        pack4e4m3((v.x - mean) * rstd * gg.x + bb.x,
                  (v.y - mean) * rstd * gg.y + bb.y,
                  (v.z - mean) * rstd * gg.z + bb.z,
                  (v.w - mean) * rstd * gg.w + bb.w);
}

// ---------------- fp8 dual xWx GEMM (unchanged from R12) ------------------------
__global__ __launch_bounds__(256) void gemm_fp8_dual_kernel(
    const uint32_t* __restrict__ A4,
    const uint32_t* __restrict__ Wqf, const uint32_t* __restrict__ Wqb,
    const float* __restrict__ biasf, const float* __restrict__ biasb,
    float* __restrict__ Cf, float* __restrict__ Cb)
{
    const int Nn = G4;
    __shared__ uint32_t As[2][128 * AST2];
    __shared__ uint32_t Bs[2][16 * BSTX];
    int tid = threadIdx.x;
    int half = blockIdx.y >> 3;
    int n0 = (blockIdx.y & 7) * 128;
    const uint32_t* Wq   = half ? Wqb : Wqf;
    const float*    bias = half ? biasb : biasf;
    float*          Cc   = half ? Cb : Cf;
    int m0 = blockIdx.x * 128;
    int wid = tid >> 5, lane = tid & 31;
    int wm0 = (wid & 3) * 32, wn0 = (wid >> 2) * 64;
    int g = lane >> 2, tg = lane & 3;
    const int K4 = C4T >> 2;

    float acc[2][8][4];
#pragma unroll
    for (int mt = 0; mt < 2; mt++)
#pragma unroll
        for (int nt = 0; nt < 8; nt++)
#pragma unroll
            for (int i = 0; i < 4; i++) acc[mt][nt][i] = 0.f;

    uint32_t abase[2];
#pragma unroll
    for (int sb = 0; sb < 2; sb++)
        abase[sb] = (uint32_t)__cvta_generic_to_shared(
            &As[sb][(wm0 + (lane & 15)) * AST2 + (lane >> 4) * 4]);

    uint4 pa[2], pb[2];
    const int nk = C4T / 64;
    auto loadA = [&](int kt) {
#pragma unroll
        for (int j = 0; j < 2; j++) {
            int idx4 = tid + j * 256;
            int row = idx4 >> 2, qc = (idx4 & 3) << 2;
            pa[j] = *reinterpret_cast<const uint4*>(A4 + (size_t)(m0 + row) * K4 + kt * 16 + qc);
        }
    };
    auto loadB = [&](int kt) {
#pragma unroll
        for (int j = 0; j < 2; j++) {
            int idx4 = tid + j * 256;
            int kp = idx4 >> 5, nc = (idx4 & 31) << 2;
            pb[j] = *reinterpret_cast<const uint4*>(Wq + (size_t)(kt * 16 + kp) * Nn + n0 + nc);
        }
    };
    auto stage = [&](int sb) {
#pragma unroll
        for (int j = 0; j < 2; j++) {
            int idx4 = tid + j * 256;
            int row = idx4 >> 2, qc = (idx4 & 3) << 2;
            *reinterpret_cast<uint4*>(&As[sb][row * AST2 + qc]) = pa[j];
        }
#pragma unroll
        for (int j = 0; j < 2; j++) {
            int idx4 = tid + j * 256;
            int kp = idx4 >> 5, nc = (idx4 & 31) << 2;
            *reinterpret_cast<uint4*>(&Bs[sb][kp * BSTX + nc]) = pb[j];
        }
    };

    loadA(0); loadB(0);
    stage(0);
    __syncthreads();
    for (int kt = 0; kt < nk; kt++) {
        int cur = kt & 1;
        if (kt + 1 < nk) { loadA(kt + 1); loadB(kt + 1); }
        const uint32_t* Bc = Bs[cur];
        uint32_t ab = abase[cur];
#pragma unroll
        for (int ks = 0; ks < 2; ks++) {
            int kk4 = ks * 8;
            uint32_t a[2][4], b[8][2];
#pragma unroll
            for (int mt = 0; mt < 2; mt++)
                ldsm4(a[mt], ab + (uint32_t)((mt * 16 * AST2 + kk4) * 4));
#pragma unroll
            for (int nt = 0; nt < 8; nt++) {
                int col = wn0 + nt * 8 + g;
                b[nt][0] = Bc[(kk4 + tg    ) * BSTX + col];
                b[nt][1] = Bc[(kk4 + tg + 4) * BSTX + col];
            }
#pragma unroll
            for (int mt = 0; mt < 2; mt++)
#pragma unroll
                for (int nt = 0; nt < 8; nt++)
                    mma_fp8(acc[mt][nt], a[mt][0], a[mt][1], a[mt][2], a[mt][3],
                            b[nt][0], b[nt][1]);
        }
        if (kt + 1 < nk) {
            stage(cur ^ 1);
            __syncthreads();
        }
    }
#pragma unroll
    for (int mt = 0; mt < 2; mt++)
#pragma unroll
        for (int nt = 0; nt < 8; nt++) {
            int col = n0 + wn0 + nt * 8 + 2 * tg;
#pragma unroll
            for (int i = 0; i < 4; i++) {
                int row = m0 + wm0 + mt * 16 + g + (i >> 1) * 8;
                int c = col + (i & 1);
                Cc[(size_t)row * Nn + c] = acc[mt][nt][i] + bias[c];
            }
        }
}

// ---------------- Conv fp8 (unchanged from R12) ---------------------------------
__global__ __launch_bounds__(256) void conv_fp8_kernel(
    const uint32_t* __restrict__ xnq, const uint32_t* __restrict__ cwq,
    const float* __restrict__ cb1, const float* __restrict__ cb2,
    const float* __restrict__ cb3, const float* __restrict__ cb4,
    float* __restrict__ cv)
{
    __shared__ uint32_t As[2][128 * AST2];
    __shared__ uint32_t Bs[2][16 * BST3];
    int tid = threadIdx.x;
    int m0 = blockIdx.x * 128;
    int conv = blockIdx.y;
    int bidx = m0 >> 9;
    int t0   = m0 & 511;
    int tap0 = (conv == 0) ? 0 : (conv == 1) ? 1 : (conv == 2) ? 3 : 6;
    const float* bias = (conv == 0) ? cb1 : (conv == 1) ? cb2 : (conv == 2) ? cb3 : cb4;
    int ntaps = conv + 1;
    int dmin  = (conv < 2) ? 1 : 0;

    int wid = tid >> 5, lane = tid & 31;
    int wm0 = (wid & 3) * 32, wn0 = (wid >> 2) * 96;
    int g = lane >> 2, tg = lane & 3;

    float acc[2][12][4];
#pragma unroll
    for (int mt = 0; mt < 2; mt++)
#pragma unroll
        for (int nt = 0; nt < 12; nt++)
#pragma unroll
            for (int i = 0; i < 4; i++) acc[mt][nt][i] = 0.f;

    uint32_t abase[2];
#pragma unroll
    for (int sb = 0; sb < 2; sb++)
        abase[sb] = (uint32_t)__cvta_generic_to_shared(
            &As[sb][(wm0 + (lane & 15)) * AST2 + (lane >> 4) * 4]);

    const int nkt = DN / 64;
    int total = ntaps * nkt;
    const int K4 = DN / 4;

    uint4 pa[2], pb[3];
    auto loadA = [&](int it) {
        int ti = it / nkt, kt = it - ti * nkt;
        int shift = dmin + ti - 1;
#pragma unroll
        for (int j = 0; j < 2; j++) {
            int idx4 = tid + j * 256;
            int row = idx4 >> 2, qc = (idx4 & 3) << 2;
            int tsrc = t0 + row + shift;
            if (tsrc >= 0 && tsrc < TN)
                pa[j] = *reinterpret_cast<const uint4*>(
                    xnq + (size_t)((bidx << 9) + tsrc) * K4 + kt * 16 + qc);
            else
                pa[j] = make_uint4(0u, 0u, 0u, 0u);
        }
    };
    auto loadB = [&](int it) {
        int ti = it / nkt, kt = it - ti * nkt;
#pragma unroll
        for (int j = 0; j < 3; j++) {
            int idx4 = tid + j * 256;
            int kp = idx4 / 48, nc = (idx4 % 48) << 2;
            pb[j] = *reinterpret_cast<const uint4*>(
                cwq + ((size_t)(tap0 + ti) * (DN / 4) + kt * 16 + kp) * C1 + nc);
        }
    };
    auto stage = [&](int sb) {
#pragma unroll
        for (int j = 0; j < 2; j++) {
            int idx4 = tid + j * 256;
            int row = idx4 >> 2, qc = (idx4 & 3) << 2;
            *reinterpret_cast<uint4*>(&As[sb][row * AST2 + qc]) = pa[j];
        }
#pragma unroll
        for (int j = 0; j < 3; j++) {
            int idx4 = tid + j * 256;
            int kp = idx4 / 48, nc = (idx4 % 48) << 2;
            *reinterpret_cast<uint4*>(&Bs[sb][kp * BST3 + nc]) = pb[j];
        }
    };

    loadA(0); loadB(0);
    stage(0);
    __syncthreads();
    for (int it = 0; it < total; it++) {
        int cur = it & 1;
        if (it + 1 < total) { loadA(it + 1); loadB(it + 1); }
        const uint32_t* Bc = Bs[cur];
        uint32_t ab = abase[cur];
#pragma unroll
        for (int ks = 0; ks < 2; ks++) {
            int kk4 = ks * 8;
            uint32_t a[2][4], b[12][2];
#pragma unroll
            for (int mt = 0; mt < 2; mt++)
                ldsm4(a[mt], ab + (uint32_t)((mt * 16 * AST2 + kk4) * 4));
#pragma unroll
            for (int nt = 0; nt < 12; nt++) {
                int col = wn0 + nt * 8 + g;
                b[nt][0] = Bc[(kk4 + tg    ) * BST3 + col];
                b[nt][1] = Bc[(kk4 + tg + 4) * BST3 + col];
            }
#pragma unroll
            for (int mt = 0; mt < 2; mt++)
#pragma unroll
                for (int nt = 0; nt < 12; nt++)
                    mma_fp8(acc[mt][nt], a[mt][0], a[mt][1], a[mt][2], a[mt][3],
                            b[nt][0], b[nt][1]);
        }
        if (it + 1 < total) {
            stage(cur ^ 1);
            __syncthreads();
        }
    }
#pragma unroll
    for (int mt = 0; mt < 2; mt++)
#pragma unroll
        for (int nt = 0; nt < 12; nt++) {
            int cl = wn0 + nt * 8 + 2 * tg;
#pragma unroll
            for (int i = 0; i < 4; i++) {
                int row = m0 + wm0 + mt * 16 + g + (i >> 1) * 8;
                int c   = cl + (i & 1);
                float v = acc[mt][nt][i] + bias[c];
                cv[(size_t)row * C4T + conv * C1 + c] = fmaxf(v, 0.f);
            }
        }
}

// ---------------- TF32 GEMM (logits) --------------------------------------------
__global__ __launch_bounds__(256) void gemm_tf32_kernel(
    const float* __restrict__ A, const float* __restrict__ W,
    const float* __restrict__ bias, float* __restrict__ Cc,
    int M, int Nn, int Kk)
{
    __shared__ uint32_t As[128 * AST];
    __shared__ uint32_t Bs[32 * BST];
    int tid = threadIdx.x;
    int m0 = blockIdx.x * 128, n0 = blockIdx.y * 64;
    int wid = tid >> 5, lane = tid & 31;
    int wm0 = (wid & 3) * 32, wn0 = (wid >> 2) * 32;
    int g = lane >> 2, tg = lane & 3;
    float acc[2][4][4];
#pragma unroll
    for (int mt = 0; mt < 2; mt++)
#pragma unroll
        for (int nt = 0; nt < 4; nt++)
#pragma unroll
            for (int i = 0; i < 4; i++) acc[mt][nt][i] = 0.f;
    float4 pa[4], pb[2];
    int nk = Kk / 32;
    auto loadA = [&](int kt) {
#pragma unroll
        for (int j = 0; j < 4; j++) {
            int idx4 = tid + j * 256;
            int row = idx4 >> 3, kc = (idx4 & 7) << 2;
            pa[j] = *reinterpret_cast<const float4*>(A + (size_t)(m0 + row) * Kk + kt * 32 + kc);
        }
    };
    auto loadB = [&](int kt) {
#pragma unroll
        for (int j = 0; j < 2; j++) {
            int idx4 = tid + j * 256;
            int row = idx4 >> 4, nc = (idx4 & 15) << 2;
            int ncol = n0 + nc;
            const float* Wr = W + (size_t)(kt * 32 + row) * Nn;
            float4 v;
            if (ncol + 3 < Nn) v = *reinterpret_cast<const float4*>(Wr + ncol);
            else {
                v.x = (ncol + 0 < Nn) ? Wr[ncol + 0] : 0.f;
                v.y = (ncol + 1 < Nn) ? Wr[ncol + 1] : 0.f;
                v.z = (ncol + 2 < Nn) ? Wr[ncol + 2] : 0.f;
                v.w = (ncol + 3 < Nn) ? Wr[ncol + 3] : 0.f;
            }
            pb[j] = v;
        }
    };
    auto stage = [&]() {
#pragma unroll
        for (int j = 0; j < 4; j++) {
            int idx4 = tid + j * 256;
            int row = idx4 >> 3, kc = (idx4 & 7) << 2;
            As[row * AST + kc + 0] = f2tf32(pa[j].x);
            As[row * AST + kc + 1] = f2tf32(pa[j].y);
            As[row * AST + kc + 2] = f2tf32(pa[j].z);
            As[row * AST + kc + 3] = f2tf32(pa[j].w);
        }
#pragma unroll
        for (int j = 0; j < 2; j++) {
            int idx4 = tid + j * 256;
            int row = idx4 >> 4, nc = (idx4 & 15) << 2;
            Bs[row * BST + nc + 0] = f2tf32(pb[j].x);
            Bs[row * BST + nc + 1] = f2tf32(pb[j].y);
            Bs[row * BST + nc + 2] = f2tf32(pb[j].z);
            Bs[row * BST + nc + 3] = f2tf32(pb[j].w);
        }
    };
    loadA(0); loadB(0);
    for (int kt = 0; kt < nk; kt++) {
        __syncthreads();
        stage();
        __syncthreads();
        if (kt + 1 < nk) { loadA(kt + 1); loadB(kt + 1); }
#pragma unroll
        for (int ks = 0; ks < 4; ks++) {
            int kk = ks * 8;
            uint32_t a[2][4], b[4][2];
#pragma unroll
            for (int mt = 0; mt < 2; mt++) {
                int r0 = wm0 + mt * 16 + g;
                a[mt][0] = As[(r0    ) * AST + kk + tg];
                a[mt][1] = As[(r0 + 8) * AST + kk + tg];
                a[mt][2] = As[(r0    ) * AST + kk + tg + 4];
                a[mt][3] = As[(r0 + 8) * AST + kk + tg + 4];
            }
#pragma unroll
            for (int nt = 0; nt < 4; nt++) {
                int col = wn0 + nt * 8 + g;
                b[nt][0] = Bs[(kk + tg    ) * BST + col];
                b[nt][1] = Bs[(kk + tg + 4) * BST + col];
            }
#pragma unroll
            for (int mt = 0; mt < 2; mt++)
#pragma unroll
                for (int nt = 0; nt < 4; nt++)
                    mma_tf32(acc[mt][nt], a[mt][0], a[mt][1], a[mt][2], a[mt][3],
                             b[nt][0], b[nt][1]);
        }
    }
#pragma unroll
    for (int mt = 0; mt < 2; mt++)
#pragma unroll
        for (int nt = 0; nt < 4; nt++) {
            int col = n0 + wn0 + nt * 8 + 2 * tg;
#pragma unroll
            for (int i = 0; i < 4; i++) {
                int row = m0 + wm0 + mt * 16 + g + (i >> 1) * 8;
                int c = col + (i & 1);
                if (c < Nn) Cc[(size_t)row * Nn + c] = acc[mt][nt][i] + bias[c];
            }
        }
}

// ---------------- LSTM: 4-CTA cluster, mbarrier handoff, split MMA chains -------
#define LSW   (256 * 132 * 4)
#define LSH2  (2 * 128 * 8 * 4)
#define LSZ   (256 * 5 * 4)
#define LSMB  (LSW + LSH2 + LSZ)
#define LS_TOTAL (LSMB + 16)

__global__ void __cluster_dims__(4, 1, 1) __launch_bounds__(256)
lstm_cluster_kernel(
    const float* __restrict__ gxf, const float* __restrict__ gxb,
    const float* __restrict__ wh_f, const float* __restrict__ wh_b,
    const int* __restrict__ amask, float* __restrict__ hout)
{
    extern __shared__ char sm_[];
    uint32_t* whs2 = (uint32_t*)sm_;
    uint32_t* h2   = (uint32_t*)(sm_ + LSW);
    float*    zbuf = (float*)(sm_ + LSW + LSH2);
    uint32_t  mb   = smem_u32(sm_ + LSMB);     // two mbarriers: mb+0 (buf0), mb+8 (buf1)

    int tid = threadIdx.x;
    uint32_t rank;
    asm("mov.u32 %0, %%cluster_ctarank;" : "=r"(rank));
    int grp = blockIdx.x >> 2;
    int dir = grp >> 4;
    int b0  = (grp & 15) * 4;
    const float* __restrict__ Wh = dir ? wh_b : wh_f;
    const float* __restrict__ gx = dir ? gxb : gxf;

    for (int i = tid; i < 256 * 128; i += 256) {
        int lcol = i >> 7, kp = i & 127;
        int gcol = ((lcol >> 6) << 8) + (int)rank * 64 + (lcol & 63);
        whs2[lcol * 132 + kp] = packbf(Wh[(2 * kp) * G4 + gcol],
                                       Wh[(2 * kp + 1) * G4 + gcol]);
    }
    for (int i = tid; i < 2048; i += 256) h2[i] = 0u;
    if (tid == 0) { MB_INIT(mb, 4); MB_INIT(mb + 8, 4); }

    int lane = tid & 31, wrp = tid >> 5;
    int g = lane >> 2, tg = lane & 3;
    int pb = tid >> 6, pj = tid & 63;
    int bb = b0 + pb;
    float h_r = 0.f, c_r = 0.f, op_r = 0.f;

    // remote h-store addresses (both buffers, 4 CTAs)
    uint32_t ha[2][4];
    {
        int k = (int)rank * 64 + pj;
        uint32_t loc;
        const void* p = (const void*)((const char*)h2 + ((k >> 1) * 8 + pb) * 4 + (k & 1) * 2);
        asm("{ .reg .u64 t; cvta.to.shared.u64 t, %1; cvt.u32.u64 %0, t; }"
            : "=r"(loc) : "l"(p));
#pragma unroll
        for (int bf = 0; bf < 2; bf++) {
            uint32_t off = loc + bf * 4096;
#pragma unroll
            for (int r = 0; r < 4; r++)
                asm("mapa.shared::cluster.u32 %0, %1, %2;"
                    : "=r"(ha[bf][r]) : "r"(off), "r"(r));
        }
    }
    // remote mbarrier arrive addresses (both buffers, 4 CTAs)
    uint32_t mba[2][4];
#pragma unroll
    for (int bf = 0; bf < 2; bf++)
#pragma unroll
        for (int r = 0; r < 4; r++)
            asm("mapa.shared::cluster.u32 %0, %1, %2;"
                : "=r"(mba[bf][r]) : "r"(mb + bf * 8), "r"(r));

    asm volatile("barrier.cluster.arrive.aligned;" ::: "memory");
    asm volatile("barrier.cluster.wait.aligned;"   ::: "memory");

    int buf = 0, ph0 = 0, ph1 = 0;
    for (int s = 0; s < TN; s++) {
        int t = dir ? (TN - 1 - s) : s;
        size_t gb = ((size_t)(bb * TN + t)) * G4 + (size_t)rank * 64 + pj;
        float gx0 = gx[gb], gx1 = gx[gb + 256], gx2 = gx[gb + 512], gx3 = gx[gb + 768];
        int mv = amask[bb * TN + t];

        // wait for buffer `buf` to be fully written (step s-1's remote stores)
        if (s > 0) {
            if (buf == 0) { MB_WAIT(mb, ph0);     ph0 ^= 1; }
            else          { MB_WAIT(mb + 8, ph1); ph1 ^= 1; }
        }

        // z-phase: two independent 8-deep MMA chains per accumulator
        const uint32_t* h2c = h2 + buf * 1024;
        float d0[4] = {0,0,0,0}, d1[4] = {0,0,0,0};
        float e0[4] = {0,0,0,0}, e1[4] = {0,0,0,0};
        int r0 = wrp * 32 + g;
#pragma unroll
        for (int kt = 0; kt < 8; kt++) {
            int kA = kt * 8, kB = (kt + 8) * 8;
            uint32_t bqA0 = h2c[(kA + tg) * 8 + g];
            uint32_t bqA1 = h2c[(kA + tg + 4) * 8 + g];
            uint32_t bqB0 = h2c[(kB + tg) * 8 + g];
            uint32_t bqB1 = h2c[(kB + tg + 4) * 8 + g];
            uint32_t a0, a1, a2, a3;
            a0 = whs2[(r0     ) * 132 + kA + tg];
            a1 = whs2[(r0 +  8) * 132 + kA + tg];
            a2 = whs2[(r0     ) * 132 + kA + tg + 4];
            a3 = whs2[(r0 +  8) * 132 + kA + tg + 4];
            mma_bf16(d0, a0, a1, a2, a3, bqA0, bqA1);
            a0 = whs2[(r0 + 16) * 132 + kA + tg];
            a1 = whs2[(r0 + 24) * 132 + kA + tg];
            a2 = whs2[(r0 + 16) * 132 + kA + tg + 4];
            a3 = whs2[(r0 + 24) * 132 + kA + tg + 4];
            mma_bf16(d1, a0, a1, a2, a3, bqA0, bqA1);
            a0 = whs2[(r0     ) * 132 + kB + tg];
            a1 = whs2[(r0 +  8) * 132 + kB + tg];
            a2 = whs2[(r0     ) * 132 + kB + tg + 4];
            a3 = whs2[(r0 +  8) * 132 + kB + tg + 4];
            mma_bf16(e0, a0, a1, a2, a3, bqB0, bqB1);
            a0 = whs2[(r0 + 16) * 132 + kB + tg];
            a1 = whs2[(r0 + 24) * 132 + kB + tg];
            a2 = whs2[(r0 + 16) * 132 + kB + tg + 4];
            a3 = whs2[(r0 + 24) * 132 + kB + tg + 4];
            mma_bf16(e1, a0, a1, a2, a3, bqB0, bqB1);
        }
        if (tg < 2) {
#pragma unroll
            for (int i = 0; i < 4; i++) {
                int col = 2 * tg + (i & 1);
                zbuf[(r0 + (i >> 1) * 8     ) * 5 + col] = d0[i] + e0[i];
                zbuf[(r0 + (i >> 1) * 8 + 16) * 5 + col] = d1[i] + e1[i];
            }
        }
        __syncthreads();

        int nb = buf ^ 1;
        {
            float zi = zbuf[(      pj) * 5 + pb] + gx0;
            float zf = zbuf[( 64 + pj) * 5 + pb] + gx1;
            float zg = zbuf[(128 + pj) * 5 + pb] + gx2;
            float zo = zbuf[(192 + pj) * 5 + pb] + gx3;
            float ii = fsig(zi);
            float ff = fsig(zf);
            float gg = ftanh(zg);
            float oo = fsig(zo);
            float cn = ff * c_r + ii * gg;
            float hn = oo * ftanh(cn);
            bool m = mv != 0;
            float hq = m ? hn : h_r;
            c_r  = m ? cn : c_r;
            op_r = m ? hn : op_r;
            h_r  = hq;
            hout[((size_t)(bb * TN + t)) * (2 * HN) + dir * HN + (int)rank * 64 + pj] = op_r;
            uint16_t hb16;
            asm("cvt.rn.bf16.f32 %0, %1;" : "=h"(hb16) : "f"(hq));
#pragma unroll
            for (int r = 0; r < 4; r++)
                asm volatile("st.shared::cluster.b16 [%0], %1;"
                             :: "r"(ha[nb][r]), "h"(hb16) : "memory");
        }
        __syncthreads();
        if (tid == 0) {
            asm volatile("fence.acq_rel.cluster;" ::: "memory");
#pragma unroll
            for (int r = 0; r < 4; r++)
                MB_ARRIVE_REMOTE(mba[nb][r]);
        }
        buf = nb;
    }
    asm volatile("barrier.cluster.arrive.aligned;" ::: "memory");
    asm volatile("barrier.cluster.wait.aligned;"   ::: "memory");
}

// ---------------- CRF: prefetched emits + fast math ------------------------------
__global__ __launch_bounds__(32) void crf_kernel(
    const int* __restrict__ inputs, const int* __restrict__ targets,
    const float* __restrict__ trans, const float* __restrict__ logits,
    float* __restrict__ out)
{
    int b = blockIdx.x;
    int lane = threadIdx.x;
    __shared__ float tr[LBL * LBL];
    __shared__ float alpha[LBL];
    for (int i = lane; i < LBL * LBL; i += 32) tr[i] = trans[i];
    int cnt = 0;
    for (int t = lane; t < TN; t += 32) cnt += (inputs[b * TN + t] != 0);
#pragma unroll
    for (int o = 16; o; o >>= 1) cnt += __shfl_xor_sync(0xffffffffu, cnt, o);
    int seqlen = cnt;
    const float* lg = logits + (size_t)b * TN * LBL;
    const int*   tg = targets + b * TN;
    float us = 0.f, bs = 0.f;
    for (int t = lane; t < TN; t += 32) {
        if (t < seqlen) us += lg[t * LBL + tg[t]];
        if (t >= 1 && t < seqlen) bs += tr[tg[t - 1] * LBL + tg[t]];
    }
#pragma unroll
    for (int o = 16; o; o >>= 1) {
        us += __shfl_xor_sync(0xffffffffu, us, o);
        bs += __shfl_xor_sync(0xffffffffu, bs, o);
    }
    __syncwarp();
    if (lane < LBL) alpha[lane] = lg[lane];
    __syncwarp();

    float emit = (lane < LBL) ? lg[LBL + lane] : 0.f;
    for (int t = 1; t < TN; t++) {
        float emitN = (lane < LBL && t + 1 < TN) ? lg[(t + 1) * LBL + lane] : 0.f;
        float newv = 0.f;
        if (lane < LBL) {
            float m = -1e30f;
#pragma unroll
            for (int i = 0; i < LBL; i++) m = fmaxf(m, alpha[i] + tr[i * LBL + lane]);
            float ss = 0.f;
#pragma unroll
            for (int i = 0; i < LBL; i++) ss += __expf(alpha[i] + tr[i * LBL + lane] - m);
            newv = m + __logf(ss) + emit;
        }
        __syncwarp();
        if (lane < LBL && t < seqlen) alpha[lane] = newv;
        __syncwarp();
        emit = emitN;
    }
    float a = (lane < LBL) ? alpha[lane] : -1e30f;
    float mx = a;
#pragma unroll
    for (int o = 16; o; o >>= 1) mx = fmaxf(mx, __shfl_xor_sync(0xffffffffu, mx, o));
    float e = (lane < LBL) ? __expf(a - mx) : 0.f;
#pragma unroll
    for (int o = 16; o; o >>= 1) e += __shfl_xor_sync(0xffffffffu, e, o);
    float lognorm = mx + __logf(e);
    if (lane == 0) out[b] = us + bs - lognorm;
}

// ---------------- launch -----------------------------------------------------------
extern "C" void kernel_launch(void* const* d_in, const int* in_sizes, int n_in,
                              void* d_out, int out_size)
{
    const int*   inputs = (const int*)  d_in[0];
    const int*   amask  = (const int*)  d_in[1];
    const int*   targets= (const int*)  d_in[2];
    const float* hid_a  = (const float*)d_in[3];
    const float* hid_b  = (const float*)d_in[4];
    const float* ln1_g  = (const float*)d_in[5];
    const float* ln1_b  = (const float*)d_in[6];
    const float* w1 = (const float*)d_in[7];
    const float* b1 = (const float*)d_in[8];
    const float* w2 = (const float*)d_in[9];
    const float* b2 = (const float*)d_in[10];
    const float* w3 = (const float*)d_in[11];
    const float* b3 = (const float*)d_in[12];
    const float* w4 = (const float*)d_in[13];
    const float* b4 = (const float*)d_in[14];
    const float* ln2_g = (const float*)d_in[15];
    const float* ln2_b = (const float*)d_in[16];
    const float* wx_f  = (const float*)d_in[17];
    const float* wh_f  = (const float*)d_in[18];
    const float* bf    = (const float*)d_in[19];
    const float* wx_b  = (const float*)d_in[20];
    const float* wh_b  = (const float*)d_in[21];
    const float* bb    = (const float*)d_in[22];
    const float* wd    = (const float*)d_in[23];
    const float* bd    = (const float*)d_in[24];
    const float* trans = (const float*)d_in[25];

    uint32_t *xnq, *coq, *wxqf, *wxqb, *cwq;
    float *cv, *gxf, *gxb, *hh, *lg;
    cudaGetSymbolAddress((void**)&xnq,  g_xnq);
    cudaGetSymbolAddress((void**)&cv,   g_cv);
    cudaGetSymbolAddress((void**)&coq,  g_coq);
    cudaGetSymbolAddress((void**)&gxf,  g_gxf);
    cudaGetSymbolAddress((void**)&gxb,  g_gxb);
    cudaGetSymbolAddress((void**)&hh,   g_h);
    cudaGetSymbolAddress((void**)&lg,   g_lg);
    cudaGetSymbolAddress((void**)&wxqf, g_wxqf);
    cudaGetSymbolAddress((void**)&wxqb, g_wxqb);
    cudaGetSymbolAddress((void**)&cwq,  g_cwq);

    cudaFuncSetAttribute(lstm_cluster_kernel,
                         cudaFuncAttributeMaxDynamicSharedMemorySize, LS_TOTAL);

    {
        int ntot = 2 * ((C4T / 4) * G4) + 10 * (DN / 4) * C1;
        pack_all_kernel<<<(ntot + 255) / 256, 256>>>(
            wx_f, wx_b, w1, w2, w3, w4, wxqf, wxqb, cwq);
    }

    ln1_kernel<<<BT, 192>>>(hid_a, hid_b, ln1_g, ln1_b, xnq);
    conv_fp8_kernel<<<dim3(BT / 128, 4), 256>>>(xnq, cwq, b1, b2, b3, b4, cv);
    ln2_kernel<<<BT, 192>>>(cv, ln2_g, ln2_b, coq);
    gemm_fp8_dual_kernel<<<dim3(BT / 128, 16), 256>>>(
        coq, wxqf, wxqb, bf, bb, gxf, gxb);
    lstm_cluster_kernel<<<128, 256, LS_TOTAL>>>(gxf, gxb, wh_f, wh_b, amask, hh);
    gemm_tf32_kernel<<<dim3(BT / 128, 1), 256>>>(hh, wd, bd, lg, BT, LBL, 2 * HN);
    crf_kernel<<<BN, 32>>>(inputs, targets, trans, lg, (float*)d_out);
}